// round 2
// baseline (speedup 1.0000x reference)
#include <cuda_runtime.h>
#include <math.h>

#define NB 8
#define NC 256
#define NP1 1024      // 32*32
#define NP2 256       // 16*16
#define NINNER 512
#define NHEADS 8
#define NDH 64
#define ATT_SCALE 0.125f
#define BN_EPS 1e-5f

// ---------------- scratch (global memory via __device__ arrays) ----------------
__device__ float g_hq [2][NB][NC][NP1];        // dw+bn (stride 1) output
__device__ float g_hkv[2][NB][NC][NP2];        // dw+bn (stride 2) output
__device__ float g_q  [2][NB][NINNER][NP1];    // q projection
__device__ float g_kv [2][NB][2*NINNER][NP2];  // k|v projection
__device__ float g_ao [2][NB][NINNER][NP1];    // attention output

// ---------------- depthwise conv (stride 1) + BN ----------------
__global__ __launch_bounds__(1024)
void dwbn1_kernel(const float* __restrict__ x0, const float* __restrict__ x1,
                  const float* __restrict__ wdw,
                  const float* __restrict__ gamma, const float* __restrict__ beta,
                  const float* __restrict__ mean,  const float* __restrict__ var)
{
    int inp = blockIdx.y;
    int bc  = blockIdx.x;           // b*256 + c
    int c   = bc & 255;
    int b   = bc >> 8;
    const float* in = (inp ? x1 : x0) + (size_t)bc * 1024;

    __shared__ float t[34][34];
    int tid = threadIdx.x;
    for (int i = tid; i < 34 * 34; i += 1024) {
        int r = i / 34 - 1, q = i % 34 - 1;
        t[i / 34][i % 34] = (r >= 0 && r < 32 && q >= 0 && q < 32) ? in[r * 32 + q] : 0.f;
    }
    float w0 = wdw[c*9+0], w1 = wdw[c*9+1], w2 = wdw[c*9+2];
    float w3 = wdw[c*9+3], w4 = wdw[c*9+4], w5 = wdw[c*9+5];
    float w6 = wdw[c*9+6], w7 = wdw[c*9+7], w8 = wdw[c*9+8];
    __syncthreads();

    int ty = tid >> 5, tx = tid & 31;
    float acc = t[ty  ][tx] * w0 + t[ty  ][tx+1] * w1 + t[ty  ][tx+2] * w2
              + t[ty+1][tx] * w3 + t[ty+1][tx+1] * w4 + t[ty+1][tx+2] * w5
              + t[ty+2][tx] * w6 + t[ty+2][tx+1] * w7 + t[ty+2][tx+2] * w8;
    float s = gamma[c] * rsqrtf(var[c] + BN_EPS);
    g_hq[inp][b][c][tid] = (acc - mean[c]) * s + beta[c];
}

// ---------------- depthwise conv (stride 2) + BN ----------------
__global__ __launch_bounds__(256)
void dwbn2_kernel(const float* __restrict__ x0, const float* __restrict__ x1,
                  const float* __restrict__ wdw,
                  const float* __restrict__ gamma, const float* __restrict__ beta,
                  const float* __restrict__ mean,  const float* __restrict__ var)
{
    int inp = blockIdx.y;
    int bc  = blockIdx.x;
    int c   = bc & 255;
    int b   = bc >> 8;
    const float* in = (inp ? x1 : x0) + (size_t)bc * 1024;

    __shared__ float t[32][32];
    int tid = threadIdx.x;
    for (int i = tid; i < 1024; i += 256) t[i / 32][i % 32] = in[i];

    float w[9];
#pragma unroll
    for (int i = 0; i < 9; i++) w[i] = wdw[c * 9 + i];
    __syncthreads();

    int oy = tid >> 4, ox = tid & 15;
    int iy = oy * 2 - 1, ix = ox * 2 - 1;
    float acc = 0.f;
#pragma unroll
    for (int kh = 0; kh < 3; kh++) {
#pragma unroll
        for (int kw = 0; kw < 3; kw++) {
            int r = iy + kh, q = ix + kw;
            if (r >= 0 && r < 32 && q >= 0 && q < 32) acc += t[r][q] * w[kh * 3 + kw];
        }
    }
    float s = gamma[c] * rsqrtf(var[c] + BN_EPS);
    g_hkv[inp][b][c][tid] = (acc - mean[c]) * s + beta[c];
}

// ---------------- batched SGEMM: C[b] = A[M,K] @ X[b][K,P] (+bias) ----------------
// BM=BN=128, BK=16, 256 threads, 8x8 microtile
__global__ __launch_bounds__(256)
void sgemm_kernel(const float* __restrict__ A, const float* __restrict__ Xbase,
                  float* __restrict__ Cbase, int M, int K, int P,
                  const float* __restrict__ bias)
{
    const float* X = Xbase + (size_t)blockIdx.z * K * P;
    float*       Cp = Cbase + (size_t)blockIdx.z * M * P;

    __shared__ float As[16][132];
    __shared__ float Bs[16][128];

    int tid = threadIdx.x;
    int tx = tid & 15, ty = tid >> 4;
    int m0 = blockIdx.y * 128, n0 = blockIdx.x * 128;

    float acc[8][8];
#pragma unroll
    for (int i = 0; i < 8; i++)
#pragma unroll
        for (int j = 0; j < 8; j++) acc[i][j] = 0.f;

    for (int k0 = 0; k0 < K; k0 += 16) {
#pragma unroll
        for (int u = 0; u < 2; u++) {
            int idx = tid * 2 + u;               // 0..511 float4 units
            int row = idx >> 2;                  // 0..127
            int fid = idx & 3;
            float4 v = *(const float4*)&A[(size_t)(m0 + row) * K + k0 + fid * 4];
            As[fid * 4 + 0][row] = v.x;
            As[fid * 4 + 1][row] = v.y;
            As[fid * 4 + 2][row] = v.z;
            As[fid * 4 + 3][row] = v.w;
        }
#pragma unroll
        for (int u = 0; u < 2; u++) {
            int idx = tid * 2 + u;
            int row = idx >> 5;                  // 0..15
            int col = (idx & 31) * 4;
            *(float4*)&Bs[row][col] = *(const float4*)&X[(size_t)(k0 + row) * P + n0 + col];
        }
        __syncthreads();

#pragma unroll
        for (int k = 0; k < 16; k++) {
            float a[8], bb[8];
            *(float4*)&a[0]  = *(const float4*)&As[k][ty * 8];
            *(float4*)&a[4]  = *(const float4*)&As[k][ty * 8 + 4];
            *(float4*)&bb[0] = *(const float4*)&Bs[k][tx * 8];
            *(float4*)&bb[4] = *(const float4*)&Bs[k][tx * 8 + 4];
#pragma unroll
            for (int i = 0; i < 8; i++)
#pragma unroll
                for (int j = 0; j < 8; j++) acc[i][j] += a[i] * bb[j];
        }
        __syncthreads();
    }

#pragma unroll
    for (int i = 0; i < 8; i++) {
        int m = m0 + ty * 8 + i;
        float bv = bias ? bias[m] : 0.f;
        float4 o0 = make_float4(acc[i][0] + bv, acc[i][1] + bv, acc[i][2] + bv, acc[i][3] + bv);
        float4 o1 = make_float4(acc[i][4] + bv, acc[i][5] + bv, acc[i][6] + bv, acc[i][7] + bv);
        *(float4*)&Cp[(size_t)m * P + n0 + tx * 8]     = o0;
        *(float4*)&Cp[(size_t)m * P + n0 + tx * 8 + 4] = o1;
    }
}

// ---------------- fused attention ----------------
// grid: (16 i-tiles, B*HEADS, 2 dirs), 256 threads
// dir 0: outx = attn(qx, ky, vy);  dir 1: outy = attn(qy, kx, vx)
#define SM_Q  0
#define SM_K  (64 * 64)
#define SM_S  (64 * 64 + 64 * 256)
#define S_LD  260
#define ATTN_SMEM ((64 * 64 + 64 * 256 + 64 * S_LD) * 4)

__global__ __launch_bounds__(256)
void attn_kernel()
{
    extern __shared__ float sm[];
    float* qs = sm + SM_Q;   // [64 d][64 i]
    float* ks = sm + SM_K;   // [64 d][256 j]   (reused for V in phase 2)
    float* S  = sm + SM_S;   // [64 i][260]

    int dir = blockIdx.z;
    int bh  = blockIdx.y;
    int b   = bh >> 3, h = bh & 7;
    int i0  = blockIdx.x * 64;
    int qin = dir, kin = dir ^ 1;
    int tid = threadIdx.x;

    // load Q tile: qs[d][i] = g_q[qin][b][h*64+d][i0+i]
#pragma unroll
    for (int u = 0; u < 4; u++) {
        int idx = tid + u * 256;          // float4 units, 0..1023
        int d  = idx >> 4;
        int i4 = (idx & 15) * 4;
        *(float4*)&qs[d * 64 + i4] = *(const float4*)&g_q[qin][b][h * 64 + d][i0 + i4];
    }
    // load K: ks[d][j]
#pragma unroll
    for (int u = 0; u < 16; u++) {
        int idx = tid + u * 256;          // 0..4095 float4 units
        int d  = idx >> 6;
        int j4 = (idx & 63) * 4;
        *(float4*)&ks[d * 256 + j4] = *(const float4*)&g_kv[kin][b][h * 64 + d][j4];
    }
    __syncthreads();

    // phase 1: S[i][j] = SCALE * sum_d qs[d][i]*ks[d][j]
    {
        int ti = tid & 7, tj = tid >> 3;
        int ib = ti * 8, jb = tj * 8;
        float acc[8][8];
#pragma unroll
        for (int i = 0; i < 8; i++)
#pragma unroll
            for (int j = 0; j < 8; j++) acc[i][j] = 0.f;

#pragma unroll 4
        for (int d = 0; d < 64; d++) {
            float a[8], bb[8];
            *(float4*)&a[0]  = *(const float4*)&qs[d * 64 + ib];
            *(float4*)&a[4]  = *(const float4*)&qs[d * 64 + ib + 4];
            *(float4*)&bb[0] = *(const float4*)&ks[d * 256 + jb];
            *(float4*)&bb[4] = *(const float4*)&ks[d * 256 + jb + 4];
#pragma unroll
            for (int i = 0; i < 8; i++)
#pragma unroll
                for (int j = 0; j < 8; j++) acc[i][j] += a[i] * bb[j];
        }
#pragma unroll
        for (int i = 0; i < 8; i++) {
            float4 s0 = make_float4(acc[i][0] * ATT_SCALE, acc[i][1] * ATT_SCALE,
                                    acc[i][2] * ATT_SCALE, acc[i][3] * ATT_SCALE);
            float4 s1 = make_float4(acc[i][4] * ATT_SCALE, acc[i][5] * ATT_SCALE,
                                    acc[i][6] * ATT_SCALE, acc[i][7] * ATT_SCALE);
            *(float4*)&S[(ib + i) * S_LD + jb]     = s0;
            *(float4*)&S[(ib + i) * S_LD + jb + 4] = s1;
        }
    }
    __syncthreads();

    // load V into ks (overwrite), overlapping with softmax below
#pragma unroll
    for (int u = 0; u < 16; u++) {
        int idx = tid + u * 256;
        int d  = idx >> 6;
        int j4 = (idx & 63) * 4;
        *(float4*)&ks[d * 256 + j4] = *(const float4*)&g_kv[kin][b][NINNER + h * 64 + d][j4];
    }

    // softmax over j (256) per row, 8 warps x 8 rows
    {
        int warp = tid >> 5, lane = tid & 31;
#pragma unroll
        for (int r = 0; r < 8; r++) {
            int i = warp * 8 + r;
            float vals[8];
            float vmax = -1e30f;
#pragma unroll
            for (int u = 0; u < 8; u++) {
                vals[u] = S[i * S_LD + lane + u * 32];
                vmax = fmaxf(vmax, vals[u]);
            }
#pragma unroll
            for (int off = 16; off > 0; off >>= 1)
                vmax = fmaxf(vmax, __shfl_xor_sync(0xffffffffu, vmax, off));
            float sum = 0.f;
#pragma unroll
            for (int u = 0; u < 8; u++) { vals[u] = __expf(vals[u] - vmax); sum += vals[u]; }
#pragma unroll
            for (int off = 16; off > 0; off >>= 1)
                sum += __shfl_xor_sync(0xffffffffu, sum, off);
            float inv = 1.f / sum;
#pragma unroll
            for (int u = 0; u < 8; u++) S[i * S_LD + lane + u * 32] = vals[u] * inv;
        }
    }
    __syncthreads();

    // phase 2: out[d][i] = sum_j S[i][j] * V[d][j]
    {
        int txq = tid & 15, tyq = tid >> 4;
        int ib2 = txq * 4, db = tyq * 4;
        float acc2[4][4];
#pragma unroll
        for (int d = 0; d < 4; d++)
#pragma unroll
            for (int i = 0; i < 4; i++) acc2[d][i] = 0.f;

        for (int j = 0; j < 256; j += 4) {
            float4 vv[4], ss[4];
#pragma unroll
            for (int d = 0; d < 4; d++) vv[d] = *(const float4*)&ks[(db + d) * 256 + j];
#pragma unroll
            for (int i = 0; i < 4; i++) ss[i] = *(const float4*)&S[(ib2 + i) * S_LD + j];
#pragma unroll
            for (int d = 0; d < 4; d++)
#pragma unroll
                for (int i = 0; i < 4; i++)
                    acc2[d][i] += vv[d].x * ss[i].x + vv[d].y * ss[i].y
                                + vv[d].z * ss[i].z + vv[d].w * ss[i].w;
        }
#pragma unroll
        for (int d = 0; d < 4; d++) {
            float4 o = make_float4(acc2[d][0], acc2[d][1], acc2[d][2], acc2[d][3]);
            *(float4*)&g_ao[qin][b][h * 64 + db + d][i0 + ib2] = o;
        }
    }
}

// ---------------- launch ----------------
extern "C" void kernel_launch(void* const* d_in, const int* in_sizes, int n_in,
                              void* d_out, int out_size)
{
    const float* x      = (const float*)d_in[0];
    const float* y      = (const float*)d_in[1];
    const float* q_dw_w = (const float*)d_in[2];
    const float* q_g    = (const float*)d_in[3];
    const float* q_b    = (const float*)d_in[4];
    const float* q_m    = (const float*)d_in[5];
    const float* q_v    = (const float*)d_in[6];
    const float* q_pw   = (const float*)d_in[7];
    const float* kv_dw_w= (const float*)d_in[8];
    const float* kv_g   = (const float*)d_in[9];
    const float* kv_b   = (const float*)d_in[10];
    const float* kv_m   = (const float*)d_in[11];
    const float* kv_v   = (const float*)d_in[12];
    const float* kv_pw  = (const float*)d_in[13];
    const float* out_w  = (const float*)d_in[14];
    const float* out_b  = (const float*)d_in[15];
    float* out = (float*)d_out;

    float *p_hq, *p_hkv, *p_q, *p_kv, *p_ao;
    cudaGetSymbolAddress((void**)&p_hq,  g_hq);
    cudaGetSymbolAddress((void**)&p_hkv, g_hkv);
    cudaGetSymbolAddress((void**)&p_q,   g_q);
    cudaGetSymbolAddress((void**)&p_kv,  g_kv);
    cudaGetSymbolAddress((void**)&p_ao,  g_ao);

    // stage 1: depthwise conv + BN (both inputs)
    dwbn1_kernel<<<dim3(NB * NC, 2), 1024>>>(x, y, q_dw_w, q_g, q_b, q_m, q_v);
    dwbn2_kernel<<<dim3(NB * NC, 2), 256>>>(x, y, kv_dw_w, kv_g, kv_b, kv_m, kv_v);

    // stage 2: pointwise projections
    for (int inp = 0; inp < 2; inp++) {
        sgemm_kernel<<<dim3(NP1 / 128, NINNER / 128, NB), 256>>>(
            q_pw,
            p_hq + (size_t)inp * NB * NC * NP1,
            p_q  + (size_t)inp * NB * NINNER * NP1,
            NINNER, NC, NP1, nullptr);
        sgemm_kernel<<<dim3(NP2 / 128, (2 * NINNER) / 128, NB), 256>>>(
            kv_pw,
            p_hkv + (size_t)inp * NB * NC * NP2,
            p_kv  + (size_t)inp * NB * 2 * NINNER * NP2,
            2 * NINNER, NC, NP2, nullptr);
    }

    // stage 3: fused cross-attention, both directions
    cudaFuncSetAttribute(attn_kernel, cudaFuncAttributeMaxDynamicSharedMemorySize, ATTN_SMEM);
    attn_kernel<<<dim3(NP1 / 64, NB * NHEADS, 2), 256, ATTN_SMEM>>>();

    // stage 4: output projection (+bias) straight into d_out; tuple is (outx, outy)
    for (int inp = 0; inp < 2; inp++) {
        sgemm_kernel<<<dim3(NP1 / 128, NC / 128, NB), 256>>>(
            out_w,
            p_ao + (size_t)inp * NB * NINNER * NP1,
            out  + (size_t)inp * NB * NC * NP1,
            NC, NINNER, NP1, out_b);
    }
}

// round 4
// speedup vs baseline: 1.9440x; 1.9440x over previous
#include <cuda_runtime.h>
#include <cuda_bf16.h>
#include <stdint.h>
#include <math.h>

#define NB 8
#define NC 256
#define NP1 1024
#define NP2 256
#define NINNER 512
#define BN_EPS 1e-5f

__device__ float g_hq [2][NB][NC][NP1];
__device__ float g_hkv[2][NB][NC][NP2];
__device__ float g_q  [2][NB][NINNER][NP1];
__device__ float g_kv [2][NB][2*NINNER][NP2];
__device__ float g_ao [2][NB][NINNER][NP1];

// ---------------- helpers ----------------
__device__ __forceinline__ uint32_t smem_u32(const void* p){
    uint32_t a;
    asm("{ .reg .u64 t; cvta.to.shared.u64 t, %1; cvt.u32.u64 %0, t; }" : "=r"(a) : "l"(p));
    return a;
}
__device__ __forceinline__ void ldmx4(uint32_t* r, uint32_t a){
    asm volatile("ldmatrix.sync.aligned.m8n8.x4.shared.b16 {%0,%1,%2,%3}, [%4];"
        : "=r"(r[0]),"=r"(r[1]),"=r"(r[2]),"=r"(r[3]) : "r"(a) : "memory");
}
__device__ __forceinline__ void mma16816(float* c, const uint32_t* a, const uint32_t* b){
    asm volatile("mma.sync.aligned.m16n8k16.row.col.f32.bf16.bf16.f32 "
        "{%0,%1,%2,%3}, {%4,%5,%6,%7}, {%8,%9}, {%0,%1,%2,%3};"
        : "+f"(c[0]),"+f"(c[1]),"+f"(c[2]),"+f"(c[3])
        : "r"(a[0]),"r"(a[1]),"r"(a[2]),"r"(a[3]),"r"(b[0]),"r"(b[1]));
}
__device__ __forceinline__ void put_hl(__nv_bfloat16* bh, __nv_bfloat16* bl, int idx, float v){
    __nv_bfloat16 h = __float2bfloat16(v);
    bh[idx] = h;
    bl[idx] = __float2bfloat16(v - __bfloat162float(h));
}
__device__ __forceinline__ void put_hl2(__nv_bfloat16* bh, __nv_bfloat16* bl, int idx, float v0, float v1){
    __nv_bfloat16 h0 = __float2bfloat16(v0), h1 = __float2bfloat16(v1);
    __nv_bfloat162 H; H.x = h0; H.y = h1;
    __nv_bfloat162 L;
    L.x = __float2bfloat16(v0 - __bfloat162float(h0));
    L.y = __float2bfloat16(v1 - __bfloat162float(h1));
    *(__nv_bfloat162*)(bh + idx) = H;
    *(__nv_bfloat162*)(bl + idx) = L;
}

// ---------------- depthwise conv + BN ----------------
__global__ __launch_bounds__(1024)
void dwbn1_kernel(const float* __restrict__ x0, const float* __restrict__ x1,
                  const float* __restrict__ wdw, const float* __restrict__ gamma,
                  const float* __restrict__ beta, const float* __restrict__ mean,
                  const float* __restrict__ var)
{
    int inp = blockIdx.y, bc = blockIdx.x, c = bc & 255, b = bc >> 8;
    const float* in = (inp ? x1 : x0) + (size_t)bc * 1024;
    __shared__ float t[34][34];
    int tid = threadIdx.x;
    for (int i = tid; i < 34 * 34; i += 1024) {
        int r = i / 34 - 1, q = i % 34 - 1;
        t[i / 34][i % 34] = (r >= 0 && r < 32 && q >= 0 && q < 32) ? in[r * 32 + q] : 0.f;
    }
    float w0=wdw[c*9+0],w1=wdw[c*9+1],w2=wdw[c*9+2],w3=wdw[c*9+3],w4=wdw[c*9+4];
    float w5=wdw[c*9+5],w6=wdw[c*9+6],w7=wdw[c*9+7],w8=wdw[c*9+8];
    __syncthreads();
    int ty = tid >> 5, tx = tid & 31;
    float acc = t[ty][tx]*w0 + t[ty][tx+1]*w1 + t[ty][tx+2]*w2
              + t[ty+1][tx]*w3 + t[ty+1][tx+1]*w4 + t[ty+1][tx+2]*w5
              + t[ty+2][tx]*w6 + t[ty+2][tx+1]*w7 + t[ty+2][tx+2]*w8;
    float s = gamma[c] * rsqrtf(var[c] + BN_EPS);
    g_hq[inp][b][c][tid] = (acc - mean[c]) * s + beta[c];
}

__global__ __launch_bounds__(256)
void dwbn2_kernel(const float* __restrict__ x0, const float* __restrict__ x1,
                  const float* __restrict__ wdw, const float* __restrict__ gamma,
                  const float* __restrict__ beta, const float* __restrict__ mean,
                  const float* __restrict__ var)
{
    int inp = blockIdx.y, bc = blockIdx.x, c = bc & 255, b = bc >> 8;
    const float* in = (inp ? x1 : x0) + (size_t)bc * 1024;
    __shared__ float t[32][32];
    int tid = threadIdx.x;
    for (int i = tid; i < 1024; i += 256) t[i / 32][i % 32] = in[i];
    float w[9];
#pragma unroll
    for (int i = 0; i < 9; i++) w[i] = wdw[c * 9 + i];
    __syncthreads();
    int oy = tid >> 4, ox = tid & 15, iy = oy * 2 - 1, ix = ox * 2 - 1;
    float acc = 0.f;
#pragma unroll
    for (int kh = 0; kh < 3; kh++)
#pragma unroll
        for (int kw = 0; kw < 3; kw++) {
            int r = iy + kh, q = ix + kw;
            if (r >= 0 && r < 32 && q >= 0 && q < 32) acc += t[r][q] * w[kh * 3 + kw];
        }
    float s = gamma[c] * rsqrtf(var[c] + BN_EPS);
    g_hkv[inp][b][c][tid] = (acc - mean[c]) * s + beta[c];
}

// ---------------- tensor-core GEMM (mma.sync bf16 hi/lo split) ----------------
// C[z][m][p] = A[M,K] @ B[z][K,P] (+bias). CTA 128x128, BK=32, 256 threads.
#define BLD 40
#define GSMEM (4 * 128 * BLD * 2)

__global__ __launch_bounds__(256)
void mm_gemm(const float* __restrict__ A, const float* __restrict__ Bsrc,
             float* __restrict__ C, int Mtot, int K, int P,
             const float* __restrict__ bias)
{
    extern __shared__ char sm[];
    __nv_bfloat16* Ah = (__nv_bfloat16*)sm;
    __nv_bfloat16* Al = Ah + 128 * BLD;
    __nv_bfloat16* Bh = Al + 128 * BLD;
    __nv_bfloat16* Bl = Bh + 128 * BLD;
    uint32_t sAh = smem_u32(Ah), sAl = smem_u32(Al);
    uint32_t sBh = smem_u32(Bh), sBl = smem_u32(Bl);

    int tid = threadIdx.x, lane = tid & 31, wid = tid >> 5;
    int wr = wid >> 1, wc = wid & 1;
    int m0 = blockIdx.y * 128, n0 = blockIdx.x * 128;
    const float* Bp = Bsrc + (size_t)blockIdx.z * K * P;
    float* Cp = C + (size_t)blockIdx.z * Mtot * P;

    float acc[2][8][4];
#pragma unroll
    for (int i = 0; i < 2; i++)
#pragma unroll
        for (int j = 0; j < 8; j++)
#pragma unroll
            for (int k = 0; k < 4; k++) acc[i][j][k] = 0.f;

    int am = tid >> 1, ak = (tid & 1) * 16;
    int bn = tid & 127, bk = (tid >> 7) * 16;

    for (int k0 = 0; k0 < K; k0 += 32) {
        __syncthreads();
        {   // A tile [128 m][32 k]
            const float* Ar = A + (size_t)(m0 + am) * K + k0 + ak;
            float4 v0 = *(const float4*)(Ar);
            float4 v1 = *(const float4*)(Ar + 4);
            float4 v2 = *(const float4*)(Ar + 8);
            float4 v3 = *(const float4*)(Ar + 12);
            int base = am * BLD + ak;
            put_hl2(Ah, Al, base + 0,  v0.x, v0.y);
            put_hl2(Ah, Al, base + 2,  v0.z, v0.w);
            put_hl2(Ah, Al, base + 4,  v1.x, v1.y);
            put_hl2(Ah, Al, base + 6,  v1.z, v1.w);
            put_hl2(Ah, Al, base + 8,  v2.x, v2.y);
            put_hl2(Ah, Al, base + 10, v2.z, v2.w);
            put_hl2(Ah, Al, base + 12, v3.x, v3.y);
            put_hl2(Ah, Al, base + 14, v3.z, v3.w);
        }
        {   // B tile [128 n][32 k] transpose load
            const float* Bc = Bp + (size_t)(k0 + bk) * P + n0 + bn;
            int base = bn * BLD + bk;
#pragma unroll
            for (int e = 0; e < 16; e += 2) {
                float f0 = Bc[(size_t)e * P];
                float f1 = Bc[(size_t)(e + 1) * P];
                put_hl2(Bh, Bl, base + e, f0, f1);
            }
        }
        __syncthreads();

#pragma unroll
        for (int kk = 0; kk < 2; kk++) {
            uint32_t ah[2][4], al[2][4];
#pragma unroll
            for (int mi = 0; mi < 2; mi++) {
                uint32_t aaddr = sAh + ((wr*32 + mi*16 + (lane & 15)) * BLD
                                        + kk*16 + (lane >> 4) * 8) * 2;
                ldmx4(ah[mi], aaddr);
                ldmx4(al[mi], aaddr + (sAl - sAh));
            }
#pragma unroll
            for (int ni2 = 0; ni2 < 4; ni2++) {
                uint32_t bh[4], bl[4];
                uint32_t baddr = sBh + ((wc*64 + ni2*16 + ((lane >> 4) & 1) * 8 + (lane & 7)) * BLD
                                        + kk*16 + ((lane >> 3) & 1) * 8) * 2;
                ldmx4(bh, baddr);
                ldmx4(bl, baddr + (sBl - sBh));
#pragma unroll
                for (int mi = 0; mi < 2; mi++) {
                    mma16816(acc[mi][ni2*2],   ah[mi], &bh[0]);
                    mma16816(acc[mi][ni2*2],   ah[mi], &bl[0]);
                    mma16816(acc[mi][ni2*2],   al[mi], &bh[0]);
                    mma16816(acc[mi][ni2*2+1], ah[mi], &bh[2]);
                    mma16816(acc[mi][ni2*2+1], ah[mi], &bl[2]);
                    mma16816(acc[mi][ni2*2+1], al[mi], &bh[2]);
                }
            }
        }
    }

#pragma unroll
    for (int mi = 0; mi < 2; mi++) {
        int row = m0 + wr*32 + mi*16 + (lane >> 2);
        float b0 = bias ? bias[row] : 0.f;
        float b1 = bias ? bias[row + 8] : 0.f;
#pragma unroll
        for (int ni = 0; ni < 8; ni++) {
            int col = n0 + wc*64 + ni*8 + (lane & 3) * 2;
            float2 o0 = make_float2(acc[mi][ni][0] + b0, acc[mi][ni][1] + b0);
            float2 o1 = make_float2(acc[mi][ni][2] + b1, acc[mi][ni][3] + b1);
            *(float2*)&Cp[(size_t)row * P + col] = o0;
            *(float2*)&Cp[(size_t)(row + 8) * P + col] = o1;
        }
    }
}

// ---------------- fused attention (mma.sync) ----------------
// grid (16 i-tiles, 64 b*h, 2 dirs), 256 threads; i-tile 64, j = 256 resident.
#define QLD 72
#define KLD 72
#define VLD 264
#define SLDF 264
#define PLD 264
#define OFF_QH 0
#define OFF_QL 9216
#define OFF_KH 18432
#define OFF_KL 55296
#define OFF_VH 92160
#define OFF_VL 125952
#define OFF_S  0
#define OFF_PH 159744
#define OFF_PL 193536
#define ATT_SMEM 227328

__global__ __launch_bounds__(256)
void mm_attn()
{
    extern __shared__ char sm[];
    __nv_bfloat16* Qh = (__nv_bfloat16*)(sm + OFF_QH);
    __nv_bfloat16* Ql = (__nv_bfloat16*)(sm + OFF_QL);
    __nv_bfloat16* Kh = (__nv_bfloat16*)(sm + OFF_KH);
    __nv_bfloat16* Kl = (__nv_bfloat16*)(sm + OFF_KL);
    __nv_bfloat16* Vh = (__nv_bfloat16*)(sm + OFF_VH);
    __nv_bfloat16* Vl = (__nv_bfloat16*)(sm + OFF_VL);
    __nv_bfloat16* Ph = (__nv_bfloat16*)(sm + OFF_PH);
    __nv_bfloat16* Pl = (__nv_bfloat16*)(sm + OFF_PL);
    float* S = (float*)(sm + OFF_S);

    uint32_t sQH = smem_u32(Qh), sQL = smem_u32(Ql);
    uint32_t sKH = smem_u32(Kh), sKL = smem_u32(Kl);
    uint32_t sVH = smem_u32(Vh), sVL = smem_u32(Vl);
    uint32_t sPH = smem_u32(Ph), sPL = smem_u32(Pl);

    int tid = threadIdx.x, lane = tid & 31, wid = tid >> 5;
    int dir = blockIdx.z, bh = blockIdx.y;
    int b = bh >> 3, h = bh & 7;
    int i0 = blockIdx.x * 64;
    int qin = dir, kin = dir ^ 1;
    int wr = wid >> 1, wc = wid & 1;

    {   // Q [64 i][64 d], prescaled x0.125
        int iq = tid & 63, dg = tid >> 6;
        const float* qsrc = &g_q[qin][b][h * 64 + dg * 16][i0 + iq];
#pragma unroll
        for (int e = 0; e < 16; e++) {
            float v = qsrc[(size_t)e * NP1] * 0.125f;
            put_hl(Qh, Ql, iq * QLD + dg * 16 + e, v);
        }
    }
    {   // K [256 j][64 d]
        int j = tid;
        const float* ksrc = &g_kv[kin][b][h * 64][j];
#pragma unroll 8
        for (int d = 0; d < 64; d++)
            put_hl(Kh, Kl, j * KLD + d, ksrc[(size_t)d * NP2]);
    }
    {   // V [64 d][256 j]
        int j = tid;
        const float* vsrc = &g_kv[kin][b][NINNER + h * 64][j];
#pragma unroll 8
        for (int d = 0; d < 64; d++)
            put_hl(Vh, Vl, d * VLD + j, vsrc[(size_t)d * NP2]);
    }
    __syncthreads();

    // phase 1: S[64 i][256 j], warp tile 16 x 128
    float acc[16][4];
#pragma unroll
    for (int i = 0; i < 16; i++)
#pragma unroll
        for (int k = 0; k < 4; k++) acc[i][k] = 0.f;

#pragma unroll
    for (int kk = 0; kk < 4; kk++) {
        uint32_t ah[4], al[4];
        uint32_t aaddr = sQH + ((wr*16 + (lane & 15)) * QLD + kk*16 + (lane >> 4) * 8) * 2;
        ldmx4(ah, aaddr);
        ldmx4(al, aaddr + (sQL - sQH));
#pragma unroll
        for (int ni2 = 0; ni2 < 8; ni2++) {
            uint32_t bhf[4], blf[4];
            uint32_t baddr = sKH + ((wc*128 + ni2*16 + ((lane >> 4) & 1) * 8 + (lane & 7)) * KLD
                                    + kk*16 + ((lane >> 3) & 1) * 8) * 2;
            ldmx4(bhf, baddr);
            ldmx4(blf, baddr + (sKL - sKH));
            mma16816(acc[ni2*2],   ah, &bhf[0]);
            mma16816(acc[ni2*2],   ah, &blf[0]);
            mma16816(acc[ni2*2],   al, &bhf[0]);
            mma16816(acc[ni2*2+1], ah, &bhf[2]);
            mma16816(acc[ni2*2+1], ah, &blf[2]);
            mma16816(acc[ni2*2+1], al, &bhf[2]);
        }
    }
    __syncthreads();   // all warps done reading Q/K; S overwrites that region

#pragma unroll
    for (int ni = 0; ni < 16; ni++) {
        int r0 = wr*16 + (lane >> 2);
        int c  = wc*128 + ni*8 + (lane & 3) * 2;
        *(float2*)&S[r0 * SLDF + c]       = make_float2(acc[ni][0], acc[ni][1]);
        *(float2*)&S[(r0 + 8) * SLDF + c] = make_float2(acc[ni][2], acc[ni][3]);
    }
    __syncthreads();

    // softmax: 8 warps x 8 rows, write normalized P (hi/lo split)
#pragma unroll
    for (int r = 0; r < 8; r++) {
        int i = wid * 8 + r;
        float vals[8];
        float vmax = -1e30f;
#pragma unroll
        for (int u = 0; u < 8; u++) {
            vals[u] = S[i * SLDF + lane + u * 32];
            vmax = fmaxf(vmax, vals[u]);
        }
#pragma unroll
        for (int off = 16; off > 0; off >>= 1)
            vmax = fmaxf(vmax, __shfl_xor_sync(0xffffffffu, vmax, off));
        float sum = 0.f;
#pragma unroll
        for (int u = 0; u < 8; u++) { vals[u] = __expf(vals[u] - vmax); sum += vals[u]; }
#pragma unroll
        for (int off = 16; off > 0; off >>= 1)
            sum += __shfl_xor_sync(0xffffffffu, sum, off);
        float inv = 1.f / sum;
#pragma unroll
        for (int u = 0; u < 8; u++)
            put_hl(Ph, Pl, i * PLD + lane + u * 32, vals[u] * inv);
    }
    __syncthreads();

    // phase 2: O[64 i][64 d] = P @ V, warp tile 16 x 32
    float acc2[4][4];
#pragma unroll
    for (int i = 0; i < 4; i++)
#pragma unroll
        for (int k = 0; k < 4; k++) acc2[i][k] = 0.f;

#pragma unroll 4
    for (int kk = 0; kk < 16; kk++) {
        uint32_t ah[4], al[4];
        uint32_t aaddr = sPH + ((wr*16 + (lane & 15)) * PLD + kk*16 + (lane >> 4) * 8) * 2;
        ldmx4(ah, aaddr);
        ldmx4(al, aaddr + (sPL - sPH));
#pragma unroll
        for (int ni2 = 0; ni2 < 2; ni2++) {
            uint32_t bhf[4], blf[4];
            uint32_t baddr = sVH + ((wc*32 + ni2*16 + ((lane >> 4) & 1) * 8 + (lane & 7)) * VLD
                                    + kk*16 + ((lane >> 3) & 1) * 8) * 2;
            ldmx4(bhf, baddr);
            ldmx4(blf, baddr + (sVL - sVH));
            mma16816(acc2[ni2*2],   ah, &bhf[0]);
            mma16816(acc2[ni2*2],   ah, &blf[0]);
            mma16816(acc2[ni2*2],   al, &bhf[0]);
            mma16816(acc2[ni2*2+1], ah, &bhf[2]);
            mma16816(acc2[ni2*2+1], ah, &blf[2]);
            mma16816(acc2[ni2*2+1], al, &bhf[2]);
        }
    }

#pragma unroll
    for (int ni = 0; ni < 4; ni++) {
        int i = i0 + wr*16 + (lane >> 2);
        int d = h*64 + wc*32 + ni*8 + (lane & 3) * 2;
        g_ao[qin][b][d][i]         = acc2[ni][0];
        g_ao[qin][b][d + 1][i]     = acc2[ni][1];
        g_ao[qin][b][d][i + 8]     = acc2[ni][2];
        g_ao[qin][b][d + 1][i + 8] = acc2[ni][3];
    }
}

// ---------------- launch ----------------
extern "C" void kernel_launch(void* const* d_in, const int* in_sizes, int n_in,
                              void* d_out, int out_size)
{
    const float* x      = (const float*)d_in[0];
    const float* y      = (const float*)d_in[1];
    const float* q_dw_w = (const float*)d_in[2];
    const float* q_g    = (const float*)d_in[3];
    const float* q_b    = (const float*)d_in[4];
    const float* q_m    = (const float*)d_in[5];
    const float* q_v    = (const float*)d_in[6];
    const float* q_pw   = (const float*)d_in[7];
    const float* kv_dw_w= (const float*)d_in[8];
    const float* kv_g   = (const float*)d_in[9];
    const float* kv_b   = (const float*)d_in[10];
    const float* kv_m   = (const float*)d_in[11];
    const float* kv_v   = (const float*)d_in[12];
    const float* kv_pw  = (const float*)d_in[13];
    const float* out_w  = (const float*)d_in[14];
    const float* out_b  = (const float*)d_in[15];
    float* out = (float*)d_out;

    float *p_hq, *p_hkv, *p_q, *p_kv, *p_ao;
    cudaGetSymbolAddress((void**)&p_hq,  g_hq);
    cudaGetSymbolAddress((void**)&p_hkv, g_hkv);
    cudaGetSymbolAddress((void**)&p_q,   g_q);
    cudaGetSymbolAddress((void**)&p_kv,  g_kv);
    cudaGetSymbolAddress((void**)&p_ao,  g_ao);

    cudaFuncSetAttribute(mm_attn, cudaFuncAttributeMaxDynamicSharedMemorySize, ATT_SMEM);

    dwbn1_kernel<<<dim3(NB * NC, 2), 1024>>>(x, y, q_dw_w, q_g, q_b, q_m, q_v);
    dwbn2_kernel<<<dim3(NB * NC, 2), 256>>>(x, y, kv_dw_w, kv_g, kv_b, kv_m, kv_v);

    for (int inp = 0; inp < 2; inp++) {
        mm_gemm<<<dim3(NP1 / 128, NINNER / 128, NB), 256, GSMEM>>>(
            q_pw, p_hq + (size_t)inp * NB * NC * NP1,
            p_q + (size_t)inp * NB * NINNER * NP1, NINNER, NC, NP1, nullptr);
        mm_gemm<<<dim3(NP2 / 128, (2 * NINNER) / 128, NB), 256, GSMEM>>>(
            kv_pw, p_hkv + (size_t)inp * NB * NC * NP2,
            p_kv + (size_t)inp * NB * 2 * NINNER * NP2, 2 * NINNER, NC, NP2, nullptr);
    }

    mm_attn<<<dim3(NP1 / 64, NB * 8, 2), 256, ATT_SMEM>>>();

    for (int inp = 0; inp < 2; inp++) {
        mm_gemm<<<dim3(NP1 / 128, NC / 128, NB), 256, GSMEM>>>(
            out_w, p_ao + (size_t)inp * NB * NINNER * NP1,
            out + (size_t)inp * NB * NC * NP1, NC, NINNER, NP1, out_b);
    }
}

// round 5
// speedup vs baseline: 2.2217x; 1.1429x over previous
#include <cuda_runtime.h>
#include <cuda_bf16.h>
#include <stdint.h>
#include <math.h>

#define NB 8
#define NC 256
#define NP1 1024
#define NP2 256
#define NINNER 512
#define BN_EPS 1e-5f

// ---------------- bf16 hi/lo scratch ----------------
__device__ __nv_bfloat16 g_hq_h [2][NB][NC][NP1],      g_hq_l [2][NB][NC][NP1];
__device__ __nv_bfloat16 g_hkv_h[2][NB][NC][NP2],      g_hkv_l[2][NB][NC][NP2];
__device__ __nv_bfloat16 g_q_h  [2][NB][NINNER][NP1],  g_q_l  [2][NB][NINNER][NP1];
__device__ __nv_bfloat16 g_kv_h [2][NB][2*NINNER][NP2],g_kv_l [2][NB][2*NINNER][NP2];
__device__ __nv_bfloat16 g_ao_h [2][NB][NINNER][NP1],  g_ao_l [2][NB][NINNER][NP1];
__device__ __nv_bfloat16 g_wq_h [NINNER*NC],   g_wq_l [NINNER*NC];
__device__ __nv_bfloat16 g_wkv_h[2*NINNER*NC], g_wkv_l[2*NINNER*NC];
__device__ __nv_bfloat16 g_wo_h [NC*NINNER],   g_wo_l [NC*NINNER];

// ---------------- helpers ----------------
__device__ __forceinline__ uint32_t smem_u32(const void* p){
    uint32_t a;
    asm("{ .reg .u64 t; cvta.to.shared.u64 t, %1; cvt.u32.u64 %0, t; }" : "=r"(a) : "l"(p));
    return a;
}
__device__ __forceinline__ void ldmx4(uint32_t* r, uint32_t a){
    asm volatile("ldmatrix.sync.aligned.m8n8.x4.shared.b16 {%0,%1,%2,%3}, [%4];"
        : "=r"(r[0]),"=r"(r[1]),"=r"(r[2]),"=r"(r[3]) : "r"(a) : "memory");
}
__device__ __forceinline__ void ldmx4t(uint32_t* r, uint32_t a){
    asm volatile("ldmatrix.sync.aligned.m8n8.x4.trans.shared.b16 {%0,%1,%2,%3}, [%4];"
        : "=r"(r[0]),"=r"(r[1]),"=r"(r[2]),"=r"(r[3]) : "r"(a) : "memory");
}
__device__ __forceinline__ void mma16816(float* c, const uint32_t* a, const uint32_t* b){
    asm volatile("mma.sync.aligned.m16n8k16.row.col.f32.bf16.bf16.f32 "
        "{%0,%1,%2,%3}, {%4,%5,%6,%7}, {%8,%9}, {%0,%1,%2,%3};"
        : "+f"(c[0]),"+f"(c[1]),"+f"(c[2]),"+f"(c[3])
        : "r"(a[0]),"r"(a[1]),"r"(a[2]),"r"(a[3]),"r"(b[0]),"r"(b[1]));
}
__device__ __forceinline__ void cpa16(uint32_t s, const void* g){
    asm volatile("cp.async.cg.shared.global [%0], [%1], 16;" :: "r"(s), "l"(g));
}
#define CP_COMMIT() asm volatile("cp.async.commit_group;" ::: "memory")
#define CP_WAIT0()  asm volatile("cp.async.wait_group 0;" ::: "memory")
#define CP_WAIT1()  asm volatile("cp.async.wait_group 1;" ::: "memory")

__device__ __forceinline__ void put_hl(__nv_bfloat16* bh, __nv_bfloat16* bl, int idx, float v){
    __nv_bfloat16 h = __float2bfloat16(v);
    bh[idx] = h;
    bl[idx] = __float2bfloat16(v - __bfloat162float(h));
}
__device__ __forceinline__ void put_hl2(__nv_bfloat16* bh, __nv_bfloat16* bl, int idx, float v0, float v1){
    __nv_bfloat16 h0 = __float2bfloat16(v0), h1 = __float2bfloat16(v1);
    __nv_bfloat162 H; H.x = h0; H.y = h1;
    __nv_bfloat162 L;
    L.x = __float2bfloat16(v0 - __bfloat162float(h0));
    L.y = __float2bfloat16(v1 - __bfloat162float(h1));
    *(__nv_bfloat162*)(bh + idx) = H;
    *(__nv_bfloat162*)(bl + idx) = L;
}

// ---------------- weight fp32 -> hi/lo ----------------
__global__ void cvt_hl_kernel(const float* __restrict__ src, __nv_bfloat16* __restrict__ h,
                              __nv_bfloat16* __restrict__ l, int n2){
    int i = blockIdx.x * 256 + threadIdx.x;
    if (i < n2) {
        float2 v = *(const float2*)(src + i * 2);
        put_hl2(h, l, i * 2, v.x, v.y);
    }
}

// ---------------- depthwise conv + BN -> bf16 hi/lo ----------------
__global__ __launch_bounds__(1024)
void dwbn1_kernel(const float* __restrict__ x0, const float* __restrict__ x1,
                  const float* __restrict__ wdw, const float* __restrict__ gamma,
                  const float* __restrict__ beta, const float* __restrict__ mean,
                  const float* __restrict__ var)
{
    int inp = blockIdx.y, bc = blockIdx.x, c = bc & 255, b = bc >> 8;
    const float* in = (inp ? x1 : x0) + (size_t)bc * 1024;
    __shared__ float t[34][34];
    int tid = threadIdx.x;
    for (int i = tid; i < 34 * 34; i += 1024) {
        int r = i / 34 - 1, q = i % 34 - 1;
        t[i / 34][i % 34] = (r >= 0 && r < 32 && q >= 0 && q < 32) ? in[r * 32 + q] : 0.f;
    }
    float w0=wdw[c*9+0],w1=wdw[c*9+1],w2=wdw[c*9+2],w3=wdw[c*9+3],w4=wdw[c*9+4];
    float w5=wdw[c*9+5],w6=wdw[c*9+6],w7=wdw[c*9+7],w8=wdw[c*9+8];
    __syncthreads();
    int ty = tid >> 5, tx = tid & 31;
    float acc = t[ty][tx]*w0 + t[ty][tx+1]*w1 + t[ty][tx+2]*w2
              + t[ty+1][tx]*w3 + t[ty+1][tx+1]*w4 + t[ty+1][tx+2]*w5
              + t[ty+2][tx]*w6 + t[ty+2][tx+1]*w7 + t[ty+2][tx+2]*w8;
    float s = gamma[c] * rsqrtf(var[c] + BN_EPS);
    float v = (acc - mean[c]) * s + beta[c];
    put_hl(&g_hq_h[inp][b][c][0], &g_hq_l[inp][b][c][0], tid, v);
}

__global__ __launch_bounds__(256)
void dwbn2_kernel(const float* __restrict__ x0, const float* __restrict__ x1,
                  const float* __restrict__ wdw, const float* __restrict__ gamma,
                  const float* __restrict__ beta, const float* __restrict__ mean,
                  const float* __restrict__ var)
{
    int inp = blockIdx.y, bc = blockIdx.x, c = bc & 255, b = bc >> 8;
    const float* in = (inp ? x1 : x0) + (size_t)bc * 1024;
    __shared__ float t[32][32];
    int tid = threadIdx.x;
    for (int i = tid; i < 1024; i += 256) t[i / 32][i % 32] = in[i];
    float w[9];
#pragma unroll
    for (int i = 0; i < 9; i++) w[i] = wdw[c * 9 + i];
    __syncthreads();
    int oy = tid >> 4, ox = tid & 15, iy = oy * 2 - 1, ix = ox * 2 - 1;
    float acc = 0.f;
#pragma unroll
    for (int kh = 0; kh < 3; kh++)
#pragma unroll
        for (int kw = 0; kw < 3; kw++) {
            int r = iy + kh, q = ix + kw;
            if (r >= 0 && r < 32 && q >= 0 && q < 32) acc += t[r][q] * w[kh * 3 + kw];
        }
    float s = gamma[c] * rsqrtf(var[c] + BN_EPS);
    float v = (acc - mean[c]) * s + beta[c];
    put_hl(&g_hkv_h[inp][b][c][0], &g_hkv_l[inp][b][c][0], tid, v);
}

// ---------------- tensor-core GEMM v2 (bf16 in, cp.async double buffered) ----------------
// C[z] = A[M,K] @ B[z][K,P]; A row-major [m][k], B row-major [k][p].
// CTA 128x128, BK=32, 256 threads (8 warps: wr=wid>>1 in M, wc=wid&1 in N).
#define ALD2 40
#define BLD2 136
#define A_H0 0
#define A_H1 10240
#define A_L0 20480
#define A_L1 30720
#define B_H0 40960
#define B_H1 49664
#define B_L0 58368
#define B_L1 67072
#define GSM2 75776

__global__ __launch_bounds__(256)
void mm_gemm2(const __nv_bfloat16* __restrict__ Ah, const __nv_bfloat16* __restrict__ Al,
              const __nv_bfloat16* __restrict__ Bh, const __nv_bfloat16* __restrict__ Bl,
              __nv_bfloat16* __restrict__ Ch, __nv_bfloat16* __restrict__ Cl,
              float* __restrict__ Cf, const float* __restrict__ bias,
              int Mtot, int K, int P)
{
    extern __shared__ char sm[];
    uint32_t sb = smem_u32(sm);
    int tid = threadIdx.x, lane = tid & 31, wid = tid >> 5;
    int wr = wid >> 1, wc = wid & 1;
    int m0 = blockIdx.y * 128, n0 = blockIdx.x * 128;
    size_t zoff = (size_t)blockIdx.z * K * P;
    const __nv_bfloat16* Bhz = Bh + zoff;
    const __nv_bfloat16* Blz = Bl + zoff;

    float acc[2][8][4];
#pragma unroll
    for (int i = 0; i < 2; i++)
#pragma unroll
        for (int j = 0; j < 8; j++)
#pragma unroll
            for (int k = 0; k < 4; k++) acc[i][j][k] = 0.f;

    int niter = K >> 5;

    // stage loader
#define LOAD_STAGE(st, k0) do { \
    uint32_t aH = sb + ((st) ? A_H1 : A_H0); \
    uint32_t aL = sb + ((st) ? A_L1 : A_L0); \
    uint32_t bH = sb + ((st) ? B_H1 : B_H0); \
    uint32_t bL = sb + ((st) ? B_L1 : B_L0); \
    _Pragma("unroll") \
    for (int u = 0; u < 2; u++) { \
        int idx = tid + u * 256; \
        int row = idx >> 2, ch = (idx & 3) * 8; \
        size_t go = (size_t)(m0 + row) * K + (k0) + ch; \
        uint32_t so = (uint32_t)(row * ALD2 + ch) * 2; \
        cpa16(aH + so, Ah + go); \
        cpa16(aL + so, Al + go); \
    } \
    _Pragma("unroll") \
    for (int u = 0; u < 2; u++) { \
        int idx = tid + u * 256; \
        int row = idx >> 4, ch = (idx & 15) * 8; \
        size_t go = (size_t)((k0) + row) * P + n0 + ch; \
        uint32_t so = (uint32_t)(row * BLD2 + ch) * 2; \
        cpa16(bH + so, Bhz + go); \
        cpa16(bL + so, Blz + go); \
    } \
} while (0)

    LOAD_STAGE(0, 0);
    CP_COMMIT();

    for (int it = 0; it < niter; it++) {
        if (it + 1 < niter) { LOAD_STAGE((it + 1) & 1, (it + 1) << 5); CP_COMMIT(); CP_WAIT1(); }
        else CP_WAIT0();
        __syncthreads();

        uint32_t aHb = sb + ((it & 1) ? A_H1 : A_H0);
        uint32_t bHb = sb + ((it & 1) ? B_H1 : B_H0);
#pragma unroll
        for (int kk = 0; kk < 2; kk++) {
            uint32_t ah[2][4], al[2][4];
#pragma unroll
            for (int mi = 0; mi < 2; mi++) {
                uint32_t aaddr = aHb + (uint32_t)((wr*32 + mi*16 + (lane & 15)) * ALD2
                                                  + kk*16 + (lane >> 4) * 8) * 2;
                ldmx4(ah[mi], aaddr);
                ldmx4(al[mi], aaddr + 20480u);
            }
#pragma unroll
            for (int ni2 = 0; ni2 < 4; ni2++) {
                uint32_t bh[4], bl[4];
                uint32_t baddr = bHb + (uint32_t)((kk*16 + (lane & 15)) * BLD2
                                                  + wc*64 + ni2*16 + ((lane & 16) >> 1)) * 2;
                ldmx4t(bh, baddr);
                ldmx4t(bl, baddr + 17408u);
#pragma unroll
                for (int mi = 0; mi < 2; mi++) {
                    mma16816(acc[mi][ni2*2],   ah[mi], &bh[0]);
                    mma16816(acc[mi][ni2*2],   ah[mi], &bl[0]);
                    mma16816(acc[mi][ni2*2],   al[mi], &bh[0]);
                    mma16816(acc[mi][ni2*2+1], ah[mi], &bh[2]);
                    mma16816(acc[mi][ni2*2+1], ah[mi], &bl[2]);
                    mma16816(acc[mi][ni2*2+1], al[mi], &bh[2]);
                }
            }
        }
        __syncthreads();
    }

    if (Cf) {
        float* Cp = Cf + zoff / K * Mtot;   // z * Mtot * P
#pragma unroll
        for (int mi = 0; mi < 2; mi++) {
            int row = m0 + wr*32 + mi*16 + (lane >> 2);
            float b0 = bias ? bias[row] : 0.f;
            float b1 = bias ? bias[row + 8] : 0.f;
#pragma unroll
            for (int ni = 0; ni < 8; ni++) {
                int col = n0 + wc*64 + ni*8 + (lane & 3) * 2;
                *(float2*)&Cp[(size_t)row * P + col] =
                    make_float2(acc[mi][ni][0] + b0, acc[mi][ni][1] + b0);
                *(float2*)&Cp[(size_t)(row + 8) * P + col] =
                    make_float2(acc[mi][ni][2] + b1, acc[mi][ni][3] + b1);
            }
        }
    } else {
        __nv_bfloat16* Chz = Ch + (size_t)blockIdx.z * Mtot * P;
        __nv_bfloat16* Clz = Cl + (size_t)blockIdx.z * Mtot * P;
#pragma unroll
        for (int mi = 0; mi < 2; mi++) {
            int row = m0 + wr*32 + mi*16 + (lane >> 2);
#pragma unroll
            for (int ni = 0; ni < 8; ni++) {
                int col = n0 + wc*64 + ni*8 + (lane & 3) * 2;
                put_hl2(Chz, Clz, (int)((size_t)row * P + col), acc[mi][ni][0], acc[mi][ni][1]);
                put_hl2(Chz, Clz, (int)((size_t)(row + 8) * P + col), acc[mi][ni][2], acc[mi][ni][3]);
            }
        }
    }
}

// ---------------- fused attention v2 (bf16 in, cp.async) ----------------
// grid (16 i-tiles, 64 b*h, 2 dirs), 256 threads; i-tile 64, j=256 resident.
#define QLD 72
#define KLD 264
#define SLDF 264
#define PLD 264
#define OLD 65
#define AQH 0
#define AQL 9216
#define AKH 18432
#define AKL 52224
#define AVH 86016
#define AVL 119808
#define APH 153600
#define APL 187392
#define ATT_SM2 221184

__global__ __launch_bounds__(256)
void mm_attn2()
{
    extern __shared__ char sm[];
    uint32_t sb = smem_u32(sm);
    float* S = (float*)sm;          // aliases Q/K region after phase 1
    float* O = (float*)sm;          // aliases again in epilogue
    __nv_bfloat16* Ph = (__nv_bfloat16*)(sm + APH);
    __nv_bfloat16* Pl = (__nv_bfloat16*)(sm + APL);

    int tid = threadIdx.x, lane = tid & 31, wid = tid >> 5;
    int dir = blockIdx.z, bh = blockIdx.y;
    int b = bh >> 3, h = bh & 7;
    int i0 = blockIdx.x * 64;
    int qin = dir, kin = dir ^ 1;
    int wr = wid >> 1, wc = wid & 1;

    const __nv_bfloat16* qh = &g_q_h[qin][b][0][0];
    const __nv_bfloat16* ql = &g_q_l[qin][b][0][0];
    const __nv_bfloat16* kh = &g_kv_h[kin][b][0][0];
    const __nv_bfloat16* kl = &g_kv_l[kin][b][0][0];

    // cp.async everything
#pragma unroll
    for (int u = 0; u < 2; u++) {           // Q [64 d][64 i] from [h*64+d][i0..]
        int idx = tid + u * 256;
        int d = idx >> 3, ch = (idx & 7) * 8;
        size_t go = (size_t)(h * 64 + d) * NP1 + i0 + ch;
        uint32_t so = (uint32_t)(d * QLD + ch) * 2;
        cpa16(sb + AQH + so, qh + go);
        cpa16(sb + AQL + so, ql + go);
    }
#pragma unroll
    for (int u = 0; u < 8; u++) {           // K and V [64 d][256 j]
        int idx = tid + u * 256;
        int d = idx >> 5, ch = (idx & 31) * 8;
        size_t gk = (size_t)(h * 64 + d) * NP2 + ch;
        size_t gv = (size_t)(NINNER + h * 64 + d) * NP2 + ch;
        uint32_t so = (uint32_t)(d * KLD + ch) * 2;
        cpa16(sb + AKH + so, kh + gk);
        cpa16(sb + AKL + so, kl + gk);
        cpa16(sb + AVH + so, kh + gv);
        cpa16(sb + AVL + so, kl + gv);
    }
    CP_COMMIT();
    CP_WAIT0();
    __syncthreads();

    // phase 1: S[64 i][256 j] = (Q/8) @ K^T ; warp tile 16 x 128
    float acc[16][4];
#pragma unroll
    for (int i = 0; i < 16; i++)
#pragma unroll
        for (int k = 0; k < 4; k++) acc[i][k] = 0.f;

#pragma unroll
    for (int kk = 0; kk < 4; kk++) {
        uint32_t ah[4], al[4];
        uint32_t krow = (uint32_t)(kk*16 + (lane & 7) + ((lane >> 1) & 8));
        uint32_t acol = (uint32_t)(wr*16 + (lane & 8));
        uint32_t aaddr = sb + AQH + (krow * QLD + acol) * 2;
        ldmx4t(ah, aaddr);
        ldmx4t(al, aaddr + (AQL - AQH));
#pragma unroll
        for (int ni2 = 0; ni2 < 8; ni2++) {
            uint32_t bhf[4], blf[4];
            uint32_t baddr = sb + AKH + (uint32_t)((kk*16 + (lane & 15)) * KLD
                                                   + wc*128 + ni2*16 + ((lane & 16) >> 1)) * 2;
            ldmx4t(bhf, baddr);
            ldmx4t(blf, baddr + (AKL - AKH));
            mma16816(acc[ni2*2],   ah, &bhf[0]);
            mma16816(acc[ni2*2],   ah, &blf[0]);
            mma16816(acc[ni2*2],   al, &bhf[0]);
            mma16816(acc[ni2*2+1], ah, &bhf[2]);
            mma16816(acc[ni2*2+1], ah, &blf[2]);
            mma16816(acc[ni2*2+1], al, &bhf[2]);
        }
    }
    __syncthreads();   // Q/K reads done; S overwrites

    // Q was prescaled? No — scale by 0.125 here (exact power of two).
#pragma unroll
    for (int ni = 0; ni < 16; ni++) {
        int r0 = wr*16 + (lane >> 2);
        int c  = wc*128 + ni*8 + (lane & 3) * 2;
        *(float2*)&S[r0 * SLDF + c] = make_float2(acc[ni][0] * 0.125f, acc[ni][1] * 0.125f);
        *(float2*)&S[(r0 + 8) * SLDF + c] = make_float2(acc[ni][2] * 0.125f, acc[ni][3] * 0.125f);
    }
    __syncthreads();

    // softmax: 8 warps x 8 rows → normalized P hi/lo
#pragma unroll
    for (int r = 0; r < 8; r++) {
        int i = wid * 8 + r;
        float vals[8];
        float vmax = -1e30f;
#pragma unroll
        for (int u = 0; u < 8; u++) {
            vals[u] = S[i * SLDF + lane + u * 32];
            vmax = fmaxf(vmax, vals[u]);
        }
#pragma unroll
        for (int off = 16; off > 0; off >>= 1)
            vmax = fmaxf(vmax, __shfl_xor_sync(0xffffffffu, vmax, off));
        float sum = 0.f;
#pragma unroll
        for (int u = 0; u < 8; u++) { vals[u] = __expf(vals[u] - vmax); sum += vals[u]; }
#pragma unroll
        for (int off = 16; off > 0; off >>= 1)
            sum += __shfl_xor_sync(0xffffffffu, sum, off);
        float inv = 1.f / sum;
#pragma unroll
        for (int u = 0; u < 8; u++)
            put_hl(Ph, Pl, i * PLD + lane + u * 32, vals[u] * inv);
    }
    __syncthreads();

    // phase 2: O[64 i][64 d] = P @ V ; warp tile 16 x 32
    float acc2[4][4];
#pragma unroll
    for (int i = 0; i < 4; i++)
#pragma unroll
        for (int k = 0; k < 4; k++) acc2[i][k] = 0.f;

#pragma unroll 4
    for (int kk = 0; kk < 16; kk++) {
        uint32_t ah[4], al[4];
        uint32_t aaddr = sb + APH + (uint32_t)((wr*16 + (lane & 15)) * PLD
                                               + kk*16 + (lane >> 4) * 8) * 2;
        ldmx4(ah, aaddr);
        ldmx4(al, aaddr + (APL - APH));
#pragma unroll
        for (int ni2 = 0; ni2 < 2; ni2++) {
            uint32_t bhf[4], blf[4];
            uint32_t baddr = sb + AVH + (uint32_t)((wc*32 + ni2*16 + ((lane >> 4) & 1) * 8 + (lane & 7)) * KLD
                                                   + kk*16 + ((lane >> 3) & 1) * 8) * 2;
            ldmx4(bhf, baddr);
            ldmx4(blf, baddr + (AVL - AVH));
            mma16816(acc2[ni2*2],   ah, &bhf[0]);
            mma16816(acc2[ni2*2],   ah, &blf[0]);
            mma16816(acc2[ni2*2],   al, &bhf[0]);
            mma16816(acc2[ni2*2+1], ah, &bhf[2]);
            mma16816(acc2[ni2*2+1], ah, &blf[2]);
            mma16816(acc2[ni2*2+1], al, &bhf[2]);
        }
    }

    // stage O to smem, then coalesced hi/lo write to g_ao [d][i]
#pragma unroll
    for (int ni = 0; ni < 4; ni++) {
        int r0 = wr*16 + (lane >> 2), c = wc*32 + ni*8 + (lane & 3) * 2;
        O[r0 * OLD + c] = acc2[ni][0];
        O[r0 * OLD + c + 1] = acc2[ni][1];
        O[(r0 + 8) * OLD + c] = acc2[ni][2];
        O[(r0 + 8) * OLD + c + 1] = acc2[ni][3];
    }
    __syncthreads();
    {
        int d = tid >> 2, ip = (tid & 3) * 16;
        __nv_bfloat16* aoh = &g_ao_h[qin][b][h * 64 + d][i0 + ip];
        __nv_bfloat16* aol = &g_ao_l[qin][b][h * 64 + d][i0 + ip];
#pragma unroll
        for (int u = 0; u < 16; u += 2) {
            float v0 = O[(ip + u) * OLD + d];
            float v1 = O[(ip + u + 1) * OLD + d];
            put_hl2(aoh, aol, u, v0, v1);
        }
    }
}

// ---------------- launch ----------------
extern "C" void kernel_launch(void* const* d_in, const int* in_sizes, int n_in,
                              void* d_out, int out_size)
{
    const float* x      = (const float*)d_in[0];
    const float* y      = (const float*)d_in[1];
    const float* q_dw_w = (const float*)d_in[2];
    const float* q_g    = (const float*)d_in[3];
    const float* q_b    = (const float*)d_in[4];
    const float* q_m    = (const float*)d_in[5];
    const float* q_v    = (const float*)d_in[6];
    const float* q_pw   = (const float*)d_in[7];
    const float* kv_dw_w= (const float*)d_in[8];
    const float* kv_g   = (const float*)d_in[9];
    const float* kv_b   = (const float*)d_in[10];
    const float* kv_m   = (const float*)d_in[11];
    const float* kv_v   = (const float*)d_in[12];
    const float* kv_pw  = (const float*)d_in[13];
    const float* out_w  = (const float*)d_in[14];
    const float* out_b  = (const float*)d_in[15];
    float* out = (float*)d_out;

    __nv_bfloat16 *wq_h, *wq_l, *wkv_h, *wkv_l, *wo_h, *wo_l;
    __nv_bfloat16 *hq_h, *hq_l, *hkv_h, *hkv_l, *q_h, *q_l, *kv_h, *kv_l, *ao_h, *ao_l;
    cudaGetSymbolAddress((void**)&wq_h,  g_wq_h);  cudaGetSymbolAddress((void**)&wq_l,  g_wq_l);
    cudaGetSymbolAddress((void**)&wkv_h, g_wkv_h); cudaGetSymbolAddress((void**)&wkv_l, g_wkv_l);
    cudaGetSymbolAddress((void**)&wo_h,  g_wo_h);  cudaGetSymbolAddress((void**)&wo_l,  g_wo_l);
    cudaGetSymbolAddress((void**)&hq_h,  g_hq_h);  cudaGetSymbolAddress((void**)&hq_l,  g_hq_l);
    cudaGetSymbolAddress((void**)&hkv_h, g_hkv_h); cudaGetSymbolAddress((void**)&hkv_l, g_hkv_l);
    cudaGetSymbolAddress((void**)&q_h,   g_q_h);   cudaGetSymbolAddress((void**)&q_l,   g_q_l);
    cudaGetSymbolAddress((void**)&kv_h,  g_kv_h);  cudaGetSymbolAddress((void**)&kv_l,  g_kv_l);
    cudaGetSymbolAddress((void**)&ao_h,  g_ao_h);  cudaGetSymbolAddress((void**)&ao_l,  g_ao_l);

    cudaFuncSetAttribute(mm_attn2, cudaFuncAttributeMaxDynamicSharedMemorySize, ATT_SM2);
    cudaFuncSetAttribute(mm_gemm2, cudaFuncAttributeMaxDynamicSharedMemorySize, GSM2);

    // weights -> hi/lo
    cvt_hl_kernel<<<(NINNER * NC / 2 + 255) / 256, 256>>>(q_pw,  wq_h,  wq_l,  NINNER * NC / 2);
    cvt_hl_kernel<<<(2 * NINNER * NC / 2 + 255) / 256, 256>>>(kv_pw, wkv_h, wkv_l, 2 * NINNER * NC / 2);
    cvt_hl_kernel<<<(NC * NINNER / 2 + 255) / 256, 256>>>(out_w, wo_h,  wo_l,  NC * NINNER / 2);

    dwbn1_kernel<<<dim3(NB * NC, 2), 1024>>>(x, y, q_dw_w, q_g, q_b, q_m, q_v);
    dwbn2_kernel<<<dim3(NB * NC, 2), 256>>>(x, y, kv_dw_w, kv_g, kv_b, kv_m, kv_v);

    size_t szHQ = (size_t)NB * NC * NP1;
    size_t szHKV = (size_t)NB * NC * NP2;
    size_t szQ = (size_t)NB * NINNER * NP1;
    size_t szKV = (size_t)NB * 2 * NINNER * NP2;
    size_t szAO = (size_t)NB * NINNER * NP1;

    for (int inp = 0; inp < 2; inp++) {
        mm_gemm2<<<dim3(NP1 / 128, NINNER / 128, NB), 256, GSM2>>>(
            wq_h, wq_l, hq_h + inp * szHQ, hq_l + inp * szHQ,
            q_h + inp * szQ, q_l + inp * szQ, nullptr, nullptr,
            NINNER, NC, NP1);
        mm_gemm2<<<dim3(NP2 / 128, (2 * NINNER) / 128, NB), 256, GSM2>>>(
            wkv_h, wkv_l, hkv_h + inp * szHKV, hkv_l + inp * szHKV,
            kv_h + inp * szKV, kv_l + inp * szKV, nullptr, nullptr,
            2 * NINNER, NC, NP2);
    }

    mm_attn2<<<dim3(NP1 / 64, NB * 8, 2), 256, ATT_SM2>>>();

    for (int inp = 0; inp < 2; inp++) {
        mm_gemm2<<<dim3(NP1 / 128, NC / 128, NB), 256, GSM2>>>(
            wo_h, wo_l, ao_h + inp * szAO, ao_l + inp * szAO,
            nullptr, nullptr, out + (size_t)inp * NB * NC * NP1, out_b,
            NC, NINNER, NP1);
    }
}

// round 6
// speedup vs baseline: 2.4626x; 1.1084x over previous
#include <cuda_runtime.h>
#include <cuda_bf16.h>
#include <stdint.h>
#include <math.h>

#define NB 8
#define NC 256
#define NP1 1024
#define NP2 256
#define NINNER 512
#define BN_EPS 1e-5f

// ---------------- bf16 hi/lo scratch ----------------
__device__ __nv_bfloat16 g_hq_h [2][NB][NC][NP1],      g_hq_l [2][NB][NC][NP1];
__device__ __nv_bfloat16 g_hkv_h[2][NB][NC][NP2],      g_hkv_l[2][NB][NC][NP2];
__device__ __nv_bfloat16 g_q_h  [2][NB][NINNER][NP1],  g_q_l  [2][NB][NINNER][NP1];
__device__ __nv_bfloat16 g_kv_h [2][NB][2*NINNER][NP2],g_kv_l [2][NB][2*NINNER][NP2];
__device__ __nv_bfloat16 g_ao_h [2][NB][NINNER][NP1],  g_ao_l [2][NB][NINNER][NP1];
__device__ __nv_bfloat16 g_wq_h [NINNER*NC],   g_wq_l [NINNER*NC];
__device__ __nv_bfloat16 g_wkv_h[2*NINNER*NC], g_wkv_l[2*NINNER*NC];
__device__ __nv_bfloat16 g_wo_h [NC*NINNER],   g_wo_l [NC*NINNER];

// ---------------- helpers ----------------
__device__ __forceinline__ uint32_t smem_u32(const void* p){
    uint32_t a;
    asm("{ .reg .u64 t; cvta.to.shared.u64 t, %1; cvt.u32.u64 %0, t; }" : "=r"(a) : "l"(p));
    return a;
}
__device__ __forceinline__ void ldmx4(uint32_t* r, uint32_t a){
    asm volatile("ldmatrix.sync.aligned.m8n8.x4.shared.b16 {%0,%1,%2,%3}, [%4];"
        : "=r"(r[0]),"=r"(r[1]),"=r"(r[2]),"=r"(r[3]) : "r"(a) : "memory");
}
__device__ __forceinline__ void ldmx4t(uint32_t* r, uint32_t a){
    asm volatile("ldmatrix.sync.aligned.m8n8.x4.trans.shared.b16 {%0,%1,%2,%3}, [%4];"
        : "=r"(r[0]),"=r"(r[1]),"=r"(r[2]),"=r"(r[3]) : "r"(a) : "memory");
}
__device__ __forceinline__ void mma16816(float* c, const uint32_t* a, const uint32_t* b){
    asm volatile("mma.sync.aligned.m16n8k16.row.col.f32.bf16.bf16.f32 "
        "{%0,%1,%2,%3}, {%4,%5,%6,%7}, {%8,%9}, {%0,%1,%2,%3};"
        : "+f"(c[0]),"+f"(c[1]),"+f"(c[2]),"+f"(c[3])
        : "r"(a[0]),"r"(a[1]),"r"(a[2]),"r"(a[3]),"r"(b[0]),"r"(b[1]));
}
__device__ __forceinline__ void cpa16(uint32_t s, const void* g){
    asm volatile("cp.async.cg.shared.global [%0], [%1], 16;" :: "r"(s), "l"(g));
}
#define CP_COMMIT() asm volatile("cp.async.commit_group;" ::: "memory")
#define CP_WAIT0()  asm volatile("cp.async.wait_group 0;" ::: "memory")
#define CP_WAIT1()  asm volatile("cp.async.wait_group 1;" ::: "memory")

__device__ __forceinline__ void put_hl(__nv_bfloat16* bh, __nv_bfloat16* bl, int idx, float v){
    __nv_bfloat16 h = __float2bfloat16(v);
    bh[idx] = h;
    bl[idx] = __float2bfloat16(v - __bfloat162float(h));
}
__device__ __forceinline__ void put_hl2(__nv_bfloat16* bh, __nv_bfloat16* bl, int idx, float v0, float v1){
    __nv_bfloat16 h0 = __float2bfloat16(v0), h1 = __float2bfloat16(v1);
    __nv_bfloat162 H; H.x = h0; H.y = h1;
    __nv_bfloat162 L;
    L.x = __float2bfloat16(v0 - __bfloat162float(h0));
    L.y = __float2bfloat16(v1 - __bfloat162float(h1));
    *(__nv_bfloat162*)(bh + idx) = H;
    *(__nv_bfloat162*)(bl + idx) = L;
}

// ---------------- weight fp32 -> hi/lo ----------------
__global__ void cvt_hl_kernel(const float* __restrict__ src, __nv_bfloat16* __restrict__ h,
                              __nv_bfloat16* __restrict__ l, int n2){
    int i = blockIdx.x * 256 + threadIdx.x;
    if (i < n2) {
        float2 v = *(const float2*)(src + i * 2);
        put_hl2(h, l, i * 2, v.x, v.y);
    }
}

// ---------------- fused depthwise conv (s1 + s2) + BN -> bf16 hi/lo ----------------
// 256 threads per (inp, b*c) block. Halo is zero padding (stores, not loads).
__global__ __launch_bounds__(256)
void dwbn_fused(const float* __restrict__ x0, const float* __restrict__ x1,
                const float* __restrict__ qw, const float* __restrict__ qg,
                const float* __restrict__ qb, const float* __restrict__ qm,
                const float* __restrict__ qv,
                const float* __restrict__ kw, const float* __restrict__ kg,
                const float* __restrict__ kb, const float* __restrict__ km,
                const float* __restrict__ kvv)
{
    int inp = blockIdx.y, bc = blockIdx.x, c = bc & 255, b = bc >> 8;
    const float* in = (inp ? x1 : x0) + (size_t)bc * 1024;
    __shared__ float t[34][36];
    int tid = threadIdx.x;

    // zero halo (conv zero-padding)
    if (tid < 34) { t[0][tid] = 0.f; t[33][tid] = 0.f; }
    else if (tid < 66) { int r = tid - 33; t[r][0] = 0.f; t[r][33] = 0.f; }

    // interior: one float4 per thread
    {
        int r = tid >> 3, q = (tid & 7) * 4;
        float4 v = *(const float4*)(in + r * 32 + q);
        t[r + 1][q + 1] = v.x; t[r + 1][q + 2] = v.y;
        t[r + 1][q + 3] = v.z; t[r + 1][q + 4] = v.w;
    }

    float qwr[9], kwr[9];
#pragma unroll
    for (int i = 0; i < 9; i++) { qwr[i] = qw[c * 9 + i]; kwr[i] = kw[c * 9 + i]; }
    float qs  = qg[c] * rsqrtf(qv[c] + BN_EPS);
    float qsh = qb[c] - qm[c] * qs;
    float ks  = kg[c] * rsqrtf(kvv[c] + BN_EPS);
    float ksh = kb[c] - km[c] * ks;
    __syncthreads();

    // stride-1 conv: 1x4 strip per thread
    {
        int oy = tid >> 3, ox = (tid & 7) * 4;
        float o0 = 0.f, o1 = 0.f, o2 = 0.f, o3 = 0.f;
#pragma unroll
        for (int dy = 0; dy < 3; dy++) {
            float a0 = t[oy + dy][ox + 0], a1 = t[oy + dy][ox + 1], a2 = t[oy + dy][ox + 2];
            float a3 = t[oy + dy][ox + 3], a4 = t[oy + dy][ox + 4], a5 = t[oy + dy][ox + 5];
            float w0 = qwr[dy * 3], w1 = qwr[dy * 3 + 1], w2 = qwr[dy * 3 + 2];
            o0 += a0 * w0 + a1 * w1 + a2 * w2;
            o1 += a1 * w0 + a2 * w1 + a3 * w2;
            o2 += a2 * w0 + a3 * w1 + a4 * w2;
            o3 += a3 * w0 + a4 * w1 + a5 * w2;
        }
        o0 = o0 * qs + qsh; o1 = o1 * qs + qsh;
        o2 = o2 * qs + qsh; o3 = o3 * qs + qsh;
        int idx = oy * 32 + ox;
        put_hl2(&g_hq_h[inp][b][c][0], &g_hq_l[inp][b][c][0], idx, o0, o1);
        put_hl2(&g_hq_h[inp][b][c][0], &g_hq_l[inp][b][c][0], idx + 2, o2, o3);
    }

    // stride-2 conv: one output per thread
    {
        int oy = tid >> 4, ox = tid & 15;
        float a = 0.f;
#pragma unroll
        for (int dy = 0; dy < 3; dy++)
#pragma unroll
            for (int dx = 0; dx < 3; dx++)
                a += t[oy * 2 + dy][ox * 2 + dx] * kwr[dy * 3 + dx];
        a = a * ks + ksh;
        put_hl(&g_hkv_h[inp][b][c][0], &g_hkv_l[inp][b][c][0], oy * 16 + ox, a);
    }
}

// ---------------- tensor-core GEMM v2 (bf16 in, cp.async double buffered) ----------------
#define ALD2 40
#define BLD2 136
#define A_H0 0
#define A_H1 10240
#define A_L0 20480
#define A_L1 30720
#define B_H0 40960
#define B_H1 49664
#define B_L0 58368
#define B_L1 67072
#define GSM2 75776

__global__ __launch_bounds__(256)
void mm_gemm2(const __nv_bfloat16* __restrict__ Ah, const __nv_bfloat16* __restrict__ Al,
              const __nv_bfloat16* __restrict__ Bh, const __nv_bfloat16* __restrict__ Bl,
              __nv_bfloat16* __restrict__ Ch, __nv_bfloat16* __restrict__ Cl,
              float* __restrict__ Cf, const float* __restrict__ bias,
              int Mtot, int K, int P)
{
    extern __shared__ char sm[];
    uint32_t sb = smem_u32(sm);
    int tid = threadIdx.x, lane = tid & 31, wid = tid >> 5;
    int wr = wid >> 1, wc = wid & 1;
    int m0 = blockIdx.y * 128, n0 = blockIdx.x * 128;
    size_t zoff = (size_t)blockIdx.z * K * P;
    const __nv_bfloat16* Bhz = Bh + zoff;
    const __nv_bfloat16* Blz = Bl + zoff;

    float acc[2][8][4];
#pragma unroll
    for (int i = 0; i < 2; i++)
#pragma unroll
        for (int j = 0; j < 8; j++)
#pragma unroll
            for (int k = 0; k < 4; k++) acc[i][j][k] = 0.f;

    int niter = K >> 5;

#define LOAD_STAGE(st, k0) do { \
    uint32_t aH = sb + ((st) ? A_H1 : A_H0); \
    uint32_t aL = sb + ((st) ? A_L1 : A_L0); \
    uint32_t bH = sb + ((st) ? B_H1 : B_H0); \
    uint32_t bL = sb + ((st) ? B_L1 : B_L0); \
    _Pragma("unroll") \
    for (int u = 0; u < 2; u++) { \
        int idx = tid + u * 256; \
        int row = idx >> 2, ch = (idx & 3) * 8; \
        size_t go = (size_t)(m0 + row) * K + (k0) + ch; \
        uint32_t so = (uint32_t)(row * ALD2 + ch) * 2; \
        cpa16(aH + so, Ah + go); \
        cpa16(aL + so, Al + go); \
    } \
    _Pragma("unroll") \
    for (int u = 0; u < 2; u++) { \
        int idx = tid + u * 256; \
        int row = idx >> 4, ch = (idx & 15) * 8; \
        size_t go = (size_t)((k0) + row) * P + n0 + ch; \
        uint32_t so = (uint32_t)(row * BLD2 + ch) * 2; \
        cpa16(bH + so, Bhz + go); \
        cpa16(bL + so, Blz + go); \
    } \
} while (0)

    LOAD_STAGE(0, 0);
    CP_COMMIT();

    for (int it = 0; it < niter; it++) {
        if (it + 1 < niter) { LOAD_STAGE((it + 1) & 1, (it + 1) << 5); CP_COMMIT(); CP_WAIT1(); }
        else CP_WAIT0();
        __syncthreads();

        uint32_t aHb = sb + ((it & 1) ? A_H1 : A_H0);
        uint32_t bHb = sb + ((it & 1) ? B_H1 : B_H0);
#pragma unroll
        for (int kk = 0; kk < 2; kk++) {
            uint32_t ah[2][4], al[2][4];
#pragma unroll
            for (int mi = 0; mi < 2; mi++) {
                uint32_t aaddr = aHb + (uint32_t)((wr*32 + mi*16 + (lane & 15)) * ALD2
                                                  + kk*16 + (lane >> 4) * 8) * 2;
                ldmx4(ah[mi], aaddr);
                ldmx4(al[mi], aaddr + 20480u);
            }
#pragma unroll
            for (int ni2 = 0; ni2 < 4; ni2++) {
                uint32_t bh[4], bl[4];
                uint32_t baddr = bHb + (uint32_t)((kk*16 + (lane & 15)) * BLD2
                                                  + wc*64 + ni2*16 + ((lane & 16) >> 1)) * 2;
                ldmx4t(bh, baddr);
                ldmx4t(bl, baddr + 17408u);
#pragma unroll
                for (int mi = 0; mi < 2; mi++) {
                    mma16816(acc[mi][ni2*2],   ah[mi], &bh[0]);
                    mma16816(acc[mi][ni2*2],   ah[mi], &bl[0]);
                    mma16816(acc[mi][ni2*2],   al[mi], &bh[0]);
                    mma16816(acc[mi][ni2*2+1], ah[mi], &bh[2]);
                    mma16816(acc[mi][ni2*2+1], ah[mi], &bl[2]);
                    mma16816(acc[mi][ni2*2+1], al[mi], &bh[2]);
                }
            }
        }
        __syncthreads();
    }

    if (Cf) {
        float* Cp = Cf + (size_t)blockIdx.z * Mtot * P;
#pragma unroll
        for (int mi = 0; mi < 2; mi++) {
            int row = m0 + wr*32 + mi*16 + (lane >> 2);
            float b0 = bias ? bias[row] : 0.f;
            float b1 = bias ? bias[row + 8] : 0.f;
#pragma unroll
            for (int ni = 0; ni < 8; ni++) {
                int col = n0 + wc*64 + ni*8 + (lane & 3) * 2;
                *(float2*)&Cp[(size_t)row * P + col] =
                    make_float2(acc[mi][ni][0] + b0, acc[mi][ni][1] + b0);
                *(float2*)&Cp[(size_t)(row + 8) * P + col] =
                    make_float2(acc[mi][ni][2] + b1, acc[mi][ni][3] + b1);
            }
        }
    } else {
        __nv_bfloat16* Chz = Ch + (size_t)blockIdx.z * Mtot * P;
        __nv_bfloat16* Clz = Cl + (size_t)blockIdx.z * Mtot * P;
#pragma unroll
        for (int mi = 0; mi < 2; mi++) {
            int row = m0 + wr*32 + mi*16 + (lane >> 2);
#pragma unroll
            for (int ni = 0; ni < 8; ni++) {
                int col = n0 + wc*64 + ni*8 + (lane & 3) * 2;
                put_hl2(Chz, Clz, (int)((size_t)row * P + col), acc[mi][ni][0], acc[mi][ni][1]);
                put_hl2(Chz, Clz, (int)((size_t)(row + 8) * P + col), acc[mi][ni][2], acc[mi][ni][3]);
            }
        }
    }
}

// ---------------- fused attention v2 (bf16 in, cp.async) ----------------
#define QLD 72
#define KLD 264
#define SLDF 264
#define PLD 264
#define OLD 65
#define AQH 0
#define AQL 9216
#define AKH 18432
#define AKL 52224
#define AVH 86016
#define AVL 119808
#define APH 153600
#define APL 187392
#define ATT_SM2 221184

__global__ __launch_bounds__(256)
void mm_attn2()
{
    extern __shared__ char sm[];
    uint32_t sb = smem_u32(sm);
    float* S = (float*)sm;
    float* O = (float*)sm;
    __nv_bfloat16* Ph = (__nv_bfloat16*)(sm + APH);
    __nv_bfloat16* Pl = (__nv_bfloat16*)(sm + APL);

    int tid = threadIdx.x, lane = tid & 31, wid = tid >> 5;
    int dir = blockIdx.z, bh = blockIdx.y;
    int b = bh >> 3, h = bh & 7;
    int i0 = blockIdx.x * 64;
    int qin = dir, kin = dir ^ 1;
    int wr = wid >> 1, wc = wid & 1;

    const __nv_bfloat16* qh = &g_q_h[qin][b][0][0];
    const __nv_bfloat16* ql = &g_q_l[qin][b][0][0];
    const __nv_bfloat16* kh = &g_kv_h[kin][b][0][0];
    const __nv_bfloat16* kl = &g_kv_l[kin][b][0][0];

#pragma unroll
    for (int u = 0; u < 2; u++) {
        int idx = tid + u * 256;
        int d = idx >> 3, ch = (idx & 7) * 8;
        size_t go = (size_t)(h * 64 + d) * NP1 + i0 + ch;
        uint32_t so = (uint32_t)(d * QLD + ch) * 2;
        cpa16(sb + AQH + so, qh + go);
        cpa16(sb + AQL + so, ql + go);
    }
#pragma unroll
    for (int u = 0; u < 8; u++) {
        int idx = tid + u * 256;
        int d = idx >> 5, ch = (idx & 31) * 8;
        size_t gk = (size_t)(h * 64 + d) * NP2 + ch;
        size_t gv = (size_t)(NINNER + h * 64 + d) * NP2 + ch;
        uint32_t so = (uint32_t)(d * KLD + ch) * 2;
        cpa16(sb + AKH + so, kh + gk);
        cpa16(sb + AKL + so, kl + gk);
        cpa16(sb + AVH + so, kh + gv);
        cpa16(sb + AVL + so, kl + gv);
    }
    CP_COMMIT();
    CP_WAIT0();
    __syncthreads();

    float acc[16][4];
#pragma unroll
    for (int i = 0; i < 16; i++)
#pragma unroll
        for (int k = 0; k < 4; k++) acc[i][k] = 0.f;

#pragma unroll
    for (int kk = 0; kk < 4; kk++) {
        uint32_t ah[4], al[4];
        uint32_t krow = (uint32_t)(kk*16 + (lane & 7) + ((lane >> 1) & 8));
        uint32_t acol = (uint32_t)(wr*16 + (lane & 8));
        uint32_t aaddr = sb + AQH + (krow * QLD + acol) * 2;
        ldmx4t(ah, aaddr);
        ldmx4t(al, aaddr + (AQL - AQH));
#pragma unroll
        for (int ni2 = 0; ni2 < 8; ni2++) {
            uint32_t bhf[4], blf[4];
            uint32_t baddr = sb + AKH + (uint32_t)((kk*16 + (lane & 15)) * KLD
                                                   + wc*128 + ni2*16 + ((lane & 16) >> 1)) * 2;
            ldmx4t(bhf, baddr);
            ldmx4t(blf, baddr + (AKL - AKH));
            mma16816(acc[ni2*2],   ah, &bhf[0]);
            mma16816(acc[ni2*2],   ah, &blf[0]);
            mma16816(acc[ni2*2],   al, &bhf[0]);
            mma16816(acc[ni2*2+1], ah, &bhf[2]);
            mma16816(acc[ni2*2+1], ah, &blf[2]);
            mma16816(acc[ni2*2+1], al, &bhf[2]);
        }
    }
    __syncthreads();

#pragma unroll
    for (int ni = 0; ni < 16; ni++) {
        int r0 = wr*16 + (lane >> 2);
        int c  = wc*128 + ni*8 + (lane & 3) * 2;
        *(float2*)&S[r0 * SLDF + c] = make_float2(acc[ni][0] * 0.125f, acc[ni][1] * 0.125f);
        *(float2*)&S[(r0 + 8) * SLDF + c] = make_float2(acc[ni][2] * 0.125f, acc[ni][3] * 0.125f);
    }
    __syncthreads();

#pragma unroll
    for (int r = 0; r < 8; r++) {
        int i = wid * 8 + r;
        float vals[8];
        float vmax = -1e30f;
#pragma unroll
        for (int u = 0; u < 8; u++) {
            vals[u] = S[i * SLDF + lane + u * 32];
            vmax = fmaxf(vmax, vals[u]);
        }
#pragma unroll
        for (int off = 16; off > 0; off >>= 1)
            vmax = fmaxf(vmax, __shfl_xor_sync(0xffffffffu, vmax, off));
        float sum = 0.f;
#pragma unroll
        for (int u = 0; u < 8; u++) { vals[u] = __expf(vals[u] - vmax); sum += vals[u]; }
#pragma unroll
        for (int off = 16; off > 0; off >>= 1)
            sum += __shfl_xor_sync(0xffffffffu, sum, off);
        float inv = 1.f / sum;
#pragma unroll
        for (int u = 0; u < 8; u++)
            put_hl(Ph, Pl, i * PLD + lane + u * 32, vals[u] * inv);
    }
    __syncthreads();

    float acc2[4][4];
#pragma unroll
    for (int i = 0; i < 4; i++)
#pragma unroll
        for (int k = 0; k < 4; k++) acc2[i][k] = 0.f;

#pragma unroll 4
    for (int kk = 0; kk < 16; kk++) {
        uint32_t ah[4], al[4];
        uint32_t aaddr = sb + APH + (uint32_t)((wr*16 + (lane & 15)) * PLD
                                               + kk*16 + (lane >> 4) * 8) * 2;
        ldmx4(ah, aaddr);
        ldmx4(al, aaddr + (APL - APH));
#pragma unroll
        for (int ni2 = 0; ni2 < 2; ni2++) {
            uint32_t bhf[4], blf[4];
            uint32_t baddr = sb + AVH + (uint32_t)((wc*32 + ni2*16 + ((lane >> 4) & 1) * 8 + (lane & 7)) * KLD
                                                   + kk*16 + ((lane >> 3) & 1) * 8) * 2;
            ldmx4(bhf, baddr);
            ldmx4(blf, baddr + (AVL - AVH));
            mma16816(acc2[ni2*2],   ah, &bhf[0]);
            mma16816(acc2[ni2*2],   ah, &blf[0]);
            mma16816(acc2[ni2*2],   al, &bhf[0]);
            mma16816(acc2[ni2*2+1], ah, &bhf[2]);
            mma16816(acc2[ni2*2+1], ah, &blf[2]);
            mma16816(acc2[ni2*2+1], al, &bhf[2]);
        }
    }

#pragma unroll
    for (int ni = 0; ni < 4; ni++) {
        int r0 = wr*16 + (lane >> 2), c = wc*32 + ni*8 + (lane & 3) * 2;
        O[r0 * OLD + c] = acc2[ni][0];
        O[r0 * OLD + c + 1] = acc2[ni][1];
        O[(r0 + 8) * OLD + c] = acc2[ni][2];
        O[(r0 + 8) * OLD + c + 1] = acc2[ni][3];
    }
    __syncthreads();
    {
        int d = tid >> 2, ip = (tid & 3) * 16;
        __nv_bfloat16* aoh = &g_ao_h[qin][b][h * 64 + d][i0 + ip];
        __nv_bfloat16* aol = &g_ao_l[qin][b][h * 64 + d][i0 + ip];
#pragma unroll
        for (int u = 0; u < 16; u += 2) {
            float v0 = O[(ip + u) * OLD + d];
            float v1 = O[(ip + u + 1) * OLD + d];
            put_hl2(aoh, aol, u, v0, v1);
        }
    }
}

// ---------------- launch ----------------
extern "C" void kernel_launch(void* const* d_in, const int* in_sizes, int n_in,
                              void* d_out, int out_size)
{
    const float* x      = (const float*)d_in[0];
    const float* y      = (const float*)d_in[1];
    const float* q_dw_w = (const float*)d_in[2];
    const float* q_g    = (const float*)d_in[3];
    const float* q_b    = (const float*)d_in[4];
    const float* q_m    = (const float*)d_in[5];
    const float* q_v    = (const float*)d_in[6];
    const float* q_pw   = (const float*)d_in[7];
    const float* kv_dw_w= (const float*)d_in[8];
    const float* kv_g   = (const float*)d_in[9];
    const float* kv_b   = (const float*)d_in[10];
    const float* kv_m   = (const float*)d_in[11];
    const float* kv_v   = (const float*)d_in[12];
    const float* kv_pw  = (const float*)d_in[13];
    const float* out_w  = (const float*)d_in[14];
    const float* out_b  = (const float*)d_in[15];
    float* out = (float*)d_out;

    __nv_bfloat16 *wq_h, *wq_l, *wkv_h, *wkv_l, *wo_h, *wo_l;
    __nv_bfloat16 *hq_h, *hq_l, *hkv_h, *hkv_l, *q_hp, *q_lp, *kv_hp, *kv_lp, *ao_h, *ao_l;
    cudaGetSymbolAddress((void**)&wq_h,  g_wq_h);  cudaGetSymbolAddress((void**)&wq_l,  g_wq_l);
    cudaGetSymbolAddress((void**)&wkv_h, g_wkv_h); cudaGetSymbolAddress((void**)&wkv_l, g_wkv_l);
    cudaGetSymbolAddress((void**)&wo_h,  g_wo_h);  cudaGetSymbolAddress((void**)&wo_l,  g_wo_l);
    cudaGetSymbolAddress((void**)&hq_h,  g_hq_h);  cudaGetSymbolAddress((void**)&hq_l,  g_hq_l);
    cudaGetSymbolAddress((void**)&hkv_h, g_hkv_h); cudaGetSymbolAddress((void**)&hkv_l, g_hkv_l);
    cudaGetSymbolAddress((void**)&q_hp,  g_q_h);   cudaGetSymbolAddress((void**)&q_lp,  g_q_l);
    cudaGetSymbolAddress((void**)&kv_hp, g_kv_h);  cudaGetSymbolAddress((void**)&kv_lp, g_kv_l);
    cudaGetSymbolAddress((void**)&ao_h,  g_ao_h);  cudaGetSymbolAddress((void**)&ao_l,  g_ao_l);

    cudaFuncSetAttribute(mm_attn2, cudaFuncAttributeMaxDynamicSharedMemorySize, ATT_SM2);
    cudaFuncSetAttribute(mm_gemm2, cudaFuncAttributeMaxDynamicSharedMemorySize, GSM2);

    cvt_hl_kernel<<<(NINNER * NC / 2 + 255) / 256, 256>>>(q_pw,  wq_h,  wq_l,  NINNER * NC / 2);
    cvt_hl_kernel<<<(2 * NINNER * NC / 2 + 255) / 256, 256>>>(kv_pw, wkv_h, wkv_l, 2 * NINNER * NC / 2);
    cvt_hl_kernel<<<(NC * NINNER / 2 + 255) / 256, 256>>>(out_w, wo_h,  wo_l,  NC * NINNER / 2);

    dwbn_fused<<<dim3(NB * NC, 2), 256>>>(x, y,
        q_dw_w, q_g, q_b, q_m, q_v,
        kv_dw_w, kv_g, kv_b, kv_m, kv_v);

    // q projection: z = inp*8 + b (scratch slabs contiguous over [inp][b])
    mm_gemm2<<<dim3(NP1 / 128, NINNER / 128, 2 * NB), 256, GSM2>>>(
        wq_h, wq_l, hq_h, hq_l, q_hp, q_lp, nullptr, nullptr,
        NINNER, NC, NP1);
    // kv projection
    mm_gemm2<<<dim3(NP2 / 128, (2 * NINNER) / 128, 2 * NB), 256, GSM2>>>(
        wkv_h, wkv_l, hkv_h, hkv_l, kv_hp, kv_lp, nullptr, nullptr,
        2 * NINNER, NC, NP2);

    mm_attn2<<<dim3(NP1 / 64, NB * 8, 2), 256, ATT_SM2>>>();

    // output projection straight into d_out (tuple (outx, outy) contiguous)
    mm_gemm2<<<dim3(NP1 / 128, NC / 128, 2 * NB), 256, GSM2>>>(
        wo_h, wo_l, ao_h, ao_l, nullptr, nullptr, out, out_b,
        NC, NINNER, NP1);
}

// round 7
// speedup vs baseline: 2.7391x; 1.1123x over previous
#include <cuda_runtime.h>
#include <cuda_bf16.h>
#include <stdint.h>
#include <math.h>

#define NB 8
#define NC 256
#define NP1 1024
#define NP2 256
#define NINNER 512
#define BN_EPS 1e-5f

// ---------------- bf16 hi/lo scratch ----------------
__device__ __nv_bfloat16 g_hq_h [2][NB][NC][NP1],      g_hq_l [2][NB][NC][NP1];
__device__ __nv_bfloat16 g_hkv_h[2][NB][NC][NP2],      g_hkv_l[2][NB][NC][NP2];
__device__ __nv_bfloat16 g_q_h  [2][NB][NINNER][NP1],  g_q_l  [2][NB][NINNER][NP1];
__device__ __nv_bfloat16 g_kv_h [2][NB][2*NINNER][NP2],g_kv_l [2][NB][2*NINNER][NP2];
__device__ __nv_bfloat16 g_ao_h [2][NB][NINNER][NP1],  g_ao_l [2][NB][NINNER][NP1];
__device__ __nv_bfloat16 g_wq_h [NINNER*NC],   g_wq_l [NINNER*NC];
__device__ __nv_bfloat16 g_wkv_h[2*NINNER*NC], g_wkv_l[2*NINNER*NC];
__device__ __nv_bfloat16 g_wo_h [NC*NINNER],   g_wo_l [NC*NINNER];

// ---------------- helpers ----------------
__device__ __forceinline__ uint32_t smem_u32(const void* p){
    uint32_t a;
    asm("{ .reg .u64 t; cvta.to.shared.u64 t, %1; cvt.u32.u64 %0, t; }" : "=r"(a) : "l"(p));
    return a;
}
__device__ __forceinline__ void ldmx4(uint32_t* r, uint32_t a){
    asm volatile("ldmatrix.sync.aligned.m8n8.x4.shared.b16 {%0,%1,%2,%3}, [%4];"
        : "=r"(r[0]),"=r"(r[1]),"=r"(r[2]),"=r"(r[3]) : "r"(a) : "memory");
}
__device__ __forceinline__ void ldmx4t(uint32_t* r, uint32_t a){
    asm volatile("ldmatrix.sync.aligned.m8n8.x4.trans.shared.b16 {%0,%1,%2,%3}, [%4];"
        : "=r"(r[0]),"=r"(r[1]),"=r"(r[2]),"=r"(r[3]) : "r"(a) : "memory");
}
__device__ __forceinline__ void mma16816(float* c, const uint32_t* a, const uint32_t* b){
    asm volatile("mma.sync.aligned.m16n8k16.row.col.f32.bf16.bf16.f32 "
        "{%0,%1,%2,%3}, {%4,%5,%6,%7}, {%8,%9}, {%0,%1,%2,%3};"
        : "+f"(c[0]),"+f"(c[1]),"+f"(c[2]),"+f"(c[3])
        : "r"(a[0]),"r"(a[1]),"r"(a[2]),"r"(a[3]),"r"(b[0]),"r"(b[1]));
}
__device__ __forceinline__ void cpa16(uint32_t s, const void* g){
    asm volatile("cp.async.cg.shared.global [%0], [%1], 16;" :: "r"(s), "l"(g));
}
#define CP_COMMIT() asm volatile("cp.async.commit_group;" ::: "memory")
#define CP_WAIT0()  asm volatile("cp.async.wait_group 0;" ::: "memory")
#define CP_WAIT1()  asm volatile("cp.async.wait_group 1;" ::: "memory")

__device__ __forceinline__ void put_hl(__nv_bfloat16* bh, __nv_bfloat16* bl, int idx, float v){
    __nv_bfloat16 h = __float2bfloat16(v);
    bh[idx] = h;
    bl[idx] = __float2bfloat16(v - __bfloat162float(h));
}
__device__ __forceinline__ void put_hl2(__nv_bfloat16* bh, __nv_bfloat16* bl, int idx, float v0, float v1){
    __nv_bfloat16 h0 = __float2bfloat16(v0), h1 = __float2bfloat16(v1);
    __nv_bfloat162 H; H.x = h0; H.y = h1;
    __nv_bfloat162 L;
    L.x = __float2bfloat16(v0 - __bfloat162float(h0));
    L.y = __float2bfloat16(v1 - __bfloat162float(h1));
    *(__nv_bfloat162*)(bh + idx) = H;
    *(__nv_bfloat162*)(bl + idx) = L;
}

// ---------------- weight fp32 -> hi/lo ----------------
__global__ void cvt_hl_kernel(const float* __restrict__ src, __nv_bfloat16* __restrict__ h,
                              __nv_bfloat16* __restrict__ l, int n2){
    int i = blockIdx.x * 256 + threadIdx.x;
    if (i < n2) {
        float2 v = *(const float2*)(src + i * 2);
        put_hl2(h, l, i * 2, v.x, v.y);
    }
}

// ---------------- fused depthwise conv (s1 + s2) + BN -> bf16 hi/lo ----------------
__global__ __launch_bounds__(256)
void dwbn_fused(const float* __restrict__ x0, const float* __restrict__ x1,
                const float* __restrict__ qw, const float* __restrict__ qg,
                const float* __restrict__ qb, const float* __restrict__ qm,
                const float* __restrict__ qv,
                const float* __restrict__ kw, const float* __restrict__ kg,
                const float* __restrict__ kb, const float* __restrict__ km,
                const float* __restrict__ kvv)
{
    int inp = blockIdx.y, bc = blockIdx.x, c = bc & 255, b = bc >> 8;
    const float* in = (inp ? x1 : x0) + (size_t)bc * 1024;
    __shared__ float t[34][36];
    int tid = threadIdx.x;

    if (tid < 34) { t[0][tid] = 0.f; t[33][tid] = 0.f; }
    else if (tid < 66) { int r = tid - 33; t[r][0] = 0.f; t[r][33] = 0.f; }

    {
        int r = tid >> 3, q = (tid & 7) * 4;
        float4 v = *(const float4*)(in + r * 32 + q);
        t[r + 1][q + 1] = v.x; t[r + 1][q + 2] = v.y;
        t[r + 1][q + 3] = v.z; t[r + 1][q + 4] = v.w;
    }

    float qwr[9], kwr[9];
#pragma unroll
    for (int i = 0; i < 9; i++) { qwr[i] = qw[c * 9 + i]; kwr[i] = kw[c * 9 + i]; }
    float qs  = qg[c] * rsqrtf(qv[c] + BN_EPS);
    float qsh = qb[c] - qm[c] * qs;
    float ks  = kg[c] * rsqrtf(kvv[c] + BN_EPS);
    float ksh = kb[c] - km[c] * ks;
    __syncthreads();

    {
        int oy = tid >> 3, ox = (tid & 7) * 4;
        float o0 = 0.f, o1 = 0.f, o2 = 0.f, o3 = 0.f;
#pragma unroll
        for (int dy = 0; dy < 3; dy++) {
            float a0 = t[oy + dy][ox + 0], a1 = t[oy + dy][ox + 1], a2 = t[oy + dy][ox + 2];
            float a3 = t[oy + dy][ox + 3], a4 = t[oy + dy][ox + 4], a5 = t[oy + dy][ox + 5];
            float w0 = qwr[dy * 3], w1 = qwr[dy * 3 + 1], w2 = qwr[dy * 3 + 2];
            o0 += a0 * w0 + a1 * w1 + a2 * w2;
            o1 += a1 * w0 + a2 * w1 + a3 * w2;
            o2 += a2 * w0 + a3 * w1 + a4 * w2;
            o3 += a3 * w0 + a4 * w1 + a5 * w2;
        }
        o0 = o0 * qs + qsh; o1 = o1 * qs + qsh;
        o2 = o2 * qs + qsh; o3 = o3 * qs + qsh;
        int idx = oy * 32 + ox;
        put_hl2(&g_hq_h[inp][b][c][0], &g_hq_l[inp][b][c][0], idx, o0, o1);
        put_hl2(&g_hq_h[inp][b][c][0], &g_hq_l[inp][b][c][0], idx + 2, o2, o3);
    }

    {
        int oy = tid >> 4, ox = tid & 15;
        float a = 0.f;
#pragma unroll
        for (int dy = 0; dy < 3; dy++)
#pragma unroll
            for (int dx = 0; dx < 3; dx++)
                a += t[oy * 2 + dy][ox * 2 + dx] * kwr[dy * 3 + dx];
        a = a * ks + ksh;
        put_hl(&g_hkv_h[inp][b][c][0], &g_hkv_l[inp][b][c][0], oy * 16 + ox, a);
    }
}

// ---------------- tensor-core GEMM v2 (unchanged from R6) ----------------
#define ALD2 40
#define BLD2 136
#define A_H0 0
#define A_H1 10240
#define A_L0 20480
#define A_L1 30720
#define B_H0 40960
#define B_H1 49664
#define B_L0 58368
#define B_L1 67072
#define GSM2 75776

__global__ __launch_bounds__(256)
void mm_gemm2(const __nv_bfloat16* __restrict__ Ah, const __nv_bfloat16* __restrict__ Al,
              const __nv_bfloat16* __restrict__ Bh, const __nv_bfloat16* __restrict__ Bl,
              __nv_bfloat16* __restrict__ Ch, __nv_bfloat16* __restrict__ Cl,
              float* __restrict__ Cf, const float* __restrict__ bias,
              int Mtot, int K, int P)
{
    extern __shared__ char sm[];
    uint32_t sb = smem_u32(sm);
    int tid = threadIdx.x, lane = tid & 31, wid = tid >> 5;
    int wr = wid >> 1, wc = wid & 1;
    int m0 = blockIdx.y * 128, n0 = blockIdx.x * 128;
    size_t zoff = (size_t)blockIdx.z * K * P;
    const __nv_bfloat16* Bhz = Bh + zoff;
    const __nv_bfloat16* Blz = Bl + zoff;

    float acc[2][8][4];
#pragma unroll
    for (int i = 0; i < 2; i++)
#pragma unroll
        for (int j = 0; j < 8; j++)
#pragma unroll
            for (int k = 0; k < 4; k++) acc[i][j][k] = 0.f;

    int niter = K >> 5;

#define LOAD_STAGE(st, k0) do { \
    uint32_t aH = sb + ((st) ? A_H1 : A_H0); \
    uint32_t aL = sb + ((st) ? A_L1 : A_L0); \
    uint32_t bH = sb + ((st) ? B_H1 : B_H0); \
    uint32_t bL = sb + ((st) ? B_L1 : B_L0); \
    _Pragma("unroll") \
    for (int u = 0; u < 2; u++) { \
        int idx = tid + u * 256; \
        int row = idx >> 2, ch = (idx & 3) * 8; \
        size_t go = (size_t)(m0 + row) * K + (k0) + ch; \
        uint32_t so = (uint32_t)(row * ALD2 + ch) * 2; \
        cpa16(aH + so, Ah + go); \
        cpa16(aL + so, Al + go); \
    } \
    _Pragma("unroll") \
    for (int u = 0; u < 2; u++) { \
        int idx = tid + u * 256; \
        int row = idx >> 4, ch = (idx & 15) * 8; \
        size_t go = (size_t)((k0) + row) * P + n0 + ch; \
        uint32_t so = (uint32_t)(row * BLD2 + ch) * 2; \
        cpa16(bH + so, Bhz + go); \
        cpa16(bL + so, Blz + go); \
    } \
} while (0)

    LOAD_STAGE(0, 0);
    CP_COMMIT();

    for (int it = 0; it < niter; it++) {
        if (it + 1 < niter) { LOAD_STAGE((it + 1) & 1, (it + 1) << 5); CP_COMMIT(); CP_WAIT1(); }
        else CP_WAIT0();
        __syncthreads();

        uint32_t aHb = sb + ((it & 1) ? A_H1 : A_H0);
        uint32_t bHb = sb + ((it & 1) ? B_H1 : B_H0);
#pragma unroll
        for (int kk = 0; kk < 2; kk++) {
            uint32_t ah[2][4], al[2][4];
#pragma unroll
            for (int mi = 0; mi < 2; mi++) {
                uint32_t aaddr = aHb + (uint32_t)((wr*32 + mi*16 + (lane & 15)) * ALD2
                                                  + kk*16 + (lane >> 4) * 8) * 2;
                ldmx4(ah[mi], aaddr);
                ldmx4(al[mi], aaddr + 20480u);
            }
#pragma unroll
            for (int ni2 = 0; ni2 < 4; ni2++) {
                uint32_t bh[4], bl[4];
                uint32_t baddr = bHb + (uint32_t)((kk*16 + (lane & 15)) * BLD2
                                                  + wc*64 + ni2*16 + ((lane & 16) >> 1)) * 2;
                ldmx4t(bh, baddr);
                ldmx4t(bl, baddr + 17408u);
#pragma unroll
                for (int mi = 0; mi < 2; mi++) {
                    mma16816(acc[mi][ni2*2],   ah[mi], &bh[0]);
                    mma16816(acc[mi][ni2*2],   ah[mi], &bl[0]);
                    mma16816(acc[mi][ni2*2],   al[mi], &bh[0]);
                    mma16816(acc[mi][ni2*2+1], ah[mi], &bh[2]);
                    mma16816(acc[mi][ni2*2+1], ah[mi], &bl[2]);
                    mma16816(acc[mi][ni2*2+1], al[mi], &bh[2]);
                }
            }
        }
        __syncthreads();
    }

    if (Cf) {
        float* Cp = Cf + (size_t)blockIdx.z * Mtot * P;
#pragma unroll
        for (int mi = 0; mi < 2; mi++) {
            int row = m0 + wr*32 + mi*16 + (lane >> 2);
            float b0 = bias ? bias[row] : 0.f;
            float b1 = bias ? bias[row + 8] : 0.f;
#pragma unroll
            for (int ni = 0; ni < 8; ni++) {
                int col = n0 + wc*64 + ni*8 + (lane & 3) * 2;
                *(float2*)&Cp[(size_t)row * P + col] =
                    make_float2(acc[mi][ni][0] + b0, acc[mi][ni][1] + b0);
                *(float2*)&Cp[(size_t)(row + 8) * P + col] =
                    make_float2(acc[mi][ni][2] + b1, acc[mi][ni][3] + b1);
            }
        }
    } else {
        __nv_bfloat16* Chz = Ch + (size_t)blockIdx.z * Mtot * P;
        __nv_bfloat16* Clz = Cl + (size_t)blockIdx.z * Mtot * P;
#pragma unroll
        for (int mi = 0; mi < 2; mi++) {
            int row = m0 + wr*32 + mi*16 + (lane >> 2);
#pragma unroll
            for (int ni = 0; ni < 8; ni++) {
                int col = n0 + wc*64 + ni*8 + (lane & 3) * 2;
                put_hl2(Chz, Clz, (int)((size_t)row * P + col), acc[mi][ni][0], acc[mi][ni][1]);
                put_hl2(Chz, Clz, (int)((size_t)(row + 8) * P + col), acc[mi][ni][2], acc[mi][ni][3]);
            }
        }
    }
}

// ---------------- fused attention v3: 512 threads, register softmax ----------------
// smem: Q[64d][72i] hi/lo (0..18432) | K[64d][264j] hi/lo (18432..86016)
//       V[64d][264j] hi/lo (86016..153600) | red 64x4 f32 (153600..154624)
// P hi/lo aliases K region after phase 1; O fp32 stage aliases Q region.
#define QLD3 72
#define KLD3 264
#define PLD3 264
#define OLD3 65
#define AQH3 0
#define AQL3 9216
#define AKH3 18432
#define AKL3 52224
#define AVH3 86016
#define AVL3 119808
#define ARED 153600
#define ATT_SM3 154624

__global__ __launch_bounds__(512)
void mm_attn3()
{
    extern __shared__ char sm[];
    uint32_t sb = smem_u32(sm);
    float* red = (float*)(sm + ARED);
    float* O   = (float*)sm;                          // aliases Q region in epilogue
    __nv_bfloat16* Ph = (__nv_bfloat16*)(sm + AKH3);  // aliases K-hi region
    __nv_bfloat16* Pl = (__nv_bfloat16*)(sm + AKL3);  // aliases K-lo region

    int tid = threadIdx.x, lane = tid & 31, wid = tid >> 5;
    int dir = blockIdx.z, bh = blockIdx.y;
    int b = bh >> 3, h = bh & 7;
    int i0 = blockIdx.x * 64;
    int qin = dir, kin = dir ^ 1;
    int wr = wid >> 2, wc = wid & 3;   // 4x4 warp grid

    const __nv_bfloat16* qh = &g_q_h[qin][b][0][0];
    const __nv_bfloat16* ql = &g_q_l[qin][b][0][0];
    const __nv_bfloat16* kh = &g_kv_h[kin][b][0][0];
    const __nv_bfloat16* kl = &g_kv_l[kin][b][0][0];

    // Q: 512 transfers (hi for tid<256, lo for tid>=256)
    {
        int half = tid >> 8, t = tid & 255;
        int d = t >> 2, ch = (t & 3) * 16;
        size_t go = (size_t)(h * 64 + d) * NP1 + i0 + ch;
        uint32_t so = sb + (half ? AQL3 : AQH3) + (uint32_t)(d * QLD3 + ch) * 2;
        cpa16(so, (half ? ql : qh) + go);
        cpa16(so + 16, (half ? ql : qh) + go + 8);
    }
    // K, V: [64 d][256 j] each hi/lo
#pragma unroll
    for (int u = 0; u < 4; u++) {
        int idx = tid + u * 512;
        int d = idx >> 5, ch = (idx & 31) * 8;
        size_t gk = (size_t)(h * 64 + d) * NP2 + ch;
        size_t gv = (size_t)(NINNER + h * 64 + d) * NP2 + ch;
        uint32_t so = (uint32_t)(d * KLD3 + ch) * 2;
        cpa16(sb + AKH3 + so, kh + gk);
        cpa16(sb + AKL3 + so, kl + gk);
        cpa16(sb + AVH3 + so, kh + gv);
        cpa16(sb + AVL3 + so, kl + gv);
    }
    CP_COMMIT();
    CP_WAIT0();
    __syncthreads();

    // phase 1: S[64 i][256 j]; warp tile 16 x 64
    float acc[8][4];
#pragma unroll
    for (int i = 0; i < 8; i++)
#pragma unroll
        for (int k = 0; k < 4; k++) acc[i][k] = 0.f;

#pragma unroll
    for (int kk = 0; kk < 4; kk++) {
        uint32_t ah[4], al[4];
        uint32_t krow = (uint32_t)(kk*16 + (lane & 7) + ((lane >> 1) & 8));
        uint32_t acol = (uint32_t)(wr*16 + (lane & 8));
        uint32_t aaddr = sb + AQH3 + (krow * QLD3 + acol) * 2;
        ldmx4t(ah, aaddr);
        ldmx4t(al, aaddr + (AQL3 - AQH3));
#pragma unroll
        for (int ni2 = 0; ni2 < 4; ni2++) {
            uint32_t bhf[4], blf[4];
            uint32_t baddr = sb + AKH3 + (uint32_t)((kk*16 + (lane & 15)) * KLD3
                                                    + wc*64 + ni2*16 + ((lane & 16) >> 1)) * 2;
            ldmx4t(bhf, baddr);
            ldmx4t(blf, baddr + (AKL3 - AKH3));
            mma16816(acc[ni2*2],   ah, &bhf[0]);
            mma16816(acc[ni2*2],   ah, &blf[0]);
            mma16816(acc[ni2*2],   al, &bhf[0]);
            mma16816(acc[ni2*2+1], ah, &bhf[2]);
            mma16816(acc[ni2*2+1], ah, &blf[2]);
            mma16816(acc[ni2*2+1], al, &bhf[2]);
        }
    }
    __syncthreads();   // all Q/K smem reads done; P may overwrite K region

    // register softmax. rows: rA = wr*16 + (lane>>2), rB = rA + 8.
    int rA = wr * 16 + (lane >> 2);
    int rB = rA + 8;
    // scale by 1/8
#pragma unroll
    for (int ni = 0; ni < 8; ni++)
#pragma unroll
        for (int k = 0; k < 4; k++) acc[ni][k] *= 0.125f;

    float mA = -1e30f, mB = -1e30f;
#pragma unroll
    for (int ni = 0; ni < 8; ni++) {
        mA = fmaxf(mA, fmaxf(acc[ni][0], acc[ni][1]));
        mB = fmaxf(mB, fmaxf(acc[ni][2], acc[ni][3]));
    }
    mA = fmaxf(mA, __shfl_xor_sync(0xffffffffu, mA, 1));
    mA = fmaxf(mA, __shfl_xor_sync(0xffffffffu, mA, 2));
    mB = fmaxf(mB, __shfl_xor_sync(0xffffffffu, mB, 1));
    mB = fmaxf(mB, __shfl_xor_sync(0xffffffffu, mB, 2));
    if ((lane & 3) == 0) { red[rA * 4 + wc] = mA; red[rB * 4 + wc] = mB; }
    __syncthreads();
    mA = fmaxf(fmaxf(red[rA*4], red[rA*4+1]), fmaxf(red[rA*4+2], red[rA*4+3]));
    mB = fmaxf(fmaxf(red[rB*4], red[rB*4+1]), fmaxf(red[rB*4+2], red[rB*4+3]));

    float sA = 0.f, sB = 0.f;
#pragma unroll
    for (int ni = 0; ni < 8; ni++) {
        acc[ni][0] = __expf(acc[ni][0] - mA);
        acc[ni][1] = __expf(acc[ni][1] - mA);
        acc[ni][2] = __expf(acc[ni][2] - mB);
        acc[ni][3] = __expf(acc[ni][3] - mB);
        sA += acc[ni][0] + acc[ni][1];
        sB += acc[ni][2] + acc[ni][3];
    }
    sA += __shfl_xor_sync(0xffffffffu, sA, 1);
    sA += __shfl_xor_sync(0xffffffffu, sA, 2);
    sB += __shfl_xor_sync(0xffffffffu, sB, 1);
    sB += __shfl_xor_sync(0xffffffffu, sB, 2);
    __syncthreads();   // everyone done reading maxes before overwrite
    if ((lane & 3) == 0) { red[rA * 4 + wc] = sA; red[rB * 4 + wc] = sB; }
    __syncthreads();
    float invA = 1.f / (red[rA*4] + red[rA*4+1] + red[rA*4+2] + red[rA*4+3]);
    float invB = 1.f / (red[rB*4] + red[rB*4+1] + red[rB*4+2] + red[rB*4+3]);

    // write normalized P hi/lo into K-region alias
#pragma unroll
    for (int ni = 0; ni < 8; ni++) {
        int c = wc*64 + ni*8 + (lane & 3) * 2;
        put_hl2(Ph, Pl, rA * PLD3 + c, acc[ni][0] * invA, acc[ni][1] * invA);
        put_hl2(Ph, Pl, rB * PLD3 + c, acc[ni][2] * invB, acc[ni][3] * invB);
    }
    __syncthreads();

    // phase 2: O[64 i][64 d] = P @ V ; warp tile 16 x 16
    float acc2[2][4];
#pragma unroll
    for (int i = 0; i < 2; i++)
#pragma unroll
        for (int k = 0; k < 4; k++) acc2[i][k] = 0.f;

#pragma unroll 4
    for (int kk = 0; kk < 16; kk++) {
        uint32_t ah[4], al[4];
        uint32_t aaddr = sb + AKH3 + (uint32_t)((wr*16 + (lane & 15)) * PLD3
                                                + kk*16 + (lane >> 4) * 8) * 2;
        ldmx4(ah, aaddr);
        ldmx4(al, aaddr + (AKL3 - AKH3));
        uint32_t bhf[4], blf[4];
        uint32_t baddr = sb + AVH3 + (uint32_t)((wc*16 + ((lane >> 4) & 1) * 8 + (lane & 7)) * KLD3
                                                + kk*16 + ((lane >> 3) & 1) * 8) * 2;
        ldmx4(bhf, baddr);
        ldmx4(blf, baddr + (AVL3 - AVH3));
        mma16816(acc2[0], ah, &bhf[0]);
        mma16816(acc2[0], ah, &blf[0]);
        mma16816(acc2[0], al, &bhf[0]);
        mma16816(acc2[1], ah, &bhf[2]);
        mma16816(acc2[1], ah, &blf[2]);
        mma16816(acc2[1], al, &bhf[2]);
    }
    __syncthreads();   // P/V reads done; O aliases Q region (disjoint) but sync for clean stage

    // stage O[64 i][65] fp32 into Q-region alias
#pragma unroll
    for (int ni = 0; ni < 2; ni++) {
        int c = wc*16 + ni*8 + (lane & 3) * 2;
        O[rA * OLD3 + c]     = acc2[ni][0];
        O[rA * OLD3 + c + 1] = acc2[ni][1];
        O[rB * OLD3 + c]     = acc2[ni][2];
        O[rB * OLD3 + c + 1] = acc2[ni][3];
    }
    __syncthreads();
    {
        int d = tid >> 3, ip = (tid & 7) * 8;
        __nv_bfloat16* aoh = &g_ao_h[qin][b][h * 64 + d][i0 + ip];
        __nv_bfloat16* aol = &g_ao_l[qin][b][h * 64 + d][i0 + ip];
#pragma unroll
        for (int u = 0; u < 8; u += 2) {
            float v0 = O[(ip + u) * OLD3 + d];
            float v1 = O[(ip + u + 1) * OLD3 + d];
            put_hl2(aoh, aol, u, v0, v1);
        }
    }
}

// ---------------- launch ----------------
extern "C" void kernel_launch(void* const* d_in, const int* in_sizes, int n_in,
                              void* d_out, int out_size)
{
    const float* x      = (const float*)d_in[0];
    const float* y      = (const float*)d_in[1];
    const float* q_dw_w = (const float*)d_in[2];
    const float* q_g    = (const float*)d_in[3];
    const float* q_b    = (const float*)d_in[4];
    const float* q_m    = (const float*)d_in[5];
    const float* q_v    = (const float*)d_in[6];
    const float* q_pw   = (const float*)d_in[7];
    const float* kv_dw_w= (const float*)d_in[8];
    const float* kv_g   = (const float*)d_in[9];
    const float* kv_b   = (const float*)d_in[10];
    const float* kv_m   = (const float*)d_in[11];
    const float* kv_v   = (const float*)d_in[12];
    const float* kv_pw  = (const float*)d_in[13];
    const float* out_w  = (const float*)d_in[14];
    const float* out_b  = (const float*)d_in[15];
    float* out = (float*)d_out;

    __nv_bfloat16 *wq_h, *wq_l, *wkv_h, *wkv_l, *wo_h, *wo_l;
    __nv_bfloat16 *hq_h, *hq_l, *hkv_h, *hkv_l, *q_hp, *q_lp, *kv_hp, *kv_lp, *ao_h, *ao_l;
    cudaGetSymbolAddress((void**)&wq_h,  g_wq_h);  cudaGetSymbolAddress((void**)&wq_l,  g_wq_l);
    cudaGetSymbolAddress((void**)&wkv_h, g_wkv_h); cudaGetSymbolAddress((void**)&wkv_l, g_wkv_l);
    cudaGetSymbolAddress((void**)&wo_h,  g_wo_h);  cudaGetSymbolAddress((void**)&wo_l,  g_wo_l);
    cudaGetSymbolAddress((void**)&hq_h,  g_hq_h);  cudaGetSymbolAddress((void**)&hq_l,  g_hq_l);
    cudaGetSymbolAddress((void**)&hkv_h, g_hkv_h); cudaGetSymbolAddress((void**)&hkv_l, g_hkv_l);
    cudaGetSymbolAddress((void**)&q_hp,  g_q_h);   cudaGetSymbolAddress((void**)&q_lp,  g_q_l);
    cudaGetSymbolAddress((void**)&kv_hp, g_kv_h);  cudaGetSymbolAddress((void**)&kv_lp, g_kv_l);
    cudaGetSymbolAddress((void**)&ao_h,  g_ao_h);  cudaGetSymbolAddress((void**)&ao_l,  g_ao_l);

    cudaFuncSetAttribute(mm_attn3, cudaFuncAttributeMaxDynamicSharedMemorySize, ATT_SM3);
    cudaFuncSetAttribute(mm_gemm2, cudaFuncAttributeMaxDynamicSharedMemorySize, GSM2);

    cvt_hl_kernel<<<(NINNER * NC / 2 + 255) / 256, 256>>>(q_pw,  wq_h,  wq_l,  NINNER * NC / 2);
    cvt_hl_kernel<<<(2 * NINNER * NC / 2 + 255) / 256, 256>>>(kv_pw, wkv_h, wkv_l, 2 * NINNER * NC / 2);
    cvt_hl_kernel<<<(NC * NINNER / 2 + 255) / 256, 256>>>(out_w, wo_h,  wo_l,  NC * NINNER / 2);

    dwbn_fused<<<dim3(NB * NC, 2), 256>>>(x, y,
        q_dw_w, q_g, q_b, q_m, q_v,
        kv_dw_w, kv_g, kv_b, kv_m, kv_v);

    mm_gemm2<<<dim3(NP1 / 128, NINNER / 128, 2 * NB), 256, GSM2>>>(
        wq_h, wq_l, hq_h, hq_l, q_hp, q_lp, nullptr, nullptr,
        NINNER, NC, NP1);
    mm_gemm2<<<dim3(NP2 / 128, (2 * NINNER) / 128, 2 * NB), 256, GSM2>>>(
        wkv_h, wkv_l, hkv_h, hkv_l, kv_hp, kv_lp, nullptr, nullptr,
        2 * NINNER, NC, NP2);

    mm_attn3<<<dim3(NP1 / 64, NB * 8, 2), 512, ATT_SM3>>>();

    mm_gemm2<<<dim3(NP1 / 128, NC / 128, 2 * NB), 256, GSM2>>>(
        wo_h, wo_l, ao_h, ao_l, nullptr, nullptr, out, out_b,
        NC, NINNER, NP1);
}

// round 8
// speedup vs baseline: 2.9308x; 1.0700x over previous
#include <cuda_runtime.h>
#include <cuda_bf16.h>
#include <stdint.h>
#include <math.h>

#define NB 8
#define NC 256
#define NP1 1024
#define NP2 256
#define NINNER 512
#define BN_EPS 1e-5f

// ---------------- bf16 hi/lo scratch ----------------
__device__ __nv_bfloat16 g_hq_h [2][NB][NC][NP1],      g_hq_l [2][NB][NC][NP1];
__device__ __nv_bfloat16 g_hkv_h[2][NB][NC][NP2],      g_hkv_l[2][NB][NC][NP2];
__device__ __nv_bfloat16 g_q_h  [2][NB][NINNER][NP1],  g_q_l  [2][NB][NINNER][NP1];
__device__ __nv_bfloat16 g_kv_h [2][NB][2*NINNER][NP2],g_kv_l [2][NB][2*NINNER][NP2];
__device__ __nv_bfloat16 g_ao_h [2][NB][NINNER][NP1],  g_ao_l [2][NB][NINNER][NP1];
__device__ __nv_bfloat16 g_wq_h [NINNER*NC],   g_wq_l [NINNER*NC];
__device__ __nv_bfloat16 g_wkv_h[2*NINNER*NC], g_wkv_l[2*NINNER*NC];
__device__ __nv_bfloat16 g_wo_h [NC*NINNER],   g_wo_l [NC*NINNER];

// ---------------- helpers ----------------
__device__ __forceinline__ uint32_t smem_u32(const void* p){
    uint32_t a;
    asm("{ .reg .u64 t; cvta.to.shared.u64 t, %1; cvt.u32.u64 %0, t; }" : "=r"(a) : "l"(p));
    return a;
}
__device__ __forceinline__ void ldmx4(uint32_t* r, uint32_t a){
    asm volatile("ldmatrix.sync.aligned.m8n8.x4.shared.b16 {%0,%1,%2,%3}, [%4];"
        : "=r"(r[0]),"=r"(r[1]),"=r"(r[2]),"=r"(r[3]) : "r"(a) : "memory");
}
__device__ __forceinline__ void ldmx4t(uint32_t* r, uint32_t a){
    asm volatile("ldmatrix.sync.aligned.m8n8.x4.trans.shared.b16 {%0,%1,%2,%3}, [%4];"
        : "=r"(r[0]),"=r"(r[1]),"=r"(r[2]),"=r"(r[3]) : "r"(a) : "memory");
}
__device__ __forceinline__ void mma16816(float* c, const uint32_t* a, const uint32_t* b){
    asm volatile("mma.sync.aligned.m16n8k16.row.col.f32.bf16.bf16.f32 "
        "{%0,%1,%2,%3}, {%4,%5,%6,%7}, {%8,%9}, {%0,%1,%2,%3};"
        : "+f"(c[0]),"+f"(c[1]),"+f"(c[2]),"+f"(c[3])
        : "r"(a[0]),"r"(a[1]),"r"(a[2]),"r"(a[3]),"r"(b[0]),"r"(b[1]));
}
__device__ __forceinline__ void cpa16(uint32_t s, const void* g){
    asm volatile("cp.async.cg.shared.global [%0], [%1], 16;" :: "r"(s), "l"(g));
}
#define CP_COMMIT() asm volatile("cp.async.commit_group;" ::: "memory")
#define CP_WAIT0()  asm volatile("cp.async.wait_group 0;" ::: "memory")
#define CP_WAIT1()  asm volatile("cp.async.wait_group 1;" ::: "memory")

__device__ __forceinline__ void put_hl(__nv_bfloat16* bh, __nv_bfloat16* bl, int idx, float v){
    __nv_bfloat16 h = __float2bfloat16(v);
    bh[idx] = h;
    bl[idx] = __float2bfloat16(v - __bfloat162float(h));
}
__device__ __forceinline__ void put_hl2(__nv_bfloat16* bh, __nv_bfloat16* bl, int idx, float v0, float v1){
    __nv_bfloat16 h0 = __float2bfloat16(v0), h1 = __float2bfloat16(v1);
    __nv_bfloat162 H; H.x = h0; H.y = h1;
    __nv_bfloat162 L;
    L.x = __float2bfloat16(v0 - __bfloat162float(h0));
    L.y = __float2bfloat16(v1 - __bfloat162float(h1));
    *(__nv_bfloat162*)(bh + idx) = H;
    *(__nv_bfloat162*)(bl + idx) = L;
}

// ---------------- weight fp32 -> hi/lo ----------------
__global__ void cvt_hl_kernel(const float* __restrict__ src, __nv_bfloat16* __restrict__ h,
                              __nv_bfloat16* __restrict__ l, int n2){
    int i = blockIdx.x * 256 + threadIdx.x;
    if (i < n2) {
        float2 v = *(const float2*)(src + i * 2);
        put_hl2(h, l, i * 2, v.x, v.y);
    }
}

// ---------------- fused depthwise conv (s1 + s2) + BN -> bf16 hi/lo ----------------
__global__ __launch_bounds__(256)
void dwbn_fused(const float* __restrict__ x0, const float* __restrict__ x1,
                const float* __restrict__ qw, const float* __restrict__ qg,
                const float* __restrict__ qb, const float* __restrict__ qm,
                const float* __restrict__ qv,
                const float* __restrict__ kw, const float* __restrict__ kg,
                const float* __restrict__ kb, const float* __restrict__ km,
                const float* __restrict__ kvv)
{
    int inp = blockIdx.y, bc = blockIdx.x, c = bc & 255, b = bc >> 8;
    const float* in = (inp ? x1 : x0) + (size_t)bc * 1024;
    __shared__ float t[34][36];
    int tid = threadIdx.x;

    if (tid < 34) { t[0][tid] = 0.f; t[33][tid] = 0.f; }
    else if (tid < 66) { int r = tid - 33; t[r][0] = 0.f; t[r][33] = 0.f; }

    {
        int r = tid >> 3, q = (tid & 7) * 4;
        float4 v = *(const float4*)(in + r * 32 + q);
        t[r + 1][q + 1] = v.x; t[r + 1][q + 2] = v.y;
        t[r + 1][q + 3] = v.z; t[r + 1][q + 4] = v.w;
    }

    float qwr[9], kwr[9];
#pragma unroll
    for (int i = 0; i < 9; i++) { qwr[i] = qw[c * 9 + i]; kwr[i] = kw[c * 9 + i]; }
    float qs  = qg[c] * rsqrtf(qv[c] + BN_EPS);
    float qsh = qb[c] - qm[c] * qs;
    float ks  = kg[c] * rsqrtf(kvv[c] + BN_EPS);
    float ksh = kb[c] - km[c] * ks;
    __syncthreads();

    {
        int oy = tid >> 3, ox = (tid & 7) * 4;
        float o0 = 0.f, o1 = 0.f, o2 = 0.f, o3 = 0.f;
#pragma unroll
        for (int dy = 0; dy < 3; dy++) {
            float a0 = t[oy + dy][ox + 0], a1 = t[oy + dy][ox + 1], a2 = t[oy + dy][ox + 2];
            float a3 = t[oy + dy][ox + 3], a4 = t[oy + dy][ox + 4], a5 = t[oy + dy][ox + 5];
            float w0 = qwr[dy * 3], w1 = qwr[dy * 3 + 1], w2 = qwr[dy * 3 + 2];
            o0 += a0 * w0 + a1 * w1 + a2 * w2;
            o1 += a1 * w0 + a2 * w1 + a3 * w2;
            o2 += a2 * w0 + a3 * w1 + a4 * w2;
            o3 += a3 * w0 + a4 * w1 + a5 * w2;
        }
        o0 = o0 * qs + qsh; o1 = o1 * qs + qsh;
        o2 = o2 * qs + qsh; o3 = o3 * qs + qsh;
        int idx = oy * 32 + ox;
        put_hl2(&g_hq_h[inp][b][c][0], &g_hq_l[inp][b][c][0], idx, o0, o1);
        put_hl2(&g_hq_h[inp][b][c][0], &g_hq_l[inp][b][c][0], idx + 2, o2, o3);
    }

    {
        int oy = tid >> 4, ox = tid & 15;
        float a = 0.f;
#pragma unroll
        for (int dy = 0; dy < 3; dy++)
#pragma unroll
            for (int dx = 0; dx < 3; dx++)
                a += t[oy * 2 + dy][ox * 2 + dx] * kwr[dy * 3 + dx];
        a = a * ks + ksh;
        put_hl(&g_hkv_h[inp][b][c][0], &g_hkv_l[inp][b][c][0], oy * 16 + ox, a);
    }
}

// ---------------- tensor-core GEMM v2 (unchanged) ----------------
#define ALD2 40
#define BLD2 136
#define A_H0 0
#define A_H1 10240
#define A_L0 20480
#define A_L1 30720
#define B_H0 40960
#define B_H1 49664
#define B_L0 58368
#define B_L1 67072
#define GSM2 75776

__global__ __launch_bounds__(256)
void mm_gemm2(const __nv_bfloat16* __restrict__ Ah, const __nv_bfloat16* __restrict__ Al,
              const __nv_bfloat16* __restrict__ Bh, const __nv_bfloat16* __restrict__ Bl,
              __nv_bfloat16* __restrict__ Ch, __nv_bfloat16* __restrict__ Cl,
              float* __restrict__ Cf, const float* __restrict__ bias,
              int Mtot, int K, int P)
{
    extern __shared__ char sm[];
    uint32_t sb = smem_u32(sm);
    int tid = threadIdx.x, lane = tid & 31, wid = tid >> 5;
    int wr = wid >> 1, wc = wid & 1;
    int m0 = blockIdx.y * 128, n0 = blockIdx.x * 128;
    size_t zoff = (size_t)blockIdx.z * K * P;
    const __nv_bfloat16* Bhz = Bh + zoff;
    const __nv_bfloat16* Blz = Bl + zoff;

    float acc[2][8][4];
#pragma unroll
    for (int i = 0; i < 2; i++)
#pragma unroll
        for (int j = 0; j < 8; j++)
#pragma unroll
            for (int k = 0; k < 4; k++) acc[i][j][k] = 0.f;

    int niter = K >> 5;

#define LOAD_STAGE(st, k0) do { \
    uint32_t aH = sb + ((st) ? A_H1 : A_H0); \
    uint32_t aL = sb + ((st) ? A_L1 : A_L0); \
    uint32_t bH = sb + ((st) ? B_H1 : B_H0); \
    uint32_t bL = sb + ((st) ? B_L1 : B_L0); \
    _Pragma("unroll") \
    for (int u = 0; u < 2; u++) { \
        int idx = tid + u * 256; \
        int row = idx >> 2, ch = (idx & 3) * 8; \
        size_t go = (size_t)(m0 + row) * K + (k0) + ch; \
        uint32_t so = (uint32_t)(row * ALD2 + ch) * 2; \
        cpa16(aH + so, Ah + go); \
        cpa16(aL + so, Al + go); \
    } \
    _Pragma("unroll") \
    for (int u = 0; u < 2; u++) { \
        int idx = tid + u * 256; \
        int row = idx >> 4, ch = (idx & 15) * 8; \
        size_t go = (size_t)((k0) + row) * P + n0 + ch; \
        uint32_t so = (uint32_t)(row * BLD2 + ch) * 2; \
        cpa16(bH + so, Bhz + go); \
        cpa16(bL + so, Blz + go); \
    } \
} while (0)

    LOAD_STAGE(0, 0);
    CP_COMMIT();

    for (int it = 0; it < niter; it++) {
        if (it + 1 < niter) { LOAD_STAGE((it + 1) & 1, (it + 1) << 5); CP_COMMIT(); CP_WAIT1(); }
        else CP_WAIT0();
        __syncthreads();

        uint32_t aHb = sb + ((it & 1) ? A_H1 : A_H0);
        uint32_t bHb = sb + ((it & 1) ? B_H1 : B_H0);
#pragma unroll
        for (int kk = 0; kk < 2; kk++) {
            uint32_t ah[2][4], al[2][4];
#pragma unroll
            for (int mi = 0; mi < 2; mi++) {
                uint32_t aaddr = aHb + (uint32_t)((wr*32 + mi*16 + (lane & 15)) * ALD2
                                                  + kk*16 + (lane >> 4) * 8) * 2;
                ldmx4(ah[mi], aaddr);
                ldmx4(al[mi], aaddr + 20480u);
            }
#pragma unroll
            for (int ni2 = 0; ni2 < 4; ni2++) {
                uint32_t bh[4], bl[4];
                uint32_t baddr = bHb + (uint32_t)((kk*16 + (lane & 15)) * BLD2
                                                  + wc*64 + ni2*16 + ((lane & 16) >> 1)) * 2;
                ldmx4t(bh, baddr);
                ldmx4t(bl, baddr + 17408u);
#pragma unroll
                for (int mi = 0; mi < 2; mi++) {
                    mma16816(acc[mi][ni2*2],   ah[mi], &bh[0]);
                    mma16816(acc[mi][ni2*2],   ah[mi], &bl[0]);
                    mma16816(acc[mi][ni2*2],   al[mi], &bh[0]);
                    mma16816(acc[mi][ni2*2+1], ah[mi], &bh[2]);
                    mma16816(acc[mi][ni2*2+1], ah[mi], &bl[2]);
                    mma16816(acc[mi][ni2*2+1], al[mi], &bh[2]);
                }
            }
        }
        __syncthreads();
    }

    if (Cf) {
        float* Cp = Cf + (size_t)blockIdx.z * Mtot * P;
#pragma unroll
        for (int mi = 0; mi < 2; mi++) {
            int row = m0 + wr*32 + mi*16 + (lane >> 2);
            float b0 = bias ? bias[row] : 0.f;
            float b1 = bias ? bias[row + 8] : 0.f;
#pragma unroll
            for (int ni = 0; ni < 8; ni++) {
                int col = n0 + wc*64 + ni*8 + (lane & 3) * 2;
                *(float2*)&Cp[(size_t)row * P + col] =
                    make_float2(acc[mi][ni][0] + b0, acc[mi][ni][1] + b0);
                *(float2*)&Cp[(size_t)(row + 8) * P + col] =
                    make_float2(acc[mi][ni][2] + b1, acc[mi][ni][3] + b1);
            }
        }
    } else {
        __nv_bfloat16* Chz = Ch + (size_t)blockIdx.z * Mtot * P;
        __nv_bfloat16* Clz = Cl + (size_t)blockIdx.z * Mtot * P;
#pragma unroll
        for (int mi = 0; mi < 2; mi++) {
            int row = m0 + wr*32 + mi*16 + (lane >> 2);
#pragma unroll
            for (int ni = 0; ni < 8; ni++) {
                int col = n0 + wc*64 + ni*8 + (lane & 3) * 2;
                put_hl2(Chz, Clz, (int)((size_t)row * P + col), acc[mi][ni][0], acc[mi][ni][1]);
                put_hl2(Chz, Clz, (int)((size_t)(row + 8) * P + col), acc[mi][ni][2], acc[mi][ni][3]);
            }
        }
    }
}

// ---------------- fused attention v4: persistent per (dir,b,h) ----------------
// smem: Q[64d][72] hi/lo | K[64d][264] hi/lo | V[64d][264] hi/lo | P[64i][264] hi/lo | red
// K/V loaded ONCE; 16 i-tiles looped; Q(it+1) prefetched during softmax(it);
// O fp32 stage aliases P-hi region after phase 2.
#define QLD4 72
#define KLD4 264
#define PLD4 264
#define OLD4 65
#define AQH4 0
#define AQL4 9216
#define AKH4 18432
#define AKL4 52224
#define AVH4 86016
#define AVL4 119808
#define APH4 153600
#define APL4 187392
#define ARED4 221184
#define ATT_SM4 222208

__global__ __launch_bounds__(512)
void mm_attn4()
{
    extern __shared__ char sm[];
    uint32_t sb = smem_u32(sm);
    float* red = (float*)(sm + ARED4);
    float* O   = (float*)(sm + APH4);                 // aliases P-hi after phase 2
    __nv_bfloat16* Ph = (__nv_bfloat16*)(sm + APH4);
    __nv_bfloat16* Pl = (__nv_bfloat16*)(sm + APL4);

    int tid = threadIdx.x, lane = tid & 31, wid = tid >> 5;
    int bh = blockIdx.x, dir = blockIdx.y;
    int b = bh >> 3, h = bh & 7;
    int qin = dir, kin = dir ^ 1;
    int wr = wid >> 2, wc = wid & 3;

    const __nv_bfloat16* qh = &g_q_h[qin][b][0][0];
    const __nv_bfloat16* ql = &g_q_l[qin][b][0][0];
    const __nv_bfloat16* kh = &g_kv_h[kin][b][0][0];
    const __nv_bfloat16* kl = &g_kv_l[kin][b][0][0];

    int qhalf = tid >> 8, qt = tid & 255;
    int qd = qt >> 2, qch = (qt & 3) * 16;
    const __nv_bfloat16* qsrc = (qhalf ? ql : qh) + (size_t)(h * 64 + qd) * NP1 + qch;
    uint32_t qdst = sb + (qhalf ? AQL4 : AQH4) + (uint32_t)(qd * QLD4 + qch) * 2;

    // K, V resident load (once)
#pragma unroll
    for (int u = 0; u < 4; u++) {
        int idx = tid + u * 512;
        int d = idx >> 5, ch = (idx & 31) * 8;
        size_t gk = (size_t)(h * 64 + d) * NP2 + ch;
        size_t gv = (size_t)(NINNER + h * 64 + d) * NP2 + ch;
        uint32_t so = (uint32_t)(d * KLD4 + ch) * 2;
        cpa16(sb + AKH4 + so, kh + gk);
        cpa16(sb + AKL4 + so, kl + gk);
        cpa16(sb + AVH4 + so, kh + gv);
        cpa16(sb + AVL4 + so, kl + gv);
    }
    // Q tile 0
    cpa16(qdst, qsrc);
    cpa16(qdst + 16, qsrc + 8);
    CP_COMMIT();

    int rA = wr * 16 + (lane >> 2);
    int rB = rA + 8;

    for (int it = 0; it < 16; it++) {
        CP_WAIT0();
        __syncthreads();
        int i0 = it * 64;

        // phase 1: S[64 i][256 j]; warp tile 16 x 64
        float acc[8][4];
#pragma unroll
        for (int i = 0; i < 8; i++)
#pragma unroll
            for (int k = 0; k < 4; k++) acc[i][k] = 0.f;

#pragma unroll
        for (int kk = 0; kk < 4; kk++) {
            uint32_t ah[4], al[4];
            uint32_t krow = (uint32_t)(kk*16 + (lane & 7) + ((lane >> 1) & 8));
            uint32_t acol = (uint32_t)(wr*16 + (lane & 8));
            uint32_t aaddr = sb + AQH4 + (krow * QLD4 + acol) * 2;
            ldmx4t(ah, aaddr);
            ldmx4t(al, aaddr + (AQL4 - AQH4));
#pragma unroll
            for (int ni2 = 0; ni2 < 4; ni2++) {
                uint32_t bhf[4], blf[4];
                uint32_t baddr = sb + AKH4 + (uint32_t)((kk*16 + (lane & 15)) * KLD4
                                                        + wc*64 + ni2*16 + ((lane & 16) >> 1)) * 2;
                ldmx4t(bhf, baddr);
                ldmx4t(blf, baddr + (AKL4 - AKH4));
                mma16816(acc[ni2*2],   ah, &bhf[0]);
                mma16816(acc[ni2*2],   ah, &blf[0]);
                mma16816(acc[ni2*2],   al, &bhf[0]);
                mma16816(acc[ni2*2+1], ah, &bhf[2]);
                mma16816(acc[ni2*2+1], ah, &blf[2]);
                mma16816(acc[ni2*2+1], al, &bhf[2]);
            }
        }
        __syncthreads();   // Q reads done; prefetch next Q is now safe

        if (it + 1 < 16) {
            const __nv_bfloat16* nq = qsrc + (it + 1) * 64;
            cpa16(qdst, nq);
            cpa16(qdst + 16, nq + 8);
            CP_COMMIT();
        }

        // register softmax (scale 1/8)
#pragma unroll
        for (int ni = 0; ni < 8; ni++)
#pragma unroll
            for (int k = 0; k < 4; k++) acc[ni][k] *= 0.125f;

        float mA = -1e30f, mB = -1e30f;
#pragma unroll
        for (int ni = 0; ni < 8; ni++) {
            mA = fmaxf(mA, fmaxf(acc[ni][0], acc[ni][1]));
            mB = fmaxf(mB, fmaxf(acc[ni][2], acc[ni][3]));
        }
        mA = fmaxf(mA, __shfl_xor_sync(0xffffffffu, mA, 1));
        mA = fmaxf(mA, __shfl_xor_sync(0xffffffffu, mA, 2));
        mB = fmaxf(mB, __shfl_xor_sync(0xffffffffu, mB, 1));
        mB = fmaxf(mB, __shfl_xor_sync(0xffffffffu, mB, 2));
        if ((lane & 3) == 0) { red[rA * 4 + wc] = mA; red[rB * 4 + wc] = mB; }
        __syncthreads();
        mA = fmaxf(fmaxf(red[rA*4], red[rA*4+1]), fmaxf(red[rA*4+2], red[rA*4+3]));
        mB = fmaxf(fmaxf(red[rB*4], red[rB*4+1]), fmaxf(red[rB*4+2], red[rB*4+3]));

        float sA = 0.f, sB = 0.f;
#pragma unroll
        for (int ni = 0; ni < 8; ni++) {
            acc[ni][0] = __expf(acc[ni][0] - mA);
            acc[ni][1] = __expf(acc[ni][1] - mA);
            acc[ni][2] = __expf(acc[ni][2] - mB);
            acc[ni][3] = __expf(acc[ni][3] - mB);
            sA += acc[ni][0] + acc[ni][1];
            sB += acc[ni][2] + acc[ni][3];
        }
        sA += __shfl_xor_sync(0xffffffffu, sA, 1);
        sA += __shfl_xor_sync(0xffffffffu, sA, 2);
        sB += __shfl_xor_sync(0xffffffffu, sB, 1);
        sB += __shfl_xor_sync(0xffffffffu, sB, 2);
        __syncthreads();
        if ((lane & 3) == 0) { red[rA * 4 + wc] = sA; red[rB * 4 + wc] = sB; }
        __syncthreads();
        float invA = 1.f / (red[rA*4] + red[rA*4+1] + red[rA*4+2] + red[rA*4+3]);
        float invB = 1.f / (red[rB*4] + red[rB*4+1] + red[rB*4+2] + red[rB*4+3]);

        // write normalized P hi/lo
#pragma unroll
        for (int ni = 0; ni < 8; ni++) {
            int c = wc*64 + ni*8 + (lane & 3) * 2;
            put_hl2(Ph, Pl, rA * PLD4 + c, acc[ni][0] * invA, acc[ni][1] * invA);
            put_hl2(Ph, Pl, rB * PLD4 + c, acc[ni][2] * invB, acc[ni][3] * invB);
        }
        __syncthreads();

        // phase 2: O[64 i][64 d] = P @ V ; warp tile 16 x 16
        float acc2[2][4];
#pragma unroll
        for (int i = 0; i < 2; i++)
#pragma unroll
            for (int k = 0; k < 4; k++) acc2[i][k] = 0.f;

#pragma unroll 4
        for (int kk = 0; kk < 16; kk++) {
            uint32_t ah[4], al[4];
            uint32_t aaddr = sb + APH4 + (uint32_t)((wr*16 + (lane & 15)) * PLD4
                                                    + kk*16 + (lane >> 4) * 8) * 2;
            ldmx4(ah, aaddr);
            ldmx4(al, aaddr + (APL4 - APH4));
            uint32_t bhf[4], blf[4];
            uint32_t baddr = sb + AVH4 + (uint32_t)((wc*16 + ((lane >> 4) & 1) * 8 + (lane & 7)) * KLD4
                                                    + kk*16 + ((lane >> 3) & 1) * 8) * 2;
            ldmx4(bhf, baddr);
            ldmx4(blf, baddr + (AVL4 - AVH4));
            mma16816(acc2[0], ah, &bhf[0]);
            mma16816(acc2[0], ah, &blf[0]);
            mma16816(acc2[0], al, &bhf[0]);
            mma16816(acc2[1], ah, &bhf[2]);
            mma16816(acc2[1], ah, &blf[2]);
            mma16816(acc2[1], al, &bhf[2]);
        }
        __syncthreads();   // all P reads done; O may overwrite P-hi

        // stage O[64 i][65] fp32 into P-hi alias
#pragma unroll
        for (int ni = 0; ni < 2; ni++) {
            int c = wc*16 + ni*8 + (lane & 3) * 2;
            O[rA * OLD4 + c]     = acc2[ni][0];
            O[rA * OLD4 + c + 1] = acc2[ni][1];
            O[rB * OLD4 + c]     = acc2[ni][2];
            O[rB * OLD4 + c + 1] = acc2[ni][3];
        }
        __syncthreads();
        {
            int d = tid >> 3, ip = (tid & 7) * 8;
            __nv_bfloat16* aoh = &g_ao_h[qin][b][h * 64 + d][i0 + ip];
            __nv_bfloat16* aol = &g_ao_l[qin][b][h * 64 + d][i0 + ip];
#pragma unroll
            for (int u = 0; u < 8; u += 2) {
                float v0 = O[(ip + u) * OLD4 + d];
                float v1 = O[(ip + u + 1) * OLD4 + d];
                put_hl2(aoh, aol, u, v0, v1);
            }
        }
        // next-iter top: CP_WAIT0 + __syncthreads orders everything
    }
}

// ---------------- launch ----------------
extern "C" void kernel_launch(void* const* d_in, const int* in_sizes, int n_in,
                              void* d_out, int out_size)
{
    const float* x      = (const float*)d_in[0];
    const float* y      = (const float*)d_in[1];
    const float* q_dw_w = (const float*)d_in[2];
    const float* q_g    = (const float*)d_in[3];
    const float* q_b    = (const float*)d_in[4];
    const float* q_m    = (const float*)d_in[5];
    const float* q_v    = (const float*)d_in[6];
    const float* q_pw   = (const float*)d_in[7];
    const float* kv_dw_w= (const float*)d_in[8];
    const float* kv_g   = (const float*)d_in[9];
    const float* kv_b   = (const float*)d_in[10];
    const float* kv_m   = (const float*)d_in[11];
    const float* kv_v   = (const float*)d_in[12];
    const float* kv_pw  = (const float*)d_in[13];
    const float* out_w  = (const float*)d_in[14];
    const float* out_b  = (const float*)d_in[15];
    float* out = (float*)d_out;

    __nv_bfloat16 *wq_h, *wq_l, *wkv_h, *wkv_l, *wo_h, *wo_l;
    __nv_bfloat16 *hq_h, *hq_l, *hkv_h, *hkv_l, *q_hp, *q_lp, *kv_hp, *kv_lp, *ao_h, *ao_l;
    cudaGetSymbolAddress((void**)&wq_h,  g_wq_h);  cudaGetSymbolAddress((void**)&wq_l,  g_wq_l);
    cudaGetSymbolAddress((void**)&wkv_h, g_wkv_h); cudaGetSymbolAddress((void**)&wkv_l, g_wkv_l);
    cudaGetSymbolAddress((void**)&wo_h,  g_wo_h);  cudaGetSymbolAddress((void**)&wo_l,  g_wo_l);
    cudaGetSymbolAddress((void**)&hq_h,  g_hq_h);  cudaGetSymbolAddress((void**)&hq_l,  g_hq_l);
    cudaGetSymbolAddress((void**)&hkv_h, g_hkv_h); cudaGetSymbolAddress((void**)&hkv_l, g_hkv_l);
    cudaGetSymbolAddress((void**)&q_hp,  g_q_h);   cudaGetSymbolAddress((void**)&q_lp,  g_q_l);
    cudaGetSymbolAddress((void**)&kv_hp, g_kv_h);  cudaGetSymbolAddress((void**)&kv_lp, g_kv_l);
    cudaGetSymbolAddress((void**)&ao_h,  g_ao_h);  cudaGetSymbolAddress((void**)&ao_l,  g_ao_l);

    static cudaStream_t s1 = nullptr;
    static cudaEvent_t e_fork, e_cvt, e_dw, e_kv;
    if (!s1) {
        cudaStreamCreateWithFlags(&s1, cudaStreamNonBlocking);
        cudaEventCreateWithFlags(&e_fork, cudaEventDisableTiming);
        cudaEventCreateWithFlags(&e_cvt,  cudaEventDisableTiming);
        cudaEventCreateWithFlags(&e_dw,   cudaEventDisableTiming);
        cudaEventCreateWithFlags(&e_kv,   cudaEventDisableTiming);
        cudaFuncSetAttribute(mm_attn4, cudaFuncAttributeMaxDynamicSharedMemorySize, ATT_SM4);
        cudaFuncSetAttribute(mm_gemm2, cudaFuncAttributeMaxDynamicSharedMemorySize, GSM2);
    }

    // fork s1 off stream 0
    cudaEventRecord(e_fork, 0);
    cudaStreamWaitEvent(s1, e_fork, 0);

    // s1: weight conversions
    cvt_hl_kernel<<<(NINNER * NC / 2 + 255) / 256, 256, 0, s1>>>(q_pw,  wq_h,  wq_l,  NINNER * NC / 2);
    cvt_hl_kernel<<<(2 * NINNER * NC / 2 + 255) / 256, 256, 0, s1>>>(kv_pw, wkv_h, wkv_l, 2 * NINNER * NC / 2);
    cvt_hl_kernel<<<(NC * NINNER / 2 + 255) / 256, 256, 0, s1>>>(out_w, wo_h,  wo_l,  NC * NINNER / 2);
    cudaEventRecord(e_cvt, s1);

    // stream 0: depthwise conv
    dwbn_fused<<<dim3(NB * NC, 2), 256>>>(x, y,
        q_dw_w, q_g, q_b, q_m, q_v,
        kv_dw_w, kv_g, kv_b, kv_m, kv_v);
    cudaEventRecord(e_dw, 0);

    // s1: kv projection (needs dwbn + wkv cvt)
    cudaStreamWaitEvent(s1, e_dw, 0);
    mm_gemm2<<<dim3(NP2 / 128, (2 * NINNER) / 128, 2 * NB), 256, GSM2, s1>>>(
        wkv_h, wkv_l, hkv_h, hkv_l, kv_hp, kv_lp, nullptr, nullptr,
        2 * NINNER, NC, NP2);
    cudaEventRecord(e_kv, s1);

    // stream 0: q projection (needs dwbn + wq cvt)
    cudaStreamWaitEvent(0, e_cvt, 0);
    mm_gemm2<<<dim3(NP1 / 128, NINNER / 128, 2 * NB), 256, GSM2>>>(
        wq_h, wq_l, hq_h, hq_l, q_hp, q_lp, nullptr, nullptr,
        NINNER, NC, NP1);

    // join: attention needs q-proj (stream 0) + kv-proj (s1)
    cudaStreamWaitEvent(0, e_kv, 0);
    mm_attn4<<<dim3(2 * NB * 8 / 2, 2), 512, ATT_SM4>>>();   // (64 bh, 2 dir)

    // output projection
    mm_gemm2<<<dim3(NP1 / 128, NC / 128, 2 * NB), 256, GSM2>>>(
        wo_h, wo_l, ao_h, ao_l, nullptr, nullptr, out, out_b,
        NC, NINNER, NP1);
}

// round 9
// speedup vs baseline: 3.1703x; 1.0817x over previous
#include <cuda_runtime.h>
#include <cuda_bf16.h>
#include <stdint.h>
#include <math.h>

#define NB 8
#define NC 256
#define NP1 1024
#define NP2 256
#define NINNER 512
#define BN_EPS 1e-5f

// ---------------- bf16 hi/lo scratch ----------------
__device__ __nv_bfloat16 g_hq_h [2][NB][NC][NP1],      g_hq_l [2][NB][NC][NP1];
__device__ __nv_bfloat16 g_hkv_h[2][NB][NC][NP2],      g_hkv_l[2][NB][NC][NP2];
__device__ __nv_bfloat16 g_q_h  [2][NB][NINNER][NP1],  g_q_l  [2][NB][NINNER][NP1];
__device__ __nv_bfloat16 g_kv_h [2][NB][2*NINNER][NP2],g_kv_l [2][NB][2*NINNER][NP2];
__device__ __nv_bfloat16 g_ao_h [2][NB][NINNER][NP1],  g_ao_l [2][NB][NINNER][NP1];
__device__ __nv_bfloat16 g_wq_h [NINNER*NC],   g_wq_l [NINNER*NC];
__device__ __nv_bfloat16 g_wkv_h[2*NINNER*NC], g_wkv_l[2*NINNER*NC];
__device__ __nv_bfloat16 g_wo_h [NC*NINNER],   g_wo_l [NC*NINNER];

// ---------------- helpers ----------------
__device__ __forceinline__ uint32_t smem_u32(const void* p){
    uint32_t a;
    asm("{ .reg .u64 t; cvta.to.shared.u64 t, %1; cvt.u32.u64 %0, t; }" : "=r"(a) : "l"(p));
    return a;
}
__device__ __forceinline__ void ldmx4(uint32_t* r, uint32_t a){
    asm volatile("ldmatrix.sync.aligned.m8n8.x4.shared.b16 {%0,%1,%2,%3}, [%4];"
        : "=r"(r[0]),"=r"(r[1]),"=r"(r[2]),"=r"(r[3]) : "r"(a) : "memory");
}
__device__ __forceinline__ void ldmx4t(uint32_t* r, uint32_t a){
    asm volatile("ldmatrix.sync.aligned.m8n8.x4.trans.shared.b16 {%0,%1,%2,%3}, [%4];"
        : "=r"(r[0]),"=r"(r[1]),"=r"(r[2]),"=r"(r[3]) : "r"(a) : "memory");
}
__device__ __forceinline__ void mma16816(float* c, const uint32_t* a, const uint32_t* b){
    asm volatile("mma.sync.aligned.m16n8k16.row.col.f32.bf16.bf16.f32 "
        "{%0,%1,%2,%3}, {%4,%5,%6,%7}, {%8,%9}, {%0,%1,%2,%3};"
        : "+f"(c[0]),"+f"(c[1]),"+f"(c[2]),"+f"(c[3])
        : "r"(a[0]),"r"(a[1]),"r"(a[2]),"r"(a[3]),"r"(b[0]),"r"(b[1]));
}
__device__ __forceinline__ void cpa16(uint32_t s, const void* g){
    asm volatile("cp.async.cg.shared.global [%0], [%1], 16;" :: "r"(s), "l"(g));
}
#define CP_COMMIT() asm volatile("cp.async.commit_group;" ::: "memory")
#define CP_WAIT0()  asm volatile("cp.async.wait_group 0;" ::: "memory")
#define CP_WAIT1()  asm volatile("cp.async.wait_group 1;" ::: "memory")

__device__ __forceinline__ void put_hl(__nv_bfloat16* bh, __nv_bfloat16* bl, int idx, float v){
    __nv_bfloat16 h = __float2bfloat16(v);
    bh[idx] = h;
    bl[idx] = __float2bfloat16(v - __bfloat162float(h));
}
__device__ __forceinline__ void put_hl2(__nv_bfloat16* bh, __nv_bfloat16* bl, int idx, float v0, float v1){
    __nv_bfloat16 h0 = __float2bfloat16(v0), h1 = __float2bfloat16(v1);
    __nv_bfloat162 H; H.x = h0; H.y = h1;
    __nv_bfloat162 L;
    L.x = __float2bfloat16(v0 - __bfloat162float(h0));
    L.y = __float2bfloat16(v1 - __bfloat162float(h1));
    *(__nv_bfloat162*)(bh + idx) = H;
    *(__nv_bfloat162*)(bl + idx) = L;
}

// ---------------- weight fp32 -> hi/lo ----------------
__global__ void cvt_hl_kernel(const float* __restrict__ src, __nv_bfloat16* __restrict__ h,
                              __nv_bfloat16* __restrict__ l, int n2){
    int i = blockIdx.x * 256 + threadIdx.x;
    if (i < n2) {
        float2 v = *(const float2*)(src + i * 2);
        put_hl2(h, l, i * 2, v.x, v.y);
    }
}

// ---------------- fused depthwise conv (s1 + s2) + BN -> bf16 hi/lo ----------------
__global__ __launch_bounds__(256)
void dwbn_fused(const float* __restrict__ x0, const float* __restrict__ x1,
                const float* __restrict__ qw, const float* __restrict__ qg,
                const float* __restrict__ qb, const float* __restrict__ qm,
                const float* __restrict__ qv,
                const float* __restrict__ kw, const float* __restrict__ kg,
                const float* __restrict__ kb, const float* __restrict__ km,
                const float* __restrict__ kvv)
{
    int inp = blockIdx.y, bc = blockIdx.x, c = bc & 255, b = bc >> 8;
    const float* in = (inp ? x1 : x0) + (size_t)bc * 1024;
    __shared__ float t[34][36];
    int tid = threadIdx.x;

    if (tid < 34) { t[0][tid] = 0.f; t[33][tid] = 0.f; }
    else if (tid < 66) { int r = tid - 33; t[r][0] = 0.f; t[r][33] = 0.f; }

    {
        int r = tid >> 3, q = (tid & 7) * 4;
        float4 v = *(const float4*)(in + r * 32 + q);
        t[r + 1][q + 1] = v.x; t[r + 1][q + 2] = v.y;
        t[r + 1][q + 3] = v.z; t[r + 1][q + 4] = v.w;
    }

    float qwr[9], kwr[9];
#pragma unroll
    for (int i = 0; i < 9; i++) { qwr[i] = qw[c * 9 + i]; kwr[i] = kw[c * 9 + i]; }
    float qs  = qg[c] * rsqrtf(qv[c] + BN_EPS);
    float qsh = qb[c] - qm[c] * qs;
    float ks  = kg[c] * rsqrtf(kvv[c] + BN_EPS);
    float ksh = kb[c] - km[c] * ks;
    __syncthreads();

    {
        int oy = tid >> 3, ox = (tid & 7) * 4;
        float o0 = 0.f, o1 = 0.f, o2 = 0.f, o3 = 0.f;
#pragma unroll
        for (int dy = 0; dy < 3; dy++) {
            float a0 = t[oy + dy][ox + 0], a1 = t[oy + dy][ox + 1], a2 = t[oy + dy][ox + 2];
            float a3 = t[oy + dy][ox + 3], a4 = t[oy + dy][ox + 4], a5 = t[oy + dy][ox + 5];
            float w0 = qwr[dy * 3], w1 = qwr[dy * 3 + 1], w2 = qwr[dy * 3 + 2];
            o0 += a0 * w0 + a1 * w1 + a2 * w2;
            o1 += a1 * w0 + a2 * w1 + a3 * w2;
            o2 += a2 * w0 + a3 * w1 + a4 * w2;
            o3 += a3 * w0 + a4 * w1 + a5 * w2;
        }
        o0 = o0 * qs + qsh; o1 = o1 * qs + qsh;
        o2 = o2 * qs + qsh; o3 = o3 * qs + qsh;
        int idx = oy * 32 + ox;
        put_hl2(&g_hq_h[inp][b][c][0], &g_hq_l[inp][b][c][0], idx, o0, o1);
        put_hl2(&g_hq_h[inp][b][c][0], &g_hq_l[inp][b][c][0], idx + 2, o2, o3);
    }

    {
        int oy = tid >> 4, ox = tid & 15;
        float a = 0.f;
#pragma unroll
        for (int dy = 0; dy < 3; dy++)
#pragma unroll
            for (int dx = 0; dx < 3; dx++)
                a += t[oy * 2 + dy][ox * 2 + dx] * kwr[dy * 3 + dx];
        a = a * ks + ksh;
        put_hl(&g_hkv_h[inp][b][c][0], &g_hkv_l[inp][b][c][0], oy * 16 + ox, a);
    }
}

// ---------------- tensor-core GEMM v3: 2 CTAs/SM ----------------
#define ALD2 40
#define BLD2 136
#define A_H0 0
#define A_H1 10240
#define A_L0 20480
#define A_L1 30720
#define B_H0 40960
#define B_H1 49664
#define B_L0 58368
#define B_L1 67072
#define GSM2 75776

__global__ __launch_bounds__(256, 2)
void mm_gemm2(const __nv_bfloat16* __restrict__ Ah, const __nv_bfloat16* __restrict__ Al,
              const __nv_bfloat16* __restrict__ Bh, const __nv_bfloat16* __restrict__ Bl,
              __nv_bfloat16* __restrict__ Ch, __nv_bfloat16* __restrict__ Cl,
              float* __restrict__ Cf, const float* __restrict__ bias,
              int Mtot, int K, int P)
{
    extern __shared__ char sm[];
    uint32_t sb = smem_u32(sm);
    int tid = threadIdx.x, lane = tid & 31, wid = tid >> 5;
    int wr = wid >> 1, wc = wid & 1;
    int m0 = blockIdx.y * 128, n0 = blockIdx.x * 128;
    size_t zoff = (size_t)blockIdx.z * K * P;
    const __nv_bfloat16* Bhz = Bh + zoff;
    const __nv_bfloat16* Blz = Bl + zoff;

    float acc[2][8][4];
#pragma unroll
    for (int i = 0; i < 2; i++)
#pragma unroll
        for (int j = 0; j < 8; j++)
#pragma unroll
            for (int k = 0; k < 4; k++) acc[i][j][k] = 0.f;

    int niter = K >> 5;

#define LOAD_STAGE(st, k0) do { \
    uint32_t aH = sb + ((st) ? A_H1 : A_H0); \
    uint32_t aL = sb + ((st) ? A_L1 : A_L0); \
    uint32_t bH = sb + ((st) ? B_H1 : B_H0); \
    uint32_t bL = sb + ((st) ? B_L1 : B_L0); \
    _Pragma("unroll") \
    for (int u = 0; u < 2; u++) { \
        int idx = tid + u * 256; \
        int row = idx >> 2, ch = (idx & 3) * 8; \
        size_t go = (size_t)(m0 + row) * K + (k0) + ch; \
        uint32_t so = (uint32_t)(row * ALD2 + ch) * 2; \
        cpa16(aH + so, Ah + go); \
        cpa16(aL + so, Al + go); \
    } \
    _Pragma("unroll") \
    for (int u = 0; u < 2; u++) { \
        int idx = tid + u * 256; \
        int row = idx >> 4, ch = (idx & 15) * 8; \
        size_t go = (size_t)((k0) + row) * P + n0 + ch; \
        uint32_t so = (uint32_t)(row * BLD2 + ch) * 2; \
        cpa16(bH + so, Bhz + go); \
        cpa16(bL + so, Blz + go); \
    } \
} while (0)

    LOAD_STAGE(0, 0);
    CP_COMMIT();

    for (int it = 0; it < niter; it++) {
        if (it + 1 < niter) { LOAD_STAGE((it + 1) & 1, (it + 1) << 5); CP_COMMIT(); CP_WAIT1(); }
        else CP_WAIT0();
        __syncthreads();

        uint32_t aHb = sb + ((it & 1) ? A_H1 : A_H0);
        uint32_t bHb = sb + ((it & 1) ? B_H1 : B_H0);
#pragma unroll
        for (int kk = 0; kk < 2; kk++) {
            uint32_t ah[2][4], al[2][4];
#pragma unroll
            for (int mi = 0; mi < 2; mi++) {
                uint32_t aaddr = aHb + (uint32_t)((wr*32 + mi*16 + (lane & 15)) * ALD2
                                                  + kk*16 + (lane >> 4) * 8) * 2;
                ldmx4(ah[mi], aaddr);
                ldmx4(al[mi], aaddr + 20480u);
            }
#pragma unroll
            for (int ni2 = 0; ni2 < 4; ni2++) {
                uint32_t bh[4], bl[4];
                uint32_t baddr = bHb + (uint32_t)((kk*16 + (lane & 15)) * BLD2
                                                  + wc*64 + ni2*16 + ((lane & 16) >> 1)) * 2;
                ldmx4t(bh, baddr);
                ldmx4t(bl, baddr + 17408u);
#pragma unroll
                for (int mi = 0; mi < 2; mi++) {
                    mma16816(acc[mi][ni2*2],   ah[mi], &bh[0]);
                    mma16816(acc[mi][ni2*2],   ah[mi], &bl[0]);
                    mma16816(acc[mi][ni2*2],   al[mi], &bh[0]);
                    mma16816(acc[mi][ni2*2+1], ah[mi], &bh[2]);
                    mma16816(acc[mi][ni2*2+1], ah[mi], &bl[2]);
                    mma16816(acc[mi][ni2*2+1], al[mi], &bh[2]);
                }
            }
        }
        __syncthreads();
    }

    if (Cf) {
        float* Cp = Cf + (size_t)blockIdx.z * Mtot * P;
#pragma unroll
        for (int mi = 0; mi < 2; mi++) {
            int row = m0 + wr*32 + mi*16 + (lane >> 2);
            float b0 = bias ? bias[row] : 0.f;
            float b1 = bias ? bias[row + 8] : 0.f;
#pragma unroll
            for (int ni = 0; ni < 8; ni++) {
                int col = n0 + wc*64 + ni*8 + (lane & 3) * 2;
                *(float2*)&Cp[(size_t)row * P + col] =
                    make_float2(acc[mi][ni][0] + b0, acc[mi][ni][1] + b0);
                *(float2*)&Cp[(size_t)(row + 8) * P + col] =
                    make_float2(acc[mi][ni][2] + b1, acc[mi][ni][3] + b1);
            }
        }
    } else {
        __nv_bfloat16* Chz = Ch + (size_t)blockIdx.z * Mtot * P;
        __nv_bfloat16* Clz = Cl + (size_t)blockIdx.z * Mtot * P;
#pragma unroll
        for (int mi = 0; mi < 2; mi++) {
            int row = m0 + wr*32 + mi*16 + (lane >> 2);
#pragma unroll
            for (int ni = 0; ni < 8; ni++) {
                int col = n0 + wc*64 + ni*8 + (lane & 3) * 2;
                put_hl2(Chz, Clz, (int)((size_t)row * P + col), acc[mi][ni][0], acc[mi][ni][1]);
                put_hl2(Chz, Clz, (int)((size_t)(row + 8) * P + col), acc[mi][ni][2], acc[mi][ni][3]);
            }
        }
    }
}

// ---------------- fused attention v4: persistent per (dir,b,h) (unchanged) ----------------
#define QLD4 72
#define KLD4 264
#define PLD4 264
#define OLD4 65
#define AQH4 0
#define AQL4 9216
#define AKH4 18432
#define AKL4 52224
#define AVH4 86016
#define AVL4 119808
#define APH4 153600
#define APL4 187392
#define ARED4 221184
#define ATT_SM4 222208

__global__ __launch_bounds__(512)
void mm_attn4()
{
    extern __shared__ char sm[];
    uint32_t sb = smem_u32(sm);
    float* red = (float*)(sm + ARED4);
    float* O   = (float*)(sm + APH4);
    __nv_bfloat16* Ph = (__nv_bfloat16*)(sm + APH4);
    __nv_bfloat16* Pl = (__nv_bfloat16*)(sm + APL4);

    int tid = threadIdx.x, lane = tid & 31, wid = tid >> 5;
    int bh = blockIdx.x, dir = blockIdx.y;
    int b = bh >> 3, h = bh & 7;
    int qin = dir, kin = dir ^ 1;
    int wr = wid >> 2, wc = wid & 3;

    const __nv_bfloat16* qh = &g_q_h[qin][b][0][0];
    const __nv_bfloat16* ql = &g_q_l[qin][b][0][0];
    const __nv_bfloat16* kh = &g_kv_h[kin][b][0][0];
    const __nv_bfloat16* kl = &g_kv_l[kin][b][0][0];

    int qhalf = tid >> 8, qt = tid & 255;
    int qd = qt >> 2, qch = (qt & 3) * 16;
    const __nv_bfloat16* qsrc = (qhalf ? ql : qh) + (size_t)(h * 64 + qd) * NP1 + qch;
    uint32_t qdst = sb + (qhalf ? AQL4 : AQH4) + (uint32_t)(qd * QLD4 + qch) * 2;

#pragma unroll
    for (int u = 0; u < 4; u++) {
        int idx = tid + u * 512;
        int d = idx >> 5, ch = (idx & 31) * 8;
        size_t gk = (size_t)(h * 64 + d) * NP2 + ch;
        size_t gv = (size_t)(NINNER + h * 64 + d) * NP2 + ch;
        uint32_t so = (uint32_t)(d * KLD4 + ch) * 2;
        cpa16(sb + AKH4 + so, kh + gk);
        cpa16(sb + AKL4 + so, kl + gk);
        cpa16(sb + AVH4 + so, kh + gv);
        cpa16(sb + AVL4 + so, kl + gv);
    }
    cpa16(qdst, qsrc);
    cpa16(qdst + 16, qsrc + 8);
    CP_COMMIT();

    int rA = wr * 16 + (lane >> 2);
    int rB = rA + 8;

    for (int it = 0; it < 16; it++) {
        CP_WAIT0();
        __syncthreads();
        int i0 = it * 64;

        float acc[8][4];
#pragma unroll
        for (int i = 0; i < 8; i++)
#pragma unroll
            for (int k = 0; k < 4; k++) acc[i][k] = 0.f;

#pragma unroll
        for (int kk = 0; kk < 4; kk++) {
            uint32_t ah[4], al[4];
            uint32_t krow = (uint32_t)(kk*16 + (lane & 7) + ((lane >> 1) & 8));
            uint32_t acol = (uint32_t)(wr*16 + (lane & 8));
            uint32_t aaddr = sb + AQH4 + (krow * QLD4 + acol) * 2;
            ldmx4t(ah, aaddr);
            ldmx4t(al, aaddr + (AQL4 - AQH4));
#pragma unroll
            for (int ni2 = 0; ni2 < 4; ni2++) {
                uint32_t bhf[4], blf[4];
                uint32_t baddr = sb + AKH4 + (uint32_t)((kk*16 + (lane & 15)) * KLD4
                                                        + wc*64 + ni2*16 + ((lane & 16) >> 1)) * 2;
                ldmx4t(bhf, baddr);
                ldmx4t(blf, baddr + (AKL4 - AKH4));
                mma16816(acc[ni2*2],   ah, &bhf[0]);
                mma16816(acc[ni2*2],   ah, &blf[0]);
                mma16816(acc[ni2*2],   al, &bhf[0]);
                mma16816(acc[ni2*2+1], ah, &bhf[2]);
                mma16816(acc[ni2*2+1], ah, &blf[2]);
                mma16816(acc[ni2*2+1], al, &bhf[2]);
            }
        }
        __syncthreads();

        if (it + 1 < 16) {
            const __nv_bfloat16* nq = qsrc + (it + 1) * 64;
            cpa16(qdst, nq);
            cpa16(qdst + 16, nq + 8);
            CP_COMMIT();
        }

#pragma unroll
        for (int ni = 0; ni < 8; ni++)
#pragma unroll
            for (int k = 0; k < 4; k++) acc[ni][k] *= 0.125f;

        float mA = -1e30f, mB = -1e30f;
#pragma unroll
        for (int ni = 0; ni < 8; ni++) {
            mA = fmaxf(mA, fmaxf(acc[ni][0], acc[ni][1]));
            mB = fmaxf(mB, fmaxf(acc[ni][2], acc[ni][3]));
        }
        mA = fmaxf(mA, __shfl_xor_sync(0xffffffffu, mA, 1));
        mA = fmaxf(mA, __shfl_xor_sync(0xffffffffu, mA, 2));
        mB = fmaxf(mB, __shfl_xor_sync(0xffffffffu, mB, 1));
        mB = fmaxf(mB, __shfl_xor_sync(0xffffffffu, mB, 2));
        if ((lane & 3) == 0) { red[rA * 4 + wc] = mA; red[rB * 4 + wc] = mB; }
        __syncthreads();
        mA = fmaxf(fmaxf(red[rA*4], red[rA*4+1]), fmaxf(red[rA*4+2], red[rA*4+3]));
        mB = fmaxf(fmaxf(red[rB*4], red[rB*4+1]), fmaxf(red[rB*4+2], red[rB*4+3]));

        float sA = 0.f, sB = 0.f;
#pragma unroll
        for (int ni = 0; ni < 8; ni++) {
            acc[ni][0] = __expf(acc[ni][0] - mA);
            acc[ni][1] = __expf(acc[ni][1] - mA);
            acc[ni][2] = __expf(acc[ni][2] - mB);
            acc[ni][3] = __expf(acc[ni][3] - mB);
            sA += acc[ni][0] + acc[ni][1];
            sB += acc[ni][2] + acc[ni][3];
        }
        sA += __shfl_xor_sync(0xffffffffu, sA, 1);
        sA += __shfl_xor_sync(0xffffffffu, sA, 2);
        sB += __shfl_xor_sync(0xffffffffu, sB, 1);
        sB += __shfl_xor_sync(0xffffffffu, sB, 2);
        __syncthreads();
        if ((lane & 3) == 0) { red[rA * 4 + wc] = sA; red[rB * 4 + wc] = sB; }
        __syncthreads();
        float invA = 1.f / (red[rA*4] + red[rA*4+1] + red[rA*4+2] + red[rA*4+3]);
        float invB = 1.f / (red[rB*4] + red[rB*4+1] + red[rB*4+2] + red[rB*4+3]);

#pragma unroll
        for (int ni = 0; ni < 8; ni++) {
            int c = wc*64 + ni*8 + (lane & 3) * 2;
            put_hl2(Ph, Pl, rA * PLD4 + c, acc[ni][0] * invA, acc[ni][1] * invA);
            put_hl2(Ph, Pl, rB * PLD4 + c, acc[ni][2] * invB, acc[ni][3] * invB);
        }
        __syncthreads();

        float acc2[2][4];
#pragma unroll
        for (int i = 0; i < 2; i++)
#pragma unroll
            for (int k = 0; k < 4; k++) acc2[i][k] = 0.f;

#pragma unroll 4
        for (int kk = 0; kk < 16; kk++) {
            uint32_t ah[4], al[4];
            uint32_t aaddr = sb + APH4 + (uint32_t)((wr*16 + (lane & 15)) * PLD4
                                                    + kk*16 + (lane >> 4) * 8) * 2;
            ldmx4(ah, aaddr);
            ldmx4(al, aaddr + (APL4 - APH4));
            uint32_t bhf[4], blf[4];
            uint32_t baddr = sb + AVH4 + (uint32_t)((wc*16 + ((lane >> 4) & 1) * 8 + (lane & 7)) * KLD4
                                                    + kk*16 + ((lane >> 3) & 1) * 8) * 2;
            ldmx4(bhf, baddr);
            ldmx4(blf, baddr + (AVL4 - AVH4));
            mma16816(acc2[0], ah, &bhf[0]);
            mma16816(acc2[0], ah, &blf[0]);
            mma16816(acc2[0], al, &bhf[0]);
            mma16816(acc2[1], ah, &bhf[2]);
            mma16816(acc2[1], ah, &blf[2]);
            mma16816(acc2[1], al, &bhf[2]);
        }
        __syncthreads();

#pragma unroll
        for (int ni = 0; ni < 2; ni++) {
            int c = wc*16 + ni*8 + (lane & 3) * 2;
            O[rA * OLD4 + c]     = acc2[ni][0];
            O[rA * OLD4 + c + 1] = acc2[ni][1];
            O[rB * OLD4 + c]     = acc2[ni][2];
            O[rB * OLD4 + c + 1] = acc2[ni][3];
        }
        __syncthreads();
        {
            int d = tid >> 3, ip = (tid & 7) * 8;
            __nv_bfloat16* aoh = &g_ao_h[qin][b][h * 64 + d][i0 + ip];
            __nv_bfloat16* aol = &g_ao_l[qin][b][h * 64 + d][i0 + ip];
#pragma unroll
            for (int u = 0; u < 8; u += 2) {
                float v0 = O[(ip + u) * OLD4 + d];
                float v1 = O[(ip + u + 1) * OLD4 + d];
                put_hl2(aoh, aol, u, v0, v1);
            }
        }
    }
}

// ---------------- launch ----------------
extern "C" void kernel_launch(void* const* d_in, const int* in_sizes, int n_in,
                              void* d_out, int out_size)
{
    const float* x      = (const float*)d_in[0];
    const float* y      = (const float*)d_in[1];
    const float* q_dw_w = (const float*)d_in[2];
    const float* q_g    = (const float*)d_in[3];
    const float* q_b    = (const float*)d_in[4];
    const float* q_m    = (const float*)d_in[5];
    const float* q_v    = (const float*)d_in[6];
    const float* q_pw   = (const float*)d_in[7];
    const float* kv_dw_w= (const float*)d_in[8];
    const float* kv_g   = (const float*)d_in[9];
    const float* kv_b   = (const float*)d_in[10];
    const float* kv_m   = (const float*)d_in[11];
    const float* kv_v   = (const float*)d_in[12];
    const float* kv_pw  = (const float*)d_in[13];
    const float* out_w  = (const float*)d_in[14];
    const float* out_b  = (const float*)d_in[15];
    float* out = (float*)d_out;

    __nv_bfloat16 *wq_h, *wq_l, *wkv_h, *wkv_l, *wo_h, *wo_l;
    __nv_bfloat16 *hq_h, *hq_l, *hkv_h, *hkv_l, *q_hp, *q_lp, *kv_hp, *kv_lp, *ao_h, *ao_l;
    cudaGetSymbolAddress((void**)&wq_h,  g_wq_h);  cudaGetSymbolAddress((void**)&wq_l,  g_wq_l);
    cudaGetSymbolAddress((void**)&wkv_h, g_wkv_h); cudaGetSymbolAddress((void**)&wkv_l, g_wkv_l);
    cudaGetSymbolAddress((void**)&wo_h,  g_wo_h);  cudaGetSymbolAddress((void**)&wo_l,  g_wo_l);
    cudaGetSymbolAddress((void**)&hq_h,  g_hq_h);  cudaGetSymbolAddress((void**)&hq_l,  g_hq_l);
    cudaGetSymbolAddress((void**)&hkv_h, g_hkv_h); cudaGetSymbolAddress((void**)&hkv_l, g_hkv_l);
    cudaGetSymbolAddress((void**)&q_hp,  g_q_h);   cudaGetSymbolAddress((void**)&q_lp,  g_q_l);
    cudaGetSymbolAddress((void**)&kv_hp, g_kv_h);  cudaGetSymbolAddress((void**)&kv_lp, g_kv_l);
    cudaGetSymbolAddress((void**)&ao_h,  g_ao_h);  cudaGetSymbolAddress((void**)&ao_l,  g_ao_l);

    static cudaStream_t s1 = nullptr;
    static cudaEvent_t e_fork, e_cvt, e_dw, e_kv;
    if (!s1) {
        cudaStreamCreateWithFlags(&s1, cudaStreamNonBlocking);
        cudaEventCreateWithFlags(&e_fork, cudaEventDisableTiming);
        cudaEventCreateWithFlags(&e_cvt,  cudaEventDisableTiming);
        cudaEventCreateWithFlags(&e_dw,   cudaEventDisableTiming);
        cudaEventCreateWithFlags(&e_kv,   cudaEventDisableTiming);
        cudaFuncSetAttribute(mm_attn4, cudaFuncAttributeMaxDynamicSharedMemorySize, ATT_SM4);
        cudaFuncSetAttribute(mm_gemm2, cudaFuncAttributeMaxDynamicSharedMemorySize, GSM2);
    }

    cudaEventRecord(e_fork, 0);
    cudaStreamWaitEvent(s1, e_fork, 0);

    cvt_hl_kernel<<<(NINNER * NC / 2 + 255) / 256, 256, 0, s1>>>(q_pw,  wq_h,  wq_l,  NINNER * NC / 2);
    cvt_hl_kernel<<<(2 * NINNER * NC / 2 + 255) / 256, 256, 0, s1>>>(kv_pw, wkv_h, wkv_l, 2 * NINNER * NC / 2);
    cvt_hl_kernel<<<(NC * NINNER / 2 + 255) / 256, 256, 0, s1>>>(out_w, wo_h,  wo_l,  NC * NINNER / 2);
    cudaEventRecord(e_cvt, s1);

    dwbn_fused<<<dim3(NB * NC, 2), 256>>>(x, y,
        q_dw_w, q_g, q_b, q_m, q_v,
        kv_dw_w, kv_g, kv_b, kv_m, kv_v);
    cudaEventRecord(e_dw, 0);

    cudaStreamWaitEvent(s1, e_dw, 0);
    mm_gemm2<<<dim3(NP2 / 128, (2 * NINNER) / 128, 2 * NB), 256, GSM2, s1>>>(
        wkv_h, wkv_l, hkv_h, hkv_l, kv_hp, kv_lp, nullptr, nullptr,
        2 * NINNER, NC, NP2);
    cudaEventRecord(e_kv, s1);

    cudaStreamWaitEvent(0, e_cvt, 0);
    mm_gemm2<<<dim3(NP1 / 128, NINNER / 128, 2 * NB), 256, GSM2>>>(
        wq_h, wq_l, hq_h, hq_l, q_hp, q_lp, nullptr, nullptr,
        NINNER, NC, NP1);

    cudaStreamWaitEvent(0, e_kv, 0);
    mm_attn4<<<dim3(2 * NB * 8 / 2, 2), 512, ATT_SM4>>>();

    mm_gemm2<<<dim3(NP1 / 128, NC / 128, 2 * NB), 256, GSM2>>>(
        wo_h, wo_l, ao_h, ao_l, nullptr, nullptr, out, out_b,
        NC, NINNER, NP1);
}

// round 10
// speedup vs baseline: 3.1992x; 1.0091x over previous
#include <cuda_runtime.h>
#include <cuda_bf16.h>
#include <stdint.h>
#include <math.h>

#define NB 8
#define NC 256
#define NP1 1024
#define NP2 256
#define NINNER 512
#define BN_EPS 1e-5f

// ---------------- bf16 hi/lo scratch ----------------
__device__ __nv_bfloat16 g_hq_h [2][NB][NC][NP1],      g_hq_l [2][NB][NC][NP1];
__device__ __nv_bfloat16 g_hkv_h[2][NB][NC][NP2],      g_hkv_l[2][NB][NC][NP2];
__device__ __nv_bfloat16 g_q_h  [2][NB][NINNER][NP1],  g_q_l  [2][NB][NINNER][NP1];
__device__ __nv_bfloat16 g_kv_h [2][NB][2*NINNER][NP2],g_kv_l [2][NB][2*NINNER][NP2];
__device__ __nv_bfloat16 g_ao_h [2][NB][NINNER][NP1],  g_ao_l [2][NB][NINNER][NP1];
__device__ __nv_bfloat16 g_wq_h [NINNER*NC],   g_wq_l [NINNER*NC];
__device__ __nv_bfloat16 g_wkv_h[2*NINNER*NC], g_wkv_l[2*NINNER*NC];
__device__ __nv_bfloat16 g_wo_h [NC*NINNER],   g_wo_l [NC*NINNER];

// ---------------- helpers ----------------
__device__ __forceinline__ uint32_t smem_u32(const void* p){
    uint32_t a;
    asm("{ .reg .u64 t; cvta.to.shared.u64 t, %1; cvt.u32.u64 %0, t; }" : "=r"(a) : "l"(p));
    return a;
}
__device__ __forceinline__ void ldmx4(uint32_t* r, uint32_t a){
    asm volatile("ldmatrix.sync.aligned.m8n8.x4.shared.b16 {%0,%1,%2,%3}, [%4];"
        : "=r"(r[0]),"=r"(r[1]),"=r"(r[2]),"=r"(r[3]) : "r"(a) : "memory");
}
__device__ __forceinline__ void ldmx4t(uint32_t* r, uint32_t a){
    asm volatile("ldmatrix.sync.aligned.m8n8.x4.trans.shared.b16 {%0,%1,%2,%3}, [%4];"
        : "=r"(r[0]),"=r"(r[1]),"=r"(r[2]),"=r"(r[3]) : "r"(a) : "memory");
}
__device__ __forceinline__ void mma16816(float* c, const uint32_t* a, const uint32_t* b){
    asm volatile("mma.sync.aligned.m16n8k16.row.col.f32.bf16.bf16.f32 "
        "{%0,%1,%2,%3}, {%4,%5,%6,%7}, {%8,%9}, {%0,%1,%2,%3};"
        : "+f"(c[0]),"+f"(c[1]),"+f"(c[2]),"+f"(c[3])
        : "r"(a[0]),"r"(a[1]),"r"(a[2]),"r"(a[3]),"r"(b[0]),"r"(b[1]));
}
__device__ __forceinline__ void cpa16(uint32_t s, const void* g){
    asm volatile("cp.async.cg.shared.global [%0], [%1], 16;" :: "r"(s), "l"(g));
}
#define CP_COMMIT() asm volatile("cp.async.commit_group;" ::: "memory")
#define CP_WAIT0()  asm volatile("cp.async.wait_group 0;" ::: "memory")
#define CP_WAIT1()  asm volatile("cp.async.wait_group 1;" ::: "memory")

__device__ __forceinline__ void put_hl(__nv_bfloat16* bh, __nv_bfloat16* bl, int idx, float v){
    __nv_bfloat16 h = __float2bfloat16(v);
    bh[idx] = h;
    bl[idx] = __float2bfloat16(v - __bfloat162float(h));
}
__device__ __forceinline__ void put_hl2(__nv_bfloat16* bh, __nv_bfloat16* bl, int idx, float v0, float v1){
    __nv_bfloat16 h0 = __float2bfloat16(v0), h1 = __float2bfloat16(v1);
    __nv_bfloat162 H; H.x = h0; H.y = h1;
    __nv_bfloat162 L;
    L.x = __float2bfloat16(v0 - __bfloat162float(h0));
    L.y = __float2bfloat16(v1 - __bfloat162float(h1));
    *(__nv_bfloat162*)(bh + idx) = H;
    *(__nv_bfloat162*)(bl + idx) = L;
}

// ---------------- weight fp32 -> hi/lo ----------------
__global__ void cvt_hl_kernel(const float* __restrict__ src, __nv_bfloat16* __restrict__ h,
                              __nv_bfloat16* __restrict__ l, int n2){
    int i = blockIdx.x * 256 + threadIdx.x;
    if (i < n2) {
        float2 v = *(const float2*)(src + i * 2);
        put_hl2(h, l, i * 2, v.x, v.y);
    }
}

// ---------------- fused depthwise conv (s1 + s2) + BN -> bf16 hi/lo ----------------
__global__ __launch_bounds__(256)
void dwbn_fused(const float* __restrict__ x0, const float* __restrict__ x1,
                const float* __restrict__ qw, const float* __restrict__ qg,
                const float* __restrict__ qb, const float* __restrict__ qm,
                const float* __restrict__ qv,
                const float* __restrict__ kw, const float* __restrict__ kg,
                const float* __restrict__ kb, const float* __restrict__ km,
                const float* __restrict__ kvv)
{
    int inp = blockIdx.y, bc = blockIdx.x, c = bc & 255, b = bc >> 8;
    const float* in = (inp ? x1 : x0) + (size_t)bc * 1024;
    __shared__ float t[34][36];
    int tid = threadIdx.x;

    if (tid < 34) { t[0][tid] = 0.f; t[33][tid] = 0.f; }
    else if (tid < 66) { int r = tid - 33; t[r][0] = 0.f; t[r][33] = 0.f; }

    {
        int r = tid >> 3, q = (tid & 7) * 4;
        float4 v = *(const float4*)(in + r * 32 + q);
        t[r + 1][q + 1] = v.x; t[r + 1][q + 2] = v.y;
        t[r + 1][q + 3] = v.z; t[r + 1][q + 4] = v.w;
    }

    float qwr[9], kwr[9];
#pragma unroll
    for (int i = 0; i < 9; i++) { qwr[i] = qw[c * 9 + i]; kwr[i] = kw[c * 9 + i]; }
    float qs  = qg[c] * rsqrtf(qv[c] + BN_EPS);
    float qsh = qb[c] - qm[c] * qs;
    float ks  = kg[c] * rsqrtf(kvv[c] + BN_EPS);
    float ksh = kb[c] - km[c] * ks;
    __syncthreads();

    {
        int oy = tid >> 3, ox = (tid & 7) * 4;
        float o0 = 0.f, o1 = 0.f, o2 = 0.f, o3 = 0.f;
#pragma unroll
        for (int dy = 0; dy < 3; dy++) {
            float a0 = t[oy + dy][ox + 0], a1 = t[oy + dy][ox + 1], a2 = t[oy + dy][ox + 2];
            float a3 = t[oy + dy][ox + 3], a4 = t[oy + dy][ox + 4], a5 = t[oy + dy][ox + 5];
            float w0 = qwr[dy * 3], w1 = qwr[dy * 3 + 1], w2 = qwr[dy * 3 + 2];
            o0 += a0 * w0 + a1 * w1 + a2 * w2;
            o1 += a1 * w0 + a2 * w1 + a3 * w2;
            o2 += a2 * w0 + a3 * w1 + a4 * w2;
            o3 += a3 * w0 + a4 * w1 + a5 * w2;
        }
        o0 = o0 * qs + qsh; o1 = o1 * qs + qsh;
        o2 = o2 * qs + qsh; o3 = o3 * qs + qsh;
        int idx = oy * 32 + ox;
        put_hl2(&g_hq_h[inp][b][c][0], &g_hq_l[inp][b][c][0], idx, o0, o1);
        put_hl2(&g_hq_h[inp][b][c][0], &g_hq_l[inp][b][c][0], idx + 2, o2, o3);
    }

    {
        int oy = tid >> 4, ox = tid & 15;
        float a = 0.f;
#pragma unroll
        for (int dy = 0; dy < 3; dy++)
#pragma unroll
            for (int dx = 0; dx < 3; dx++)
                a += t[oy * 2 + dy][ox * 2 + dx] * kwr[dy * 3 + dx];
        a = a * ks + ksh;
        put_hl(&g_hkv_h[inp][b][c][0], &g_hkv_l[inp][b][c][0], oy * 16 + ox, a);
    }
}

// ---------------- tensor-core GEMM v4: 2 CTAs/SM + staged bf16 epilogue ----------------
#define ALD2 40
#define BLD2 136
#define A_H0 0
#define A_H1 10240
#define A_L0 20480
#define A_L1 30720
#define B_H0 40960
#define B_H1 49664
#define B_L0 58368
#define B_L1 67072
#define GSM2 75776
#define ELD 136          // epilogue stage leading dim (bf16): 4r+c bank pattern, conflict-free

__global__ __launch_bounds__(256, 2)
void mm_gemm2(const __nv_bfloat16* __restrict__ Ah, const __nv_bfloat16* __restrict__ Al,
              const __nv_bfloat16* __restrict__ Bh, const __nv_bfloat16* __restrict__ Bl,
              __nv_bfloat16* __restrict__ Ch, __nv_bfloat16* __restrict__ Cl,
              float* __restrict__ Cf, const float* __restrict__ bias,
              int Mtot, int K, int P)
{
    extern __shared__ char sm[];
    uint32_t sb = smem_u32(sm);
    int tid = threadIdx.x, lane = tid & 31, wid = tid >> 5;
    int wr = wid >> 1, wc = wid & 1;
    int m0 = blockIdx.y * 128, n0 = blockIdx.x * 128;
    size_t zoff = (size_t)blockIdx.z * K * P;
    const __nv_bfloat16* Bhz = Bh + zoff;
    const __nv_bfloat16* Blz = Bl + zoff;

    float acc[2][8][4];
#pragma unroll
    for (int i = 0; i < 2; i++)
#pragma unroll
        for (int j = 0; j < 8; j++)
#pragma unroll
            for (int k = 0; k < 4; k++) acc[i][j][k] = 0.f;

    int niter = K >> 5;

#define LOAD_STAGE(st, k0) do { \
    uint32_t aH = sb + ((st) ? A_H1 : A_H0); \
    uint32_t aL = sb + ((st) ? A_L1 : A_L0); \
    uint32_t bH = sb + ((st) ? B_H1 : B_H0); \
    uint32_t bL = sb + ((st) ? B_L1 : B_L0); \
    _Pragma("unroll") \
    for (int u = 0; u < 2; u++) { \
        int idx = tid + u * 256; \
        int row = idx >> 2, ch = (idx & 3) * 8; \
        size_t go = (size_t)(m0 + row) * K + (k0) + ch; \
        uint32_t so = (uint32_t)(row * ALD2 + ch) * 2; \
        cpa16(aH + so, Ah + go); \
        cpa16(aL + so, Al + go); \
    } \
    _Pragma("unroll") \
    for (int u = 0; u < 2; u++) { \
        int idx = tid + u * 256; \
        int row = idx >> 4, ch = (idx & 15) * 8; \
        size_t go = (size_t)((k0) + row) * P + n0 + ch; \
        uint32_t so = (uint32_t)(row * BLD2 + ch) * 2; \
        cpa16(bH + so, Bhz + go); \
        cpa16(bL + so, Blz + go); \
    } \
} while (0)

    LOAD_STAGE(0, 0);
    CP_COMMIT();

    for (int it = 0; it < niter; it++) {
        if (it + 1 < niter) { LOAD_STAGE((it + 1) & 1, (it + 1) << 5); CP_COMMIT(); CP_WAIT1(); }
        else CP_WAIT0();
        __syncthreads();

        uint32_t aHb = sb + ((it & 1) ? A_H1 : A_H0);
        uint32_t bHb = sb + ((it & 1) ? B_H1 : B_H0);
#pragma unroll
        for (int kk = 0; kk < 2; kk++) {
            uint32_t ah[2][4], al[2][4];
#pragma unroll
            for (int mi = 0; mi < 2; mi++) {
                uint32_t aaddr = aHb + (uint32_t)((wr*32 + mi*16 + (lane & 15)) * ALD2
                                                  + kk*16 + (lane >> 4) * 8) * 2;
                ldmx4(ah[mi], aaddr);
                ldmx4(al[mi], aaddr + 20480u);
            }
#pragma unroll
            for (int ni2 = 0; ni2 < 4; ni2++) {
                uint32_t bh[4], bl[4];
                uint32_t baddr = bHb + (uint32_t)((kk*16 + (lane & 15)) * BLD2
                                                  + wc*64 + ni2*16 + ((lane & 16) >> 1)) * 2;
                ldmx4t(bh, baddr);
                ldmx4t(bl, baddr + 17408u);
#pragma unroll
                for (int mi = 0; mi < 2; mi++) {
                    mma16816(acc[mi][ni2*2],   ah[mi], &bh[0]);
                    mma16816(acc[mi][ni2*2],   ah[mi], &bl[0]);
                    mma16816(acc[mi][ni2*2],   al[mi], &bh[0]);
                    mma16816(acc[mi][ni2*2+1], ah[mi], &bh[2]);
                    mma16816(acc[mi][ni2*2+1], ah[mi], &bl[2]);
                    mma16816(acc[mi][ni2*2+1], al[mi], &bh[2]);
                }
            }
        }
        __syncthreads();
    }

    if (Cf) {
        float* Cp = Cf + (size_t)blockIdx.z * Mtot * P;
#pragma unroll
        for (int mi = 0; mi < 2; mi++) {
            int row = m0 + wr*32 + mi*16 + (lane >> 2);
            float b0 = bias ? bias[row] : 0.f;
            float b1 = bias ? bias[row + 8] : 0.f;
#pragma unroll
            for (int ni = 0; ni < 8; ni++) {
                int col = n0 + wc*64 + ni*8 + (lane & 3) * 2;
                *(float2*)&Cp[(size_t)row * P + col] =
                    make_float2(acc[mi][ni][0] + b0, acc[mi][ni][1] + b0);
                *(float2*)&Cp[(size_t)(row + 8) * P + col] =
                    make_float2(acc[mi][ni][2] + b1, acc[mi][ni][3] + b1);
            }
        }
    } else {
        // staged bf16 epilogue: fragments -> smem (conflict-free), then uint4 coalesced stores
        __nv_bfloat16* Eh = (__nv_bfloat16*)sm;                  // 128 x ELD
        __nv_bfloat16* El = (__nv_bfloat16*)(sm + 128 * ELD * 2);
#pragma unroll
        for (int mi = 0; mi < 2; mi++) {
            int row = wr*32 + mi*16 + (lane >> 2);
#pragma unroll
            for (int ni = 0; ni < 8; ni++) {
                int col = wc*64 + ni*8 + (lane & 3) * 2;
                put_hl2(Eh, El, row * ELD + col, acc[mi][ni][0], acc[mi][ni][1]);
                put_hl2(Eh, El, (row + 8) * ELD + col, acc[mi][ni][2], acc[mi][ni][3]);
            }
        }
        __syncthreads();
        __nv_bfloat16* Chz = Ch + (size_t)blockIdx.z * Mtot * P;
        __nv_bfloat16* Clz = Cl + (size_t)blockIdx.z * Mtot * P;
#pragma unroll
        for (int u = 0; u < 8; u++) {
            int linear = tid + u * 256;
            int row = linear >> 4, c8 = (linear & 15) * 8;
            size_t go = (size_t)(m0 + row) * P + n0 + c8;
            *(uint4*)&Chz[go] = *(const uint4*)&Eh[row * ELD + c8];
            *(uint4*)&Clz[go] = *(const uint4*)&El[row * ELD + c8];
        }
    }
}

// ---------------- fused attention v5: persistent, split reduction buffers ----------------
#define QLD4 72
#define KLD4 264
#define PLD4 264
#define OLD4 65
#define AQH4 0
#define AQL4 9216
#define AKH4 18432
#define AKL4 52224
#define AVH4 86016
#define AVL4 119808
#define APH4 153600
#define APL4 187392
#define AREDM 221184
#define AREDS 222208
#define ATT_SM4 223232

__global__ __launch_bounds__(512)
void mm_attn4()
{
    extern __shared__ char sm[];
    uint32_t sb = smem_u32(sm);
    float* red_m = (float*)(sm + AREDM);
    float* red_s = (float*)(sm + AREDS);
    float* O   = (float*)(sm + APH4);
    __nv_bfloat16* Ph = (__nv_bfloat16*)(sm + APH4);
    __nv_bfloat16* Pl = (__nv_bfloat16*)(sm + APL4);

    int tid = threadIdx.x, lane = tid & 31, wid = tid >> 5;
    int bh = blockIdx.x, dir = blockIdx.y;
    int b = bh >> 3, h = bh & 7;
    int qin = dir, kin = dir ^ 1;
    int wr = wid >> 2, wc = wid & 3;

    const __nv_bfloat16* qh = &g_q_h[qin][b][0][0];
    const __nv_bfloat16* ql = &g_q_l[qin][b][0][0];
    const __nv_bfloat16* kh = &g_kv_h[kin][b][0][0];
    const __nv_bfloat16* kl = &g_kv_l[kin][b][0][0];

    int qhalf = tid >> 8, qt = tid & 255;
    int qd = qt >> 2, qch = (qt & 3) * 16;
    const __nv_bfloat16* qsrc = (qhalf ? ql : qh) + (size_t)(h * 64 + qd) * NP1 + qch;
    uint32_t qdst = sb + (qhalf ? AQL4 : AQH4) + (uint32_t)(qd * QLD4 + qch) * 2;

#pragma unroll
    for (int u = 0; u < 4; u++) {
        int idx = tid + u * 512;
        int d = idx >> 5, ch = (idx & 31) * 8;
        size_t gk = (size_t)(h * 64 + d) * NP2 + ch;
        size_t gv = (size_t)(NINNER + h * 64 + d) * NP2 + ch;
        uint32_t so = (uint32_t)(d * KLD4 + ch) * 2;
        cpa16(sb + AKH4 + so, kh + gk);
        cpa16(sb + AKL4 + so, kl + gk);
        cpa16(sb + AVH4 + so, kh + gv);
        cpa16(sb + AVL4 + so, kl + gv);
    }
    cpa16(qdst, qsrc);
    cpa16(qdst + 16, qsrc + 8);
    CP_COMMIT();

    int rA = wr * 16 + (lane >> 2);
    int rB = rA + 8;

    for (int it = 0; it < 16; it++) {
        CP_WAIT0();
        __syncthreads();
        int i0 = it * 64;

        float acc[8][4];
#pragma unroll
        for (int i = 0; i < 8; i++)
#pragma unroll
            for (int k = 0; k < 4; k++) acc[i][k] = 0.f;

#pragma unroll
        for (int kk = 0; kk < 4; kk++) {
            uint32_t ah[4], al[4];
            uint32_t krow = (uint32_t)(kk*16 + (lane & 7) + ((lane >> 1) & 8));
            uint32_t acol = (uint32_t)(wr*16 + (lane & 8));
            uint32_t aaddr = sb + AQH4 + (krow * QLD4 + acol) * 2;
            ldmx4t(ah, aaddr);
            ldmx4t(al, aaddr + (AQL4 - AQH4));
#pragma unroll
            for (int ni2 = 0; ni2 < 4; ni2++) {
                uint32_t bhf[4], blf[4];
                uint32_t baddr = sb + AKH4 + (uint32_t)((kk*16 + (lane & 15)) * KLD4
                                                        + wc*64 + ni2*16 + ((lane & 16) >> 1)) * 2;
                ldmx4t(bhf, baddr);
                ldmx4t(blf, baddr + (AKL4 - AKH4));
                mma16816(acc[ni2*2],   ah, &bhf[0]);
                mma16816(acc[ni2*2],   ah, &blf[0]);
                mma16816(acc[ni2*2],   al, &bhf[0]);
                mma16816(acc[ni2*2+1], ah, &bhf[2]);
                mma16816(acc[ni2*2+1], ah, &blf[2]);
                mma16816(acc[ni2*2+1], al, &bhf[2]);
            }
        }
        __syncthreads();

        if (it + 1 < 16) {
            const __nv_bfloat16* nq = qsrc + (it + 1) * 64;
            cpa16(qdst, nq);
            cpa16(qdst + 16, nq + 8);
            CP_COMMIT();
        }

#pragma unroll
        for (int ni = 0; ni < 8; ni++)
#pragma unroll
            for (int k = 0; k < 4; k++) acc[ni][k] *= 0.125f;

        float mA = -1e30f, mB = -1e30f;
#pragma unroll
        for (int ni = 0; ni < 8; ni++) {
            mA = fmaxf(mA, fmaxf(acc[ni][0], acc[ni][1]));
            mB = fmaxf(mB, fmaxf(acc[ni][2], acc[ni][3]));
        }
        mA = fmaxf(mA, __shfl_xor_sync(0xffffffffu, mA, 1));
        mA = fmaxf(mA, __shfl_xor_sync(0xffffffffu, mA, 2));
        mB = fmaxf(mB, __shfl_xor_sync(0xffffffffu, mB, 1));
        mB = fmaxf(mB, __shfl_xor_sync(0xffffffffu, mB, 2));
        if ((lane & 3) == 0) { red_m[rA * 4 + wc] = mA; red_m[rB * 4 + wc] = mB; }
        __syncthreads();
        mA = fmaxf(fmaxf(red_m[rA*4], red_m[rA*4+1]), fmaxf(red_m[rA*4+2], red_m[rA*4+3]));
        mB = fmaxf(fmaxf(red_m[rB*4], red_m[rB*4+1]), fmaxf(red_m[rB*4+2], red_m[rB*4+3]));

        float sA = 0.f, sB = 0.f;
#pragma unroll
        for (int ni = 0; ni < 8; ni++) {
            acc[ni][0] = __expf(acc[ni][0] - mA);
            acc[ni][1] = __expf(acc[ni][1] - mA);
            acc[ni][2] = __expf(acc[ni][2] - mB);
            acc[ni][3] = __expf(acc[ni][3] - mB);
            sA += acc[ni][0] + acc[ni][1];
            sB += acc[ni][2] + acc[ni][3];
        }
        sA += __shfl_xor_sync(0xffffffffu, sA, 1);
        sA += __shfl_xor_sync(0xffffffffu, sA, 2);
        sB += __shfl_xor_sync(0xffffffffu, sB, 1);
        sB += __shfl_xor_sync(0xffffffffu, sB, 2);
        if ((lane & 3) == 0) { red_s[rA * 4 + wc] = sA; red_s[rB * 4 + wc] = sB; }
        __syncthreads();
        float invA = 1.f / (red_s[rA*4] + red_s[rA*4+1] + red_s[rA*4+2] + red_s[rA*4+3]);
        float invB = 1.f / (red_s[rB*4] + red_s[rB*4+1] + red_s[rB*4+2] + red_s[rB*4+3]);

#pragma unroll
        for (int ni = 0; ni < 8; ni++) {
            int c = wc*64 + ni*8 + (lane & 3) * 2;
            put_hl2(Ph, Pl, rA * PLD4 + c, acc[ni][0] * invA, acc[ni][1] * invA);
            put_hl2(Ph, Pl, rB * PLD4 + c, acc[ni][2] * invB, acc[ni][3] * invB);
        }
        __syncthreads();

        float acc2[2][4];
#pragma unroll
        for (int i = 0; i < 2; i++)
#pragma unroll
            for (int k = 0; k < 4; k++) acc2[i][k] = 0.f;

#pragma unroll 4
        for (int kk = 0; kk < 16; kk++) {
            uint32_t ah[4], al[4];
            uint32_t aaddr = sb + APH4 + (uint32_t)((wr*16 + (lane & 15)) * PLD4
                                                    + kk*16 + (lane >> 4) * 8) * 2;
            ldmx4(ah, aaddr);
            ldmx4(al, aaddr + (APL4 - APH4));
            uint32_t bhf[4], blf[4];
            uint32_t baddr = sb + AVH4 + (uint32_t)((wc*16 + ((lane >> 4) & 1) * 8 + (lane & 7)) * KLD4
                                                    + kk*16 + ((lane >> 3) & 1) * 8) * 2;
            ldmx4(bhf, baddr);
            ldmx4(blf, baddr + (AVL4 - AVH4));
            mma16816(acc2[0], ah, &bhf[0]);
            mma16816(acc2[0], ah, &blf[0]);
            mma16816(acc2[0], al, &bhf[0]);
            mma16816(acc2[1], ah, &bhf[2]);
            mma16816(acc2[1], ah, &blf[2]);
            mma16816(acc2[1], al, &bhf[2]);
        }
        __syncthreads();

#pragma unroll
        for (int ni = 0; ni < 2; ni++) {
            int c = wc*16 + ni*8 + (lane & 3) * 2;
            O[rA * OLD4 + c]     = acc2[ni][0];
            O[rA * OLD4 + c + 1] = acc2[ni][1];
            O[rB * OLD4 + c]     = acc2[ni][2];
            O[rB * OLD4 + c + 1] = acc2[ni][3];
        }
        __syncthreads();
        {
            int d = tid >> 3, ip = (tid & 7) * 8;
            __nv_bfloat16* aoh = &g_ao_h[qin][b][h * 64 + d][i0 + ip];
            __nv_bfloat16* aol = &g_ao_l[qin][b][h * 64 + d][i0 + ip];
#pragma unroll
            for (int u = 0; u < 8; u += 2) {
                float v0 = O[(ip + u) * OLD4 + d];
                float v1 = O[(ip + u + 1) * OLD4 + d];
                put_hl2(aoh, aol, u, v0, v1);
            }
        }
    }
}

// ---------------- launch ----------------
extern "C" void kernel_launch(void* const* d_in, const int* in_sizes, int n_in,
                              void* d_out, int out_size)
{
    const float* x      = (const float*)d_in[0];
    const float* y      = (const float*)d_in[1];
    const float* q_dw_w = (const float*)d_in[2];
    const float* q_g    = (const float*)d_in[3];
    const float* q_b    = (const float*)d_in[4];
    const float* q_m    = (const float*)d_in[5];
    const float* q_v    = (const float*)d_in[6];
    const float* q_pw   = (const float*)d_in[7];
    const float* kv_dw_w= (const float*)d_in[8];
    const float* kv_g   = (const float*)d_in[9];
    const float* kv_b   = (const float*)d_in[10];
    const float* kv_m   = (const float*)d_in[11];
    const float* kv_v   = (const float*)d_in[12];
    const float* kv_pw  = (const float*)d_in[13];
    const float* out_w  = (const float*)d_in[14];
    const float* out_b  = (const float*)d_in[15];
    float* out = (float*)d_out;

    __nv_bfloat16 *wq_h, *wq_l, *wkv_h, *wkv_l, *wo_h, *wo_l;
    __nv_bfloat16 *hq_h, *hq_l, *hkv_h, *hkv_l, *q_hp, *q_lp, *kv_hp, *kv_lp, *ao_h, *ao_l;
    cudaGetSymbolAddress((void**)&wq_h,  g_wq_h);  cudaGetSymbolAddress((void**)&wq_l,  g_wq_l);
    cudaGetSymbolAddress((void**)&wkv_h, g_wkv_h); cudaGetSymbolAddress((void**)&wkv_l, g_wkv_l);
    cudaGetSymbolAddress((void**)&wo_h,  g_wo_h);  cudaGetSymbolAddress((void**)&wo_l,  g_wo_l);
    cudaGetSymbolAddress((void**)&hq_h,  g_hq_h);  cudaGetSymbolAddress((void**)&hq_l,  g_hq_l);
    cudaGetSymbolAddress((void**)&hkv_h, g_hkv_h); cudaGetSymbolAddress((void**)&hkv_l, g_hkv_l);
    cudaGetSymbolAddress((void**)&q_hp,  g_q_h);   cudaGetSymbolAddress((void**)&q_lp,  g_q_l);
    cudaGetSymbolAddress((void**)&kv_hp, g_kv_h);  cudaGetSymbolAddress((void**)&kv_lp, g_kv_l);
    cudaGetSymbolAddress((void**)&ao_h,  g_ao_h);  cudaGetSymbolAddress((void**)&ao_l,  g_ao_l);

    static cudaStream_t s1 = nullptr;
    static cudaEvent_t e_fork, e_cvt, e_dw, e_kv;
    if (!s1) {
        cudaStreamCreateWithFlags(&s1, cudaStreamNonBlocking);
        cudaEventCreateWithFlags(&e_fork, cudaEventDisableTiming);
        cudaEventCreateWithFlags(&e_cvt,  cudaEventDisableTiming);
        cudaEventCreateWithFlags(&e_dw,   cudaEventDisableTiming);
        cudaEventCreateWithFlags(&e_kv,   cudaEventDisableTiming);
        cudaFuncSetAttribute(mm_attn4, cudaFuncAttributeMaxDynamicSharedMemorySize, ATT_SM4);
        cudaFuncSetAttribute(mm_gemm2, cudaFuncAttributeMaxDynamicSharedMemorySize, GSM2);
    }

    cudaEventRecord(e_fork, 0);
    cudaStreamWaitEvent(s1, e_fork, 0);

    cvt_hl_kernel<<<(NINNER * NC / 2 + 255) / 256, 256, 0, s1>>>(q_pw,  wq_h,  wq_l,  NINNER * NC / 2);
    cvt_hl_kernel<<<(2 * NINNER * NC / 2 + 255) / 256, 256, 0, s1>>>(kv_pw, wkv_h, wkv_l, 2 * NINNER * NC / 2);
    cvt_hl_kernel<<<(NC * NINNER / 2 + 255) / 256, 256, 0, s1>>>(out_w, wo_h,  wo_l,  NC * NINNER / 2);
    cudaEventRecord(e_cvt, s1);

    dwbn_fused<<<dim3(NB * NC, 2), 256>>>(x, y,
        q_dw_w, q_g, q_b, q_m, q_v,
        kv_dw_w, kv_g, kv_b, kv_m, kv_v);
    cudaEventRecord(e_dw, 0);

    cudaStreamWaitEvent(s1, e_dw, 0);
    mm_gemm2<<<dim3(NP2 / 128, (2 * NINNER) / 128, 2 * NB), 256, GSM2, s1>>>(
        wkv_h, wkv_l, hkv_h, hkv_l, kv_hp, kv_lp, nullptr, nullptr,
        2 * NINNER, NC, NP2);
    cudaEventRecord(e_kv, s1);

    cudaStreamWaitEvent(0, e_cvt, 0);
    mm_gemm2<<<dim3(NP1 / 128, NINNER / 128, 2 * NB), 256, GSM2>>>(
        wq_h, wq_l, hq_h, hq_l, q_hp, q_lp, nullptr, nullptr,
        NINNER, NC, NP1);

    cudaStreamWaitEvent(0, e_kv, 0);
    mm_attn4<<<dim3(2 * NB * 8 / 2, 2), 512, ATT_SM4>>>();

    mm_gemm2<<<dim3(NP1 / 128, NC / 128, 2 * NB), 256, GSM2>>>(
        wo_h, wo_l, ao_h, ao_l, nullptr, nullptr, out, out_b,
        NC, NINNER, NP1);
}